// round 3
// baseline (speedup 1.0000x reference)
#include <cuda_runtime.h>

// Problem dims
#define BB 256
#define TT 512
#define II 512
#define HH 1024
#define OO 256
#define SHLL ((long long)TT * HH)

// ---------------- scratch (static device memory; allocation-free) ----------------
__device__ __align__(16) float g_pre[BB * TT * HH];   // pre-activations (layer0, reused for layer1)
__device__ __align__(16) float g_h1[BB * TT * HH];    // layer0 hidden sequence
__device__ __align__(16) float g_h2[2 * BB * HH];     // ping-pong hidden state for layer1
__device__ __align__(16) float g_bias0[HH];
__device__ __align__(16) float g_bias1[HH];

// grid-barrier state
__device__ unsigned g_count = 0;
__device__ unsigned g_gen = 0;

// ---------------- small helpers ----------------
__global__ void bias_combine(const float* __restrict__ a,
                             const float* __restrict__ b,
                             float* __restrict__ out, int n) {
    int i = blockIdx.x * blockDim.x + threadIdx.x;
    if (i < n) out[i] = a[i] + b[i];
}

__device__ __forceinline__ unsigned long long dup2(float v) {
    unsigned long long r;
    asm("mov.b64 %0, {%1, %1};" : "=l"(r) : "f"(v));
    return r;
}
__device__ __forceinline__ void fma2(unsigned long long& d,
                                     unsigned long long a,
                                     unsigned long long b) {
    asm("fma.rn.f32x2 %0, %1, %2, %0;" : "+l"(d) : "l"(a), "l"(b));
}
__device__ __forceinline__ float2 unpk(unsigned long long v) {
    float2 r;
    asm("mov.b64 {%0, %1}, %2;" : "=f"(r.x), "=f"(r.y) : "l"(v));
    return r;
}

__device__ __forceinline__ void grid_bar() {
    __threadfence();
    __syncthreads();
    if (threadIdx.x == 0) {
        volatile unsigned* gen = (volatile unsigned*)&g_gen;
        unsigned my = *gen;                       // MUST read before arriving
        if (atomicAdd(&g_count, 1u) == gridDim.x - 1) {
            atomicExch(&g_count, 0u);
            __threadfence();
            *gen = my + 1;
        } else {
            while (*gen == my) { }
        }
    }
    __syncthreads();
}

// ---------------- persistent recurrence kernel ----------------
// h_t = relu(pre_t + h_{t-1} @ W^T), 128 CTAs (8 batch-tiles x 16 H-tiles),
// CTA tile 32(batch) x 64(H-out), 128 threads, BK=64, packed f32x2 math.
// SEQ=true : h stored as full sequence [B][T][H] (row stride T*H, step stride H)
// SEQ=false: h ping-pong [2][B][H]
#define BKR 64

template <bool SEQ>
__global__ void __launch_bounds__(128, 1)
rnn_rec(const float* __restrict__ W,     // [HH][HH] row-major
        const float* __restrict__ pre,   // [B][T][H]
        float* __restrict__ hbuf,
        int steps) {
    __shared__ __align__(16) float As[BKR][32];    // [k][m], XOR-swizzled
    __shared__ __align__(16) float Ws2[BKR][128];  // [k][2n] duplicated pairs, XOR-swizzled

    const int tid = threadIdx.x;
    const int bid = blockIdx.x;
    const int m0 = (bid & 7) * 32;    // batch tile
    const int n0 = (bid >> 3) * 64;   // H-out tile

    // staging mapping
    const int sx = tid & 15;          // k-group (float4 index within 64-k row)
    const int sy = tid >> 4;          // 0..7
    const int sswA = 4 * (sx & 7);    // As col swizzle for k = 4*sx+c
    const int sswW = 8 * (sx & 7);    // Ws2 col swizzle

    // compute mapping: warp tile 32m x 16n; lane tile 8m x 2n
    const int w  = tid >> 5;          // warp 0..3 -> n offset 16*w
    const int lx = tid & 7;           // n pair index
    const int ly = (tid >> 3) & 3;    // m group: rows 8*ly .. 8*ly+7

    const long long astride = SEQ ? SHLL : (long long)HH;

    for (int t = 0; t < steps; ++t) {
        unsigned long long acc[4][2];
#pragma unroll
        for (int ip = 0; ip < 4; ++ip) { acc[ip][0] = 0ULL; acc[ip][1] = 0ULL; }

        if (t > 0) {
            const float* Ab = SEQ ? (hbuf + (long long)(t - 1) * HH)
                                  : (hbuf + (long long)((t - 1) & 1) * BB * HH);
            float4 Ar[4], Wr[8];
            // preload k-tile 0
#pragma unroll
            for (int it = 0; it < 4; ++it)
                Ar[it] = __ldcg((const float4*)(Ab + (long long)(m0 + sy + 8 * it) * astride + 4 * sx));
#pragma unroll
            for (int it = 0; it < 8; ++it)
                Wr[it] = __ldg((const float4*)(W + (long long)(n0 + sy + 8 * it) * HH + 4 * sx));

            for (int kt = 0; kt < HH; kt += BKR) {
                // ---- store staged regs to smem (swizzled) ----
#pragma unroll
                for (int it = 0; it < 4; ++it) {
                    const int col = (sy + 8 * it) ^ sswA;
                    As[4 * sx + 0][col] = Ar[it].x;
                    As[4 * sx + 1][col] = Ar[it].y;
                    As[4 * sx + 2][col] = Ar[it].z;
                    As[4 * sx + 3][col] = Ar[it].w;
                }
#pragma unroll
                for (int it = 0; it < 8; ++it) {
                    const int col = (2 * (sy + 8 * it)) ^ sswW;
                    *(unsigned long long*)&Ws2[4 * sx + 0][col] = dup2(Wr[it].x);
                    *(unsigned long long*)&Ws2[4 * sx + 1][col] = dup2(Wr[it].y);
                    *(unsigned long long*)&Ws2[4 * sx + 2][col] = dup2(Wr[it].z);
                    *(unsigned long long*)&Ws2[4 * sx + 3][col] = dup2(Wr[it].w);
                }
                __syncthreads();

                // ---- prefetch next k-tile ----
                const int kn = kt + BKR;
                if (kn < HH) {
#pragma unroll
                    for (int it = 0; it < 4; ++it)
                        Ar[it] = __ldcg((const float4*)(Ab + (long long)(m0 + sy + 8 * it) * astride + kn + 4 * sx));
#pragma unroll
                    for (int it = 0; it < 8; ++it)
                        Wr[it] = __ldg((const float4*)(W + (long long)(n0 + sy + 8 * it) * HH + kn + 4 * sx));
                }

                // ---- compute 64 k-steps ----
#pragma unroll 8
                for (int kk = 0; kk < BKR; ++kk) {
                    const int s4 = 4 * ((kk >> 2) & 7);
                    const int s8 = 2 * s4;
                    const double2 av0 = *(const double2*)&As[kk][(8 * ly) ^ s4];
                    const double2 av1 = *(const double2*)&As[kk][(8 * ly + 4) ^ s4];
                    const unsigned long long a0 = __double_as_longlong(av0.x);
                    const unsigned long long a1 = __double_as_longlong(av0.y);
                    const unsigned long long a2 = __double_as_longlong(av1.x);
                    const unsigned long long a3 = __double_as_longlong(av1.y);
                    const unsigned long long b0 =
                        *(const unsigned long long*)&Ws2[kk][(32 * w + 4 * lx) ^ s8];
                    const unsigned long long b1 =
                        *(const unsigned long long*)&Ws2[kk][(32 * w + 4 * lx + 2) ^ s8];
                    fma2(acc[0][0], a0, b0); fma2(acc[0][1], a0, b1);
                    fma2(acc[1][0], a1, b0); fma2(acc[1][1], a1, b1);
                    fma2(acc[2][0], a2, b0); fma2(acc[2][1], a2, b1);
                    fma2(acc[3][0], a3, b0); fma2(acc[3][1], a3, b1);
                }
                __syncthreads();
            }
        }

        // ---- epilogue: h = relu(acc + pre_t) ----
        {
            const float* Pt = pre + (long long)t * HH;
            float* Ct = SEQ ? (hbuf + (long long)t * HH)
                            : (hbuf + (long long)(t & 1) * BB * HH);
            const int ncol = n0 + 16 * w + 2 * lx;
#pragma unroll
            for (int ip = 0; ip < 4; ++ip) {
                const float2 u0 = unpk(acc[ip][0]);
                const float2 u1 = unpk(acc[ip][1]);
                const long long mlo = m0 + 8 * ly + 2 * ip;
                // row lo
                {
                    float2 p = __ldcg((const float2*)(Pt + mlo * SHLL + ncol));
                    float2 o;
                    o.x = fmaxf(u0.x + p.x, 0.0f);
                    o.y = fmaxf(u1.x + p.y, 0.0f);
                    __stcg((float2*)(Ct + mlo * astride + ncol), o);
                }
                // row hi
                {
                    float2 p = __ldcg((const float2*)(Pt + (mlo + 1) * SHLL + ncol));
                    float2 o;
                    o.x = fmaxf(u0.y + p.x, 0.0f);
                    o.y = fmaxf(u1.y + p.y, 0.0f);
                    __stcg((float2*)(Ct + (mlo + 1) * astride + ncol), o);
                }
            }
        }
        grid_bar();
    }
}

// ---------------- generic scalar GEMM (pre-activations + fc) ----------------
// C = A @ W^T (+bias), A: MxK (row stride a_stride), W: NxK row-major.
template <int BM, int BN, int TM, int TN>
__global__ void __launch_bounds__((BM / TM) * (BN / TN))
gemm_nt(const float* __restrict__ A, long long a_stride,
        const float* __restrict__ W,
        const float* __restrict__ bias,
        float* __restrict__ C, long long c_stride,
        int K) {
    constexpr int BK = 16;
    constexpr int TX = BN / TN;
    constexpr int TY = BM / TM;
    constexpr int NT = TX * TY;

    __shared__ __align__(16) float As[BK][BM];
    __shared__ __align__(16) float Ws[BK][BN];

    const int tid = threadIdx.x;
    const int tx = tid % TX;
    const int ty = tid / TX;
    const long long m0 = (long long)blockIdx.x * BM;
    const int n0 = blockIdx.y * BN;

    float acc[TM][TN];
#pragma unroll
    for (int i = 0; i < TM; i++)
#pragma unroll
        for (int j = 0; j < TN; j++) acc[i][j] = 0.0f;

    for (int kt = 0; kt < K; kt += BK) {
#pragma unroll
        for (int idx = tid; idx < BM * 4; idx += NT) {
            const int row = idx >> 2;
            const int kq = (idx & 3) * 4;
            const float4 v = *(const float4*)(A + (m0 + row) * a_stride + kt + kq);
            As[kq + 0][row] = v.x; As[kq + 1][row] = v.y;
            As[kq + 2][row] = v.z; As[kq + 3][row] = v.w;
        }
#pragma unroll
        for (int idx = tid; idx < BN * 4; idx += NT) {
            const int row = idx >> 2;
            const int kq = (idx & 3) * 4;
            const float4 v = *(const float4*)(W + (long long)(n0 + row) * K + kt + kq);
            Ws[kq + 0][row] = v.x; Ws[kq + 1][row] = v.y;
            Ws[kq + 2][row] = v.z; Ws[kq + 3][row] = v.w;
        }
        __syncthreads();

#pragma unroll
        for (int kk = 0; kk < BK; kk++) {
            float a[TM], b[TN];
#pragma unroll
            for (int i = 0; i < TM; i += 4) {
                const float4 v = *(const float4*)&As[kk][ty * TM + i];
                a[i] = v.x; a[i + 1] = v.y; a[i + 2] = v.z; a[i + 3] = v.w;
            }
#pragma unroll
            for (int j = 0; j < TN; j += 4) {
                const float4 v = *(const float4*)&Ws[kk][tx * TN + j];
                b[j] = v.x; b[j + 1] = v.y; b[j + 2] = v.z; b[j + 3] = v.w;
            }
#pragma unroll
            for (int i = 0; i < TM; i++)
#pragma unroll
                for (int j = 0; j < TN; j++)
                    acc[i][j] = fmaf(a[i], b[j], acc[i][j]);
        }
        __syncthreads();
    }

#pragma unroll
    for (int i = 0; i < TM; i++) {
        const long long m = m0 + ty * TM + i;
#pragma unroll
        for (int j = 0; j < TN; j++) {
            const int n = n0 + tx * TN + j;
            C[m * c_stride + n] = acc[i][j] + bias[n];
        }
    }
}

// ---------------- launch ----------------
extern "C" void kernel_launch(void* const* d_in, const int* in_sizes, int n_in,
                              void* d_out, int out_size) {
    const float* x     = (const float*)d_in[0];
    const float* W_ih0 = (const float*)d_in[1];
    const float* W_hh0 = (const float*)d_in[2];
    const float* b_ih0 = (const float*)d_in[3];
    const float* b_hh0 = (const float*)d_in[4];
    const float* W_ih1 = (const float*)d_in[5];
    const float* W_hh1 = (const float*)d_in[6];
    const float* b_ih1 = (const float*)d_in[7];
    const float* b_hh1 = (const float*)d_in[8];
    const float* fc_w  = (const float*)d_in[9];
    const float* fc_b  = (const float*)d_in[10];
    float* out = (float*)d_out;

    float *p_pre, *p_h1, *p_h2, *p_b0, *p_b1;
    cudaGetSymbolAddress((void**)&p_pre, g_pre);
    cudaGetSymbolAddress((void**)&p_h1, g_h1);
    cudaGetSymbolAddress((void**)&p_h2, g_h2);
    cudaGetSymbolAddress((void**)&p_b0, g_bias0);
    cudaGetSymbolAddress((void**)&p_b1, g_bias1);

    // combined biases
    bias_combine<<<(HH + 255) / 256, 256>>>(b_ih0, b_hh0, p_b0, HH);
    bias_combine<<<(HH + 255) / 256, 256>>>(b_ih1, b_hh1, p_b1, HH);

    // pre0 = x @ W_ih0^T + bias0
    gemm_nt<128, 128, 8, 8>
        <<<dim3((BB * TT) / 128, HH / 128), 256>>>(x, II, W_ih0, p_b0, p_pre, HH, II);

    // layer-0 recurrence (persistent, 512 steps, writes full sequence)
    rnn_rec<true><<<128, 128>>>(W_hh0, p_pre, p_h1, TT);

    // pre1 = h1 @ W_ih1^T + bias1
    gemm_nt<128, 128, 8, 8>
        <<<dim3((BB * TT) / 128, HH / 128), 256>>>(p_h1, HH, W_ih1, p_b1, p_pre, HH, HH);

    // layer-1 recurrence (persistent, ping-pong)
    rnn_rec<false><<<128, 128>>>(W_hh1, p_pre, p_h2, TT);

    // fc: out = h2_last @ fc_w^T + fc_b   (last step lands in buffer (TT-1)&1 = 1)
    gemm_nt<32, 64, 4, 4>
        <<<dim3(BB / 32, OO / 64), 128>>>(p_h2 + (long long)1 * BB * HH, HH, fc_w,
                                          fc_b, out, OO, HH);
}

// round 5
// speedup vs baseline: 3.8202x; 3.8202x over previous
#include <cuda_runtime.h>
#include <cuda_bf16.h>
#include <cstdint>

// ---------------- problem dims ----------------
#define BB 256
#define TT 512
#define II 512
#define HH 1024
#define OO 256

// ---------------- static device scratch (allocation-free) ----------------
__device__ __align__(16) float g_pre[BB * TT * HH];            // fp32 pre-activations (reused)
__device__ __align__(16) __nv_bfloat16 g_xh[BB * TT * II];
__device__ __align__(16) __nv_bfloat16 g_xl[BB * TT * II];
__device__ __align__(16) __nv_bfloat16 g_h1h[BB * TT * HH];
__device__ __align__(16) __nv_bfloat16 g_h1l[BB * TT * HH];
__device__ __align__(16) __nv_bfloat16 g_h2h[2 * BB * HH];
__device__ __align__(16) __nv_bfloat16 g_h2l[2 * BB * HH];
__device__ __align__(16) float g_h2f[BB * HH];
__device__ __align__(16) __nv_bfloat16 g_wih0h[HH * II], g_wih0l[HH * II];
__device__ __align__(16) __nv_bfloat16 g_wih1h[HH * HH], g_wih1l[HH * HH];
__device__ __align__(16) __nv_bfloat16 g_whh0h[HH * HH], g_whh0l[HH * HH];
__device__ __align__(16) __nv_bfloat16 g_whh1h[HH * HH], g_whh1l[HH * HH];
__device__ __align__(16) float g_bias0[HH];
__device__ __align__(16) float g_bias1[HH];
__device__ unsigned g_count = 0;
__device__ unsigned g_gen = 0;

// ---------------- PTX helpers (baseline PTX only — no 'a' features) ----------------
__device__ __forceinline__ uint32_t smem_u32(const void* p) {
    uint32_t a;
    asm("{ .reg .u64 t; cvta.to.shared.u64 t, %1; cvt.u32.u64 %0, t; }" : "=r"(a) : "l"(p));
    return a;
}
#define CP16(dst, src) \
    asm volatile("cp.async.cg.shared.global [%0], [%1], 16;" :: "r"(dst), "l"(src) : "memory")
#define CP_COMMIT() asm volatile("cp.async.commit_group;" ::: "memory")
#define CP_WAIT(n)  asm volatile("cp.async.wait_group %0;" :: "n"(n) : "memory")

#define LDMX4(r, addr) \
    asm volatile("ldmatrix.sync.aligned.m8n8.x4.shared.b16 {%0,%1,%2,%3}, [%4];" \
                 : "=r"((r)[0]), "=r"((r)[1]), "=r"((r)[2]), "=r"((r)[3]) : "r"(addr))

#define MMA16816(d, a, b0, b1) \
    asm volatile("mma.sync.aligned.m16n8k16.row.col.f32.bf16.bf16.f32 " \
                 "{%0,%1,%2,%3},{%4,%5,%6,%7},{%8,%9},{%0,%1,%2,%3};" \
                 : "+f"((d)[0]), "+f"((d)[1]), "+f"((d)[2]), "+f"((d)[3]) \
                 : "r"((a)[0]), "r"((a)[1]), "r"((a)[2]), "r"((a)[3]), "r"(b0), "r"(b1))

// ---------------- grid barrier ----------------
__device__ __forceinline__ void grid_bar() {
    __threadfence();
    __syncthreads();
    if (threadIdx.x == 0) {
        volatile unsigned* gen = (volatile unsigned*)&g_gen;
        unsigned my = *gen;
        if (atomicAdd(&g_count, 1u) == gridDim.x - 1) {
            atomicExch(&g_count, 0u);
            __threadfence();
            *gen = my + 1;
        } else {
            while (*gen == my) { }
        }
    }
    __syncthreads();
}

// ---------------- prep kernels ----------------
__global__ void split_f32(const float* __restrict__ s,
                          __nv_bfloat16* __restrict__ hi,
                          __nv_bfloat16* __restrict__ lo, long long n) {
    long long i = (long long)blockIdx.x * blockDim.x + threadIdx.x;
    if (i < n) {
        float v = s[i];
        __nv_bfloat16 h = __float2bfloat16(v);
        hi[i] = h;
        lo[i] = __float2bfloat16(v - __bfloat162float(h));
    }
}
__global__ void bias_combine(const float* __restrict__ a, const float* __restrict__ b,
                             float* __restrict__ out, int n) {
    int i = blockIdx.x * blockDim.x + threadIdx.x;
    if (i < n) out[i] = a[i] + b[i];
}

// ================= HMMA pre-activation GEMM =================
// C[M][1024] = (Ah+Al) @ (Wh+Wl)^T + bias   (3-pass split bf16, fp32 accum)
// CTA tile 128x128, 256 threads (8 warps, warp tile 32x64), K chunks of 64,
// cp.async double-buffered.  Stage layout (per 64KB stage):
//   Ahi @0 (128x128B swizzled), Alo @16384, Whi @32768, Wlo @49152.
#define PG_STAGE 65536
#define PG_SMEM  (2 * PG_STAGE)

__global__ void __launch_bounds__(256, 1)
gemm_mma(const __nv_bfloat16* __restrict__ Ah, const __nv_bfloat16* __restrict__ Al,
         const __nv_bfloat16* __restrict__ Wh, const __nv_bfloat16* __restrict__ Wl,
         const float* __restrict__ bias, float* __restrict__ C, int K) {
    extern __shared__ __align__(128) char smem[];
    const uint32_t sb = smem_u32(smem);
    const int tid = threadIdx.x, l = tid & 31, w = tid >> 5;
    const long long m0 = (long long)blockIdx.x * 128;
    const int n0 = blockIdx.y * 128;
    const int nch = K >> 6;

    // staging constants: per matrix 4 units/thread; unit j: row r0+32j, 16B-col c
    const int r0 = tid >> 3, c = tid & 7;
    const uint32_t sd0 = (uint32_t)r0 * 128 + (((uint32_t)c * 16) ^ (((uint32_t)r0 & 7) * 16));

    // compute constants
    const int m_off = (w & 3) * 32, n_off = (w >> 2) * 64;
    const int arw = m_off + (l & 7) + ((l & 8) ? 8 : 0);     // mfrag0 row
    const uint32_t abase = (uint32_t)arw * 128;
    const uint32_t ax = ((uint32_t)arw & 7) * 16;
    const uint32_t akb = (l & 16) ? 16 : 0;
    const int brw = n_off + (l & 7) + ((l & 16) ? 8 : 0);    // nb=0 row
    const uint32_t bbase = (uint32_t)brw * 128;
    const uint32_t bx = ((uint32_t)brw & 7) * 16;
    const uint32_t bkb = (l & 8) ? 16 : 0;

    float acc[2][8][4];
#pragma unroll
    for (int i = 0; i < 2; i++)
#pragma unroll
        for (int j = 0; j < 8; j++)
#pragma unroll
            for (int k = 0; k < 4; k++) acc[i][j][k] = 0.0f;

    // issue chunk 0
    {
        const uint32_t d = sb;
        const int ko = c * 8;
#pragma unroll
        for (int j = 0; j < 4; ++j) {
            const long long ar = (m0 + r0 + 32 * j) * (long long)K + ko;
            const long long wr = ((long long)(n0 + r0 + 32 * j)) * K + ko;
            const uint32_t du = d + sd0 + j * 4096;
            CP16(du,          Ah + ar);
            CP16(du + 16384,  Al + ar);
            CP16(du + 32768,  Wh + wr);
            CP16(du + 49152,  Wl + wr);
        }
        CP_COMMIT();
    }

    for (int kc = 0; kc < nch; ++kc) {
        if (kc + 1 < nch) {
            const uint32_t d = sb + ((kc + 1) & 1) * PG_STAGE;
            const int ko = (kc + 1) * 64 + c * 8;
#pragma unroll
            for (int j = 0; j < 4; ++j) {
                const long long ar = (m0 + r0 + 32 * j) * (long long)K + ko;
                const long long wr = ((long long)(n0 + r0 + 32 * j)) * K + ko;
                const uint32_t du = d + sd0 + j * 4096;
                CP16(du,          Ah + ar);
                CP16(du + 16384,  Al + ar);
                CP16(du + 32768,  Wh + wr);
                CP16(du + 49152,  Wl + wr);
            }
            CP_COMMIT();
            CP_WAIT(1);
        } else {
            CP_WAIT(0);
        }
        __syncthreads();

        const uint32_t st = sb + (kc & 1) * PG_STAGE;
#pragma unroll
        for (int ks = 0; ks < 4; ++ks) {
            uint32_t ah0[4], al0[4], ah1[4], al1[4];
            const uint32_t ao = ((uint32_t)(ks * 32) + akb) ^ ax;
            LDMX4(ah0, st + abase + ao);
            LDMX4(al0, st + 16384 + abase + ao);
            LDMX4(ah1, st + abase + 2048 + ao);
            LDMX4(al1, st + 16384 + abase + 2048 + ao);
            uint32_t bh[4][4], bl[4][4];
            const uint32_t bo = ((uint32_t)(ks * 32) + bkb) ^ bx;
#pragma unroll
            for (int nb = 0; nb < 4; ++nb) {
                LDMX4(bh[nb], st + 32768 + bbase + nb * 2048 + bo);
                LDMX4(bl[nb], st + 49152 + bbase + nb * 2048 + bo);
            }
#pragma unroll
            for (int nb = 0; nb < 4; ++nb) {
                MMA16816(acc[0][2 * nb],     ah0, bh[nb][0], bh[nb][1]);
                MMA16816(acc[0][2 * nb],     al0, bh[nb][0], bh[nb][1]);
                MMA16816(acc[0][2 * nb],     ah0, bl[nb][0], bl[nb][1]);
                MMA16816(acc[0][2 * nb + 1], ah0, bh[nb][2], bh[nb][3]);
                MMA16816(acc[0][2 * nb + 1], al0, bh[nb][2], bh[nb][3]);
                MMA16816(acc[0][2 * nb + 1], ah0, bl[nb][2], bl[nb][3]);
                MMA16816(acc[1][2 * nb],     ah1, bh[nb][0], bh[nb][1]);
                MMA16816(acc[1][2 * nb],     al1, bh[nb][0], bh[nb][1]);
                MMA16816(acc[1][2 * nb],     ah1, bl[nb][0], bl[nb][1]);
                MMA16816(acc[1][2 * nb + 1], ah1, bh[nb][2], bh[nb][3]);
                MMA16816(acc[1][2 * nb + 1], al1, bh[nb][2], bh[nb][3]);
                MMA16816(acc[1][2 * nb + 1], ah1, bl[nb][2], bl[nb][3]);
            }
        }
        __syncthreads();
    }

    // epilogue
#pragma unroll
    for (int mf = 0; mf < 2; ++mf) {
        const long long R0 = m0 + m_off + mf * 16 + (l >> 2);
#pragma unroll
        for (int nf = 0; nf < 8; ++nf) {
            const int col = n0 + n_off + nf * 8 + (l & 3) * 2;
            const float2 bv = __ldg((const float2*)(bias + col));
            float2 o0, o1;
            o0.x = acc[mf][nf][0] + bv.x; o0.y = acc[mf][nf][1] + bv.y;
            o1.x = acc[mf][nf][2] + bv.x; o1.y = acc[mf][nf][3] + bv.y;
            __stcg((float2*)(C + R0 * HH + col), o0);
            __stcg((float2*)(C + (R0 + 8) * HH + col), o1);
        }
    }
}

// ================= HMMA persistent recurrence =================
// h_t = relu(pre_t + h_{t-1} @ W^T), split-bf16 3-pass.
// grid 128 = 4 batch-tiles(64) x 32 H-tiles(32). 256 threads (8 warps: 4m x 2n,
// warp tile 16x16). W hi/lo resident in smem; A chunks via cp.async double-buffer.
#define RW_HI 0
#define RW_LO 65536
#define RA_ST 131072
#define RA_SZ 16384        // per stage: Ahi 8KB + Alo 8KB
#define RN_SMEM (RA_ST + 2 * RA_SZ)

template <bool SEQ>
__global__ void __launch_bounds__(256, 1)
rnn_mma(const __nv_bfloat16* __restrict__ Wh, const __nv_bfloat16* __restrict__ Wl,
        const float* __restrict__ pre,
        __nv_bfloat16* __restrict__ hh, __nv_bfloat16* __restrict__ hl,
        float* __restrict__ hfin) {
    extern __shared__ __align__(128) char smem[];
    const uint32_t sb = smem_u32(smem);
    const int tid = threadIdx.x, l = tid & 31, w = tid >> 5;
    const int m0 = (blockIdx.x & 3) * 64;
    const int n0 = (blockIdx.x >> 2) * 32;

    // ---- load resident W (hi+lo): 16 chunk-blocks of [32 rows][128B] ----
    for (int u = tid; u < 4096; u += 256) {
        const int kc = u >> 8, rem = u & 255, r = rem >> 3, cc = rem & 7;
        const uint32_t dst = (uint32_t)kc * 4096 + (uint32_t)r * 128 +
                             (((uint32_t)cc * 16) ^ (((uint32_t)r & 7) * 16));
        const long long src = (long long)(n0 + r) * HH + kc * 64 + cc * 8;
        *(uint4*)(smem + RW_HI + dst) = *(const uint4*)(Wh + src);
        *(uint4*)(smem + RW_LO + dst) = *(const uint4*)(Wl + src);
    }
    __syncthreads();

    // staging constants: 2 units/thread/matrix: rows sr, sr+32 at 16B-col sc
    const int sr = tid >> 3, sc = tid & 7;
    const uint32_t st0 = (uint32_t)sr * 128 + (((uint32_t)sc * 16) ^ (((uint32_t)sr & 7) * 16));
    const uint32_t st1 = st0 + 32 * 128;   // (sr+32)&7 == sr&7

    // compute constants (warp tile 16m x 16n)
    const int m_off = 16 * (w & 3), n_off = 16 * (w >> 2);
    const int arw = m_off + (l & 7) + ((l & 8) ? 8 : 0);
    const uint32_t abase = (uint32_t)arw * 128;
    const uint32_t ax = ((uint32_t)arw & 7) * 16;
    const uint32_t akb = (l & 16) ? 16 : 0;
    const int brw = n_off + (l & 7) + ((l & 16) ? 8 : 0);
    const uint32_t bbase = (uint32_t)brw * 128;
    const uint32_t bx = ((uint32_t)brw & 7) * 16;
    const uint32_t bkb = (l & 8) ? 16 : 0;

    // epilogue constants
    const int erow = m0 + m_off + (l >> 2);
    const int ecol0 = n0 + n_off + (l & 3) * 2;

    for (int t = 0; t < TT; ++t) {
        float acc[2][4];
#pragma unroll
        for (int i = 0; i < 2; i++)
#pragma unroll
            for (int j = 0; j < 4; j++) acc[i][j] = 0.0f;

        if (t > 0) {
            long long ab0, ab1;
            if (SEQ) {
                ab0 = ((long long)(m0 + sr) * TT + (t - 1)) * HH + sc * 8;
                ab1 = ab0 + 32LL * TT * HH;
            } else {
                ab0 = (long long)((t - 1) & 1) * BB * HH + (long long)(m0 + sr) * HH + sc * 8;
                ab1 = ab0 + 32LL * HH;
            }
            // issue chunk 0
            {
                const uint32_t d = sb + RA_ST;
                CP16(d + st0,        hh + ab0);
                CP16(d + st1,        hh + ab1);
                CP16(d + 8192 + st0, hl + ab0);
                CP16(d + 8192 + st1, hl + ab1);
                CP_COMMIT();
            }
            for (int kc = 0; kc < 16; ++kc) {
                if (kc < 15) {
                    const uint32_t d = sb + RA_ST + ((kc + 1) & 1) * RA_SZ;
                    const int ko = (kc + 1) * 64;
                    CP16(d + st0,        hh + ab0 + ko);
                    CP16(d + st1,        hh + ab1 + ko);
                    CP16(d + 8192 + st0, hl + ab0 + ko);
                    CP16(d + 8192 + st1, hl + ab1 + ko);
                    CP_COMMIT();
                    CP_WAIT(1);
                } else {
                    CP_WAIT(0);
                }
                __syncthreads();

                const uint32_t abuf = sb + RA_ST + (kc & 1) * RA_SZ;
                const uint32_t bbuf = sb + RW_HI + kc * 4096;
#pragma unroll
                for (int ks = 0; ks < 4; ++ks) {
                    uint32_t ah[4], al[4], bh[4], bl[4];
                    const uint32_t ao = ((uint32_t)(ks * 32) + akb) ^ ax;
                    LDMX4(ah, abuf + abase + ao);
                    LDMX4(al, abuf + 8192 + abase + ao);
                    const uint32_t bo = ((uint32_t)(ks * 32) + bkb) ^ bx;
                    LDMX4(bh, bbuf + bbase + bo);
                    LDMX4(bl, bbuf + 65536 + bbase + bo);
                    MMA16816(acc[0], ah, bh[0], bh[1]);
                    MMA16816(acc[0], al, bh[0], bh[1]);
                    MMA16816(acc[0], ah, bl[0], bl[1]);
                    MMA16816(acc[1], ah, bh[2], bh[3]);
                    MMA16816(acc[1], al, bh[2], bh[3]);
                    MMA16816(acc[1], ah, bl[2], bl[3]);
                }
                __syncthreads();
            }
        }

        // ---- epilogue: h = relu(acc + pre_t); store bf16 hi/lo (+ final fp32) ----
#pragma unroll
        for (int nf = 0; nf < 2; ++nf) {
            const int col = ecol0 + nf * 8;
            const long long R0 = erow, R1 = erow + 8;
            const float2 p0 = __ldcg((const float2*)(pre + (R0 * TT + t) * HH + col));
            const float2 p1 = __ldcg((const float2*)(pre + (R1 * TT + t) * HH + col));
            float v0 = fmaxf(acc[nf][0] + p0.x, 0.0f);
            float v1 = fmaxf(acc[nf][1] + p0.y, 0.0f);
            float v2 = fmaxf(acc[nf][2] + p1.x, 0.0f);
            float v3 = fmaxf(acc[nf][3] + p1.y, 0.0f);
            __nv_bfloat162 h01 = __float22bfloat162_rn(make_float2(v0, v1));
            __nv_bfloat162 h23 = __float22bfloat162_rn(make_float2(v2, v3));
            float l0 = v0 - __bfloat162float(__low2bfloat16(h01));
            float l1 = v1 - __bfloat162float(__high2bfloat16(h01));
            float l2 = v2 - __bfloat162float(__low2bfloat16(h23));
            float l3 = v3 - __bfloat162float(__high2bfloat16(h23));
            __nv_bfloat162 q01 = __float22bfloat162_rn(make_float2(l0, l1));
            __nv_bfloat162 q23 = __float22bfloat162_rn(make_float2(l2, l3));
            long long ob0, ob1;
            if (SEQ) {
                ob0 = (R0 * TT + t) * HH + col;
                ob1 = (R1 * TT + t) * HH + col;
            } else {
                ob0 = (long long)(t & 1) * BB * HH + R0 * HH + col;
                ob1 = (long long)(t & 1) * BB * HH + R1 * HH + col;
            }
            __stcg((uint32_t*)(hh + ob0), *(uint32_t*)&h01);
            __stcg((uint32_t*)(hl + ob0), *(uint32_t*)&q01);
            __stcg((uint32_t*)(hh + ob1), *(uint32_t*)&h23);
            __stcg((uint32_t*)(hl + ob1), *(uint32_t*)&q23);
            if (!SEQ && t == TT - 1) {
                __stcg((float2*)(hfin + R0 * HH + col), make_float2(v0, v1));
                __stcg((float2*)(hfin + R1 * HH + col), make_float2(v2, v3));
            }
        }
        grid_bar();
    }
}

// ---------------- small scalar GEMM for fc ----------------
template <int BM, int BN, int TM, int TN>
__global__ void __launch_bounds__((BM / TM) * (BN / TN))
gemm_nt(const float* __restrict__ A, long long a_stride,
        const float* __restrict__ W, const float* __restrict__ bias,
        float* __restrict__ C, long long c_stride, int K) {
    constexpr int BK = 16, TX = BN / TN, TY = BM / TM, NT = TX * TY;
    __shared__ __align__(16) float As[BK][BM];
    __shared__ __align__(16) float Ws[BK][BN];
    const int tid = threadIdx.x, tx = tid % TX, ty = tid / TX;
    const long long m0 = (long long)blockIdx.x * BM;
    const int n0 = blockIdx.y * BN;
    float acc[TM][TN];
#pragma unroll
    for (int i = 0; i < TM; i++)
#pragma unroll
        for (int j = 0; j < TN; j++) acc[i][j] = 0.0f;
    for (int kt = 0; kt < K; kt += BK) {
#pragma unroll
        for (int idx = tid; idx < BM * 4; idx += NT) {
            const int row = idx >> 2, kq = (idx & 3) * 4;
            const float4 v = *(const float4*)(A + (m0 + row) * a_stride + kt + kq);
            As[kq][row] = v.x; As[kq + 1][row] = v.y; As[kq + 2][row] = v.z; As[kq + 3][row] = v.w;
        }
#pragma unroll
        for (int idx = tid; idx < BN * 4; idx += NT) {
            const int row = idx >> 2, kq = (idx & 3) * 4;
            const float4 v = *(const float4*)(W + (long long)(n0 + row) * K + kt + kq);
            Ws[kq][row] = v.x; Ws[kq + 1][row] = v.y; Ws[kq + 2][row] = v.z; Ws[kq + 3][row] = v.w;
        }
        __syncthreads();
#pragma unroll
        for (int kk = 0; kk < BK; kk++) {
            float a[TM], b[TN];
#pragma unroll
            for (int i = 0; i < TM; i += 4) {
                const float4 v = *(const float4*)&As[kk][ty * TM + i];
                a[i] = v.x; a[i + 1] = v.y; a[i + 2] = v.z; a[i + 3] = v.w;
            }
#pragma unroll
            for (int j = 0; j < TN; j += 4) {
                const float4 v = *(const float4*)&Ws[kk][tx * TN + j];
                b[j] = v.x; b[j + 1] = v.y; b[j + 2] = v.z; b[j + 3] = v.w;
            }
#pragma unroll
            for (int i = 0; i < TM; i++)
#pragma unroll
                for (int j = 0; j < TN; j++) acc[i][j] = fmaf(a[i], b[j], acc[i][j]);
        }
        __syncthreads();
    }
#pragma unroll
    for (int i = 0; i < TM; i++) {
        const long long m = m0 + ty * TM + i;
#pragma unroll
        for (int j = 0; j < TN; j++)
            C[m * c_stride + n0 + tx * TN + j] = acc[i][j] + bias[n0 + tx * TN + j];
    }
}

// ---------------- launch ----------------
extern "C" void kernel_launch(void* const* d_in, const int* in_sizes, int n_in,
                              void* d_out, int out_size) {
    const float* x     = (const float*)d_in[0];
    const float* W_ih0 = (const float*)d_in[1];
    const float* W_hh0 = (const float*)d_in[2];
    const float* b_ih0 = (const float*)d_in[3];
    const float* b_hh0 = (const float*)d_in[4];
    const float* W_ih1 = (const float*)d_in[5];
    const float* W_hh1 = (const float*)d_in[6];
    const float* b_ih1 = (const float*)d_in[7];
    const float* b_hh1 = (const float*)d_in[8];
    const float* fc_w  = (const float*)d_in[9];
    const float* fc_b  = (const float*)d_in[10];
    float* out = (float*)d_out;

    float *p_pre, *p_b0, *p_b1, *p_h2f;
    __nv_bfloat16 *p_xh, *p_xl, *p_h1h, *p_h1l, *p_h2h, *p_h2l;
    __nv_bfloat16 *p_wih0h, *p_wih0l, *p_wih1h, *p_wih1l;
    __nv_bfloat16 *p_whh0h, *p_whh0l, *p_whh1h, *p_whh1l;
    cudaGetSymbolAddress((void**)&p_pre, g_pre);
    cudaGetSymbolAddress((void**)&p_b0, g_bias0);
    cudaGetSymbolAddress((void**)&p_b1, g_bias1);
    cudaGetSymbolAddress((void**)&p_h2f, g_h2f);
    cudaGetSymbolAddress((void**)&p_xh, g_xh);
    cudaGetSymbolAddress((void**)&p_xl, g_xl);
    cudaGetSymbolAddress((void**)&p_h1h, g_h1h);
    cudaGetSymbolAddress((void**)&p_h1l, g_h1l);
    cudaGetSymbolAddress((void**)&p_h2h, g_h2h);
    cudaGetSymbolAddress((void**)&p_h2l, g_h2l);
    cudaGetSymbolAddress((void**)&p_wih0h, g_wih0h);
    cudaGetSymbolAddress((void**)&p_wih0l, g_wih0l);
    cudaGetSymbolAddress((void**)&p_wih1h, g_wih1h);
    cudaGetSymbolAddress((void**)&p_wih1l, g_wih1l);
    cudaGetSymbolAddress((void**)&p_whh0h, g_whh0h);
    cudaGetSymbolAddress((void**)&p_whh0l, g_whh0l);
    cudaGetSymbolAddress((void**)&p_whh1h, g_whh1h);
    cudaGetSymbolAddress((void**)&p_whh1l, g_whh1l);

    cudaFuncSetAttribute(gemm_mma, cudaFuncAttributeMaxDynamicSharedMemorySize, PG_SMEM);
    cudaFuncSetAttribute(rnn_mma<true>, cudaFuncAttributeMaxDynamicSharedMemorySize, RN_SMEM);
    cudaFuncSetAttribute(rnn_mma<false>, cudaFuncAttributeMaxDynamicSharedMemorySize, RN_SMEM);

    // prep: splits + biases
    const long long nx = (long long)BB * TT * II;
    split_f32<<<(unsigned)((nx + 255) / 256), 256>>>(x, p_xh, p_xl, nx);
    const long long nw0 = (long long)HH * II;
    split_f32<<<(unsigned)((nw0 + 255) / 256), 256>>>(W_ih0, p_wih0h, p_wih0l, nw0);
    const long long nw = (long long)HH * HH;
    split_f32<<<(unsigned)((nw + 255) / 256), 256>>>(W_hh0, p_whh0h, p_whh0l, nw);
    split_f32<<<(unsigned)((nw + 255) / 256), 256>>>(W_ih1, p_wih1h, p_wih1l, nw);
    split_f32<<<(unsigned)((nw + 255) / 256), 256>>>(W_hh1, p_whh1h, p_whh1l, nw);
    bias_combine<<<(HH + 255) / 256, 256>>>(b_ih0, b_hh0, p_b0, HH);
    bias_combine<<<(HH + 255) / 256, 256>>>(b_ih1, b_hh1, p_b1, HH);

    // pre0 = x @ W_ih0^T + bias0
    gemm_mma<<<dim3((BB * TT) / 128, HH / 128), 256, PG_SMEM>>>(
        p_xh, p_xl, p_wih0h, p_wih0l, p_b0, p_pre, II);

    // layer-0 recurrence (persistent HMMA)
    rnn_mma<true><<<128, 256, RN_SMEM>>>(p_whh0h, p_whh0l, p_pre, p_h1h, p_h1l, nullptr);

    // pre1 = h1 @ W_ih1^T + bias1
    gemm_mma<<<dim3((BB * TT) / 128, HH / 128), 256, PG_SMEM>>>(
        p_h1h, p_h1l, p_wih1h, p_wih1l, p_b1, p_pre, HH);

    // layer-1 recurrence
    rnn_mma<false><<<128, 256, RN_SMEM>>>(p_whh1h, p_whh1l, p_pre, p_h2h, p_h2l, p_h2f);

    // fc
    gemm_nt<32, 64, 4, 4><<<dim3(BB / 32, OO / 64), 128>>>(
        p_h2f, HH, fc_w, fc_b, out, OO, HH);
}

// round 6
// speedup vs baseline: 3.9612x; 1.0369x over previous
#include <cuda_runtime.h>
#include <cuda_bf16.h>
#include <cstdint>

// ---------------- problem dims ----------------
#define BB 256
#define TT 512
#define II 512
#define HH 1024
#define OO 256

// ---------------- static device scratch (allocation-free) ----------------
__device__ __align__(16) float g_pre[BB * TT * HH];
__device__ __align__(16) __nv_bfloat16 g_xh[BB * TT * II];
__device__ __align__(16) __nv_bfloat16 g_xl[BB * TT * II];
__device__ __align__(16) __nv_bfloat16 g_h1h[BB * TT * HH];
__device__ __align__(16) __nv_bfloat16 g_h1l[BB * TT * HH];
__device__ __align__(16) __nv_bfloat16 g_h2h[2 * BB * HH];
__device__ __align__(16) __nv_bfloat16 g_h2l[2 * BB * HH];
__device__ __align__(16) float g_h2f[BB * HH];
__device__ __align__(16) __nv_bfloat16 g_wih0h[HH * II], g_wih0l[HH * II];
__device__ __align__(16) __nv_bfloat16 g_wih1h[HH * HH], g_wih1l[HH * HH];
__device__ __align__(16) __nv_bfloat16 g_whh0h[HH * HH], g_whh0l[HH * HH];
__device__ __align__(16) __nv_bfloat16 g_whh1h[HH * HH], g_whh1l[HH * HH];
__device__ __align__(16) float g_bias0[HH];
__device__ __align__(16) float g_bias1[HH];
// per-group barrier state: group g uses slot g*32 (128B apart)
__device__ unsigned g_cnt2[128];
__device__ unsigned g_gen2[128];

// ---------------- PTX helpers (baseline PTX only) ----------------
__device__ __forceinline__ uint32_t smem_u32(const void* p) {
    uint32_t a;
    asm("{ .reg .u64 t; cvta.to.shared.u64 t, %1; cvt.u32.u64 %0, t; }" : "=r"(a) : "l"(p));
    return a;
}
#define CP16(dst, src) \
    asm volatile("cp.async.cg.shared.global [%0], [%1], 16;" :: "r"(dst), "l"(src) : "memory")
#define CP_COMMIT() asm volatile("cp.async.commit_group;" ::: "memory")
#define CP_WAIT(n)  asm volatile("cp.async.wait_group %0;" :: "n"(n) : "memory")

#define LDMX4(r, addr) \
    asm volatile("ldmatrix.sync.aligned.m8n8.x4.shared.b16 {%0,%1,%2,%3}, [%4];" \
                 : "=r"((r)[0]), "=r"((r)[1]), "=r"((r)[2]), "=r"((r)[3]) : "r"(addr))

#define MMA16816(d, a, b0, b1) \
    asm volatile("mma.sync.aligned.m16n8k16.row.col.f32.bf16.bf16.f32 " \
                 "{%0,%1,%2,%3},{%4,%5,%6,%7},{%8,%9},{%0,%1,%2,%3};" \
                 : "+f"((d)[0]), "+f"((d)[1]), "+f"((d)[2]), "+f"((d)[3]) \
                 : "r"((a)[0]), "r"((a)[1]), "r"((a)[2]), "r"((a)[3]), "r"(b0), "r"(b1))

// ---------------- group grid barrier (32 CTAs per group) ----------------
__device__ __forceinline__ void grid_bar_g(int g) {
    __threadfence();
    __syncthreads();
    if (threadIdx.x == 0) {
        volatile unsigned* gen = (volatile unsigned*)&g_gen2[g * 32];
        unsigned my = *gen;
        if (atomicAdd(&g_cnt2[g * 32], 1u) == 31u) {
            atomicExch(&g_cnt2[g * 32], 0u);
            __threadfence();
            *gen = my + 1;
        } else {
            while (*gen == my) { }
        }
    }
    __syncthreads();
}

// ---------------- prep kernels ----------------
__global__ void split_f32v(const float4* __restrict__ s,
                           uint2* __restrict__ hi, uint2* __restrict__ lo,
                           long long n4) {
    long long i = (long long)blockIdx.x * blockDim.x + threadIdx.x;
    if (i < n4) {
        float4 v = s[i];
        __nv_bfloat162 a = __float22bfloat162_rn(make_float2(v.x, v.y));
        __nv_bfloat162 b = __float22bfloat162_rn(make_float2(v.z, v.w));
        float rx = v.x - __bfloat162float(__low2bfloat16(a));
        float ry = v.y - __bfloat162float(__high2bfloat16(a));
        float rz = v.z - __bfloat162float(__low2bfloat16(b));
        float rw = v.w - __bfloat162float(__high2bfloat16(b));
        __nv_bfloat162 c = __float22bfloat162_rn(make_float2(rx, ry));
        __nv_bfloat162 d = __float22bfloat162_rn(make_float2(rz, rw));
        uint2 hv, lv;
        hv.x = *(uint32_t*)&a; hv.y = *(uint32_t*)&b;
        lv.x = *(uint32_t*)&c; lv.y = *(uint32_t*)&d;
        hi[i] = hv; lo[i] = lv;
    }
}
__global__ void bias_combine(const float* __restrict__ a, const float* __restrict__ b,
                             float* __restrict__ out, int n) {
    int i = blockIdx.x * blockDim.x + threadIdx.x;
    if (i < n) out[i] = a[i] + b[i];
}

// ================= HMMA pre-activation GEMM (3-stage) =================
#define PG_STAGE 65536
#define PG_SMEM  (3 * PG_STAGE)

__global__ void __launch_bounds__(256, 1)
gemm_mma(const __nv_bfloat16* __restrict__ Ah, const __nv_bfloat16* __restrict__ Al,
         const __nv_bfloat16* __restrict__ Wh, const __nv_bfloat16* __restrict__ Wl,
         const float* __restrict__ bias, float* __restrict__ C, int K) {
    extern __shared__ __align__(128) char smem[];
    const uint32_t sb = smem_u32(smem);
    const int tid = threadIdx.x, l = tid & 31, w = tid >> 5;
    const long long m0 = (long long)blockIdx.x * 128;
    const int n0 = blockIdx.y * 128;
    const int nch = K >> 6;

    const int r0 = tid >> 3, c = tid & 7;
    const uint32_t sd0 = (uint32_t)r0 * 128 + (((uint32_t)c * 16) ^ (((uint32_t)r0 & 7) * 16));

    const int m_off = (w & 3) * 32, n_off = (w >> 2) * 64;
    const int arw = m_off + (l & 7) + ((l & 8) ? 8 : 0);
    const uint32_t abase = (uint32_t)arw * 128;
    const uint32_t ax = ((uint32_t)arw & 7) * 16;
    const uint32_t akb = (l & 16) ? 16 : 0;
    const int brw = n_off + (l & 7) + ((l & 16) ? 8 : 0);
    const uint32_t bbase = (uint32_t)brw * 128;
    const uint32_t bx = ((uint32_t)brw & 7) * 16;
    const uint32_t bkb = (l & 8) ? 16 : 0;

    float acc[2][8][4];
#pragma unroll
    for (int i = 0; i < 2; i++)
#pragma unroll
        for (int j = 0; j < 8; j++)
#pragma unroll
            for (int k = 0; k < 4; k++) acc[i][j][k] = 0.0f;

    // issue chunk kc into stage kc%3
    auto issue = [&](int kc) {
        const uint32_t d = sb + (uint32_t)(kc % 3) * PG_STAGE;
        const int ko = kc * 64 + c * 8;
#pragma unroll
        for (int j = 0; j < 4; ++j) {
            const long long ar = (m0 + r0 + 32 * j) * (long long)K + ko;
            const long long wr = ((long long)(n0 + r0 + 32 * j)) * K + ko;
            const uint32_t du = d + sd0 + j * 4096;
            CP16(du,          Ah + ar);
            CP16(du + 16384,  Al + ar);
            CP16(du + 32768,  Wh + wr);
            CP16(du + 49152,  Wl + wr);
        }
        CP_COMMIT();
    };

    issue(0);
    issue(1);

    for (int kc = 0; kc < nch; ++kc) {
        if (kc < nch - 1) CP_WAIT(1); else CP_WAIT(0);
        __syncthreads();
        if (kc + 2 < nch) issue(kc + 2);

        const uint32_t st = sb + (uint32_t)(kc % 3) * PG_STAGE;
#pragma unroll
        for (int ks = 0; ks < 4; ++ks) {
            uint32_t ah0[4], al0[4], ah1[4], al1[4];
            const uint32_t ao = ((uint32_t)(ks * 32) + akb) ^ ax;
            LDMX4(ah0, st + abase + ao);
            LDMX4(al0, st + 16384 + abase + ao);
            LDMX4(ah1, st + abase + 2048 + ao);
            LDMX4(al1, st + 16384 + abase + 2048 + ao);
            uint32_t bh[4][4], bl[4][4];
            const uint32_t bo = ((uint32_t)(ks * 32) + bkb) ^ bx;
#pragma unroll
            for (int nb = 0; nb < 4; ++nb) {
                LDMX4(bh[nb], st + 32768 + bbase + nb * 2048 + bo);
                LDMX4(bl[nb], st + 49152 + bbase + nb * 2048 + bo);
            }
#pragma unroll
            for (int nb = 0; nb < 4; ++nb) {
                MMA16816(acc[0][2 * nb],     ah0, bh[nb][0], bh[nb][1]);
                MMA16816(acc[0][2 * nb],     al0, bh[nb][0], bh[nb][1]);
                MMA16816(acc[0][2 * nb],     ah0, bl[nb][0], bl[nb][1]);
                MMA16816(acc[0][2 * nb + 1], ah0, bh[nb][2], bh[nb][3]);
                MMA16816(acc[0][2 * nb + 1], al0, bh[nb][2], bh[nb][3]);
                MMA16816(acc[0][2 * nb + 1], ah0, bl[nb][2], bl[nb][3]);
                MMA16816(acc[1][2 * nb],     ah1, bh[nb][0], bh[nb][1]);
                MMA16816(acc[1][2 * nb],     al1, bh[nb][0], bh[nb][1]);
                MMA16816(acc[1][2 * nb],     ah1, bl[nb][0], bl[nb][1]);
                MMA16816(acc[1][2 * nb + 1], ah1, bh[nb][2], bh[nb][3]);
                MMA16816(acc[1][2 * nb + 1], al1, bh[nb][2], bh[nb][3]);
                MMA16816(acc[1][2 * nb + 1], ah1, bl[nb][2], bl[nb][3]);
            }
        }
        __syncthreads();
    }

#pragma unroll
    for (int mf = 0; mf < 2; ++mf) {
        const long long R0 = m0 + m_off + mf * 16 + (l >> 2);
#pragma unroll
        for (int nf = 0; nf < 8; ++nf) {
            const int col = n0 + n_off + nf * 8 + (l & 3) * 2;
            const float2 bv = __ldg((const float2*)(bias + col));
            float2 o0, o1;
            o0.x = acc[mf][nf][0] + bv.x; o0.y = acc[mf][nf][1] + bv.y;
            o1.x = acc[mf][nf][2] + bv.x; o1.y = acc[mf][nf][3] + bv.y;
            __stcg((float2*)(C + R0 * HH + col), o0);
            __stcg((float2*)(C + (R0 + 8) * HH + col), o1);
        }
    }
}

// ================= HMMA persistent recurrence =================
// grid 128 = 4 batch-groups(64 rows) x 32 H-tiles(32 cols). 256 threads.
// W hi/lo resident (128KB). A streamed: 8 chunks of 128-K, 3-stage cp.async.
#define RW_LO 65536
#define RA_ST 131072
#define RA_SZ 32768              // per stage: 2x(Ahi 8K) + 2x(Alo 8K)
#define RN_SMEM (RA_ST + 3 * RA_SZ)

template <bool SEQ>
__global__ void __launch_bounds__(256, 1)
rnn_mma(const __nv_bfloat16* __restrict__ Wh, const __nv_bfloat16* __restrict__ Wl,
        const float* __restrict__ pre,
        __nv_bfloat16* __restrict__ hh, __nv_bfloat16* __restrict__ hl,
        float* __restrict__ hfin) {
    extern __shared__ __align__(128) char smem[];
    const uint32_t sb = smem_u32(smem);
    const int tid = threadIdx.x, l = tid & 31, w = tid >> 5;
    const int grp = blockIdx.x & 3;
    const int m0 = grp * 64;
    const int n0 = (blockIdx.x >> 2) * 32;

    // resident W (hi at 0, lo at RW_LO): 16 blocks of [32 rows][128B], swizzled
    for (int u = tid; u < 4096; u += 256) {
        const int kc = u >> 8, rem = u & 255, r = rem >> 3, cc = rem & 7;
        const uint32_t dst = (uint32_t)kc * 4096 + (uint32_t)r * 128 +
                             (((uint32_t)cc * 16) ^ (((uint32_t)r & 7) * 16));
        const long long src = (long long)(n0 + r) * HH + kc * 64 + cc * 8;
        *(uint4*)(smem + dst) = *(const uint4*)(Wh + src);
        *(uint4*)(smem + RW_LO + dst) = *(const uint4*)(Wl + src);
    }
    __syncthreads();

    // staging: rows sr, sr+32 at 16B-col sc within an 8KB 64-K block
    const int sr = tid >> 3, sc = tid & 7;
    const uint32_t st0 = (uint32_t)sr * 128 + (((uint32_t)sc * 16) ^ (((uint32_t)sr & 7) * 16));
    const uint32_t st1 = st0 + 4096;

    // compute mapping (warp tile 16m x 16n)
    const int m_off = 16 * (w & 3), n_off = 16 * (w >> 2);
    const int arw = m_off + (l & 7) + ((l & 8) ? 8 : 0);
    const uint32_t abase = (uint32_t)arw * 128;
    const uint32_t ax = ((uint32_t)arw & 7) * 16;
    const uint32_t akb = (l & 16) ? 16 : 0;
    const int brw = n_off + (l & 7) + ((l & 16) ? 8 : 0);
    const uint32_t bbase = (uint32_t)brw * 128;
    const uint32_t bx = ((uint32_t)brw & 7) * 16;
    const uint32_t bkb = (l & 8) ? 16 : 0;

    const int erow = m0 + m_off + (l >> 2);
    const int ecol0 = n0 + n_off + (l & 3) * 2;

    for (int t = 0; t < TT; ++t) {
        // prefetch pre_t (independent of h) — hides L2 latency behind the pipeline
        float2 p00, p01, p10, p11;
        {
            const long long R0 = erow, R1 = erow + 8;
            p00 = __ldcg((const float2*)(pre + (R0 * TT + t) * HH + ecol0));
            p01 = __ldcg((const float2*)(pre + (R0 * TT + t) * HH + ecol0 + 8));
            p10 = __ldcg((const float2*)(pre + (R1 * TT + t) * HH + ecol0));
            p11 = __ldcg((const float2*)(pre + (R1 * TT + t) * HH + ecol0 + 8));
        }

        float acc[2][4];
#pragma unroll
        for (int i = 0; i < 2; i++)
#pragma unroll
            for (int j = 0; j < 4; j++) acc[i][j] = 0.0f;

        if (t > 0) {
            long long ab0, ab1;
            if (SEQ) {
                ab0 = ((long long)(m0 + sr) * TT + (t - 1)) * HH + sc * 8;
                ab1 = ab0 + 32LL * TT * HH;
            } else {
                ab0 = (long long)((t - 1) & 1) * BB * HH + (long long)(m0 + sr) * HH + sc * 8;
                ab1 = ab0 + 32LL * HH;
            }

            // issue chunk cix (128-K wide) into stage cix%3
            auto issueA = [&](int cix) {
                const uint32_t d = sb + RA_ST + (uint32_t)(cix % 3) * RA_SZ;
#pragma unroll
                for (int b = 0; b < 2; ++b) {
                    const int ko = cix * 128 + 64 * b;
                    CP16(d + b * 8192 + st0,         hh + ab0 + ko);
                    CP16(d + b * 8192 + st1,         hh + ab1 + ko);
                    CP16(d + 16384 + b * 8192 + st0, hl + ab0 + ko);
                    CP16(d + 16384 + b * 8192 + st1, hl + ab1 + ko);
                }
                CP_COMMIT();
            };

            issueA(0);
            issueA(1);

            for (int cix = 0; cix < 8; ++cix) {
                if (cix < 7) CP_WAIT(1); else CP_WAIT(0);
                __syncthreads();
                if (cix + 2 < 8) issueA(cix + 2);

                const uint32_t stg = sb + RA_ST + (uint32_t)(cix % 3) * RA_SZ;
#pragma unroll
                for (int b = 0; b < 2; ++b) {
                    const uint32_t abuf = stg + b * 8192;
                    const uint32_t lobuf = abuf + 16384;
                    const uint32_t bbuf = sb + (uint32_t)(2 * cix + b) * 4096;
#pragma unroll
                    for (int ks = 0; ks < 4; ++ks) {
                        uint32_t ah[4], al[4], bh[4], bl[4];
                        const uint32_t ao = ((uint32_t)(ks * 32) + akb) ^ ax;
                        LDMX4(ah, abuf + abase + ao);
                        LDMX4(al, lobuf + abase + ao);
                        const uint32_t bo = ((uint32_t)(ks * 32) + bkb) ^ bx;
                        LDMX4(bh, bbuf + bbase + bo);
                        LDMX4(bl, bbuf + RW_LO + bbase + bo);
                        MMA16816(acc[0], ah, bh[0], bh[1]);
                        MMA16816(acc[0], al, bh[0], bh[1]);
                        MMA16816(acc[0], ah, bl[0], bl[1]);
                        MMA16816(acc[1], ah, bh[2], bh[3]);
                        MMA16816(acc[1], al, bh[2], bh[3]);
                        MMA16816(acc[1], ah, bl[2], bl[3]);
                    }
                }
            }
            __syncthreads();   // all reads of last stage done before next step reuses
        }

        // ---- epilogue: h = relu(acc + pre_t); store bf16 hi/lo (+ final fp32) ----
#pragma unroll
        for (int nf = 0; nf < 2; ++nf) {
            const int col = ecol0 + nf * 8;
            const long long R0 = erow, R1 = erow + 8;
            const float2 p0 = nf ? p01 : p00;
            const float2 p1 = nf ? p11 : p10;
            float v0 = fmaxf(acc[nf][0] + p0.x, 0.0f);
            float v1 = fmaxf(acc[nf][1] + p0.y, 0.0f);
            float v2 = fmaxf(acc[nf][2] + p1.x, 0.0f);
            float v3 = fmaxf(acc[nf][3] + p1.y, 0.0f);
            __nv_bfloat162 h01 = __float22bfloat162_rn(make_float2(v0, v1));
            __nv_bfloat162 h23 = __float22bfloat162_rn(make_float2(v2, v3));
            float l0 = v0 - __bfloat162float(__low2bfloat16(h01));
            float l1 = v1 - __bfloat162float(__high2bfloat16(h01));
            float l2 = v2 - __bfloat162float(__low2bfloat16(h23));
            float l3 = v3 - __bfloat162float(__high2bfloat16(h23));
            __nv_bfloat162 q01 = __float22bfloat162_rn(make_float2(l0, l1));
            __nv_bfloat162 q23 = __float22bfloat162_rn(make_float2(l2, l3));
            long long ob0, ob1;
            if (SEQ) {
                ob0 = (R0 * TT + t) * HH + col;
                ob1 = (R1 * TT + t) * HH + col;
            } else {
                ob0 = (long long)(t & 1) * BB * HH + R0 * HH + col;
                ob1 = (long long)(t & 1) * BB * HH + R1 * HH + col;
            }
            __stcg((uint32_t*)(hh + ob0), *(uint32_t*)&h01);
            __stcg((uint32_t*)(hl + ob0), *(uint32_t*)&q01);
            __stcg((uint32_t*)(hh + ob1), *(uint32_t*)&h23);
            __stcg((uint32_t*)(hl + ob1), *(uint32_t*)&q23);
            if (!SEQ && t == TT - 1) {
                __stcg((float2*)(hfin + R0 * HH + col), make_float2(v0, v1));
                __stcg((float2*)(hfin + R1 * HH + col), make_float2(v2, v3));
            }
        }
        grid_bar_g(grp);
    }
}

// ---------------- small scalar GEMM for fc ----------------
template <int BM, int BN, int TM, int TN>
__global__ void __launch_bounds__((BM / TM) * (BN / TN))
gemm_nt(const float* __restrict__ A, long long a_stride,
        const float* __restrict__ W, const float* __restrict__ bias,
        float* __restrict__ C, long long c_stride, int K) {
    constexpr int BK = 16, TX = BN / TN, TY = BM / TM, NT = TX * TY;
    __shared__ __align__(16) float As[BK][BM];
    __shared__ __align__(16) float Ws[BK][BN];
    const int tid = threadIdx.x, tx = tid % TX, ty = tid / TX;
    const long long m0 = (long long)blockIdx.x * BM;
    const int n0 = blockIdx.y * BN;
    float acc[TM][TN];
#pragma unroll
    for (int i = 0; i < TM; i++)
#pragma unroll
        for (int j = 0; j < TN; j++) acc[i][j] = 0.0f;
    for (int kt = 0; kt < K; kt += BK) {
#pragma unroll
        for (int idx = tid; idx < BM * 4; idx += NT) {
            const int row = idx >> 2, kq = (idx & 3) * 4;
            const float4 v = *(const float4*)(A + (m0 + row) * a_stride + kt + kq);
            As[kq][row] = v.x; As[kq + 1][row] = v.y; As[kq + 2][row] = v.z; As[kq + 3][row] = v.w;
        }
#pragma unroll
        for (int idx = tid; idx < BN * 4; idx += NT) {
            const int row = idx >> 2, kq = (idx & 3) * 4;
            const float4 v = *(const float4*)(W + (long long)(n0 + row) * K + kt + kq);
            Ws[kq][row] = v.x; Ws[kq + 1][row] = v.y; Ws[kq + 2][row] = v.z; Ws[kq + 3][row] = v.w;
        }
        __syncthreads();
#pragma unroll
        for (int kk = 0; kk < BK; kk++) {
            float a[TM], b[TN];
#pragma unroll
            for (int i = 0; i < TM; i += 4) {
                const float4 v = *(const float4*)&As[kk][ty * TM + i];
                a[i] = v.x; a[i + 1] = v.y; a[i + 2] = v.z; a[i + 3] = v.w;
            }
#pragma unroll
            for (int j = 0; j < TN; j += 4) {
                const float4 v = *(const float4*)&Ws[kk][tx * TN + j];
                b[j] = v.x; b[j + 1] = v.y; b[j + 2] = v.z; b[j + 3] = v.w;
            }
#pragma unroll
            for (int i = 0; i < TM; i++)
#pragma unroll
                for (int j = 0; j < TN; j++) acc[i][j] = fmaf(a[i], b[j], acc[i][j]);
        }
        __syncthreads();
    }
#pragma unroll
    for (int i = 0; i < TM; i++) {
        const long long m = m0 + ty * TM + i;
#pragma unroll
        for (int j = 0; j < TN; j++)
            C[m * c_stride + n0 + tx * TN + j] = acc[i][j] + bias[n0 + tx * TN + j];
    }
}

// ---------------- launch ----------------
extern "C" void kernel_launch(void* const* d_in, const int* in_sizes, int n_in,
                              void* d_out, int out_size) {
    const float* x     = (const float*)d_in[0];
    const float* W_ih0 = (const float*)d_in[1];
    const float* W_hh0 = (const float*)d_in[2];
    const float* b_ih0 = (const float*)d_in[3];
    const float* b_hh0 = (const float*)d_in[4];
    const float* W_ih1 = (const float*)d_in[5];
    const float* W_hh1 = (const float*)d_in[6];
    const float* b_ih1 = (const float*)d_in[7];
    const float* b_hh1 = (const float*)d_in[8];
    const float* fc_w  = (const float*)d_in[9];
    const float* fc_b  = (const float*)d_in[10];
    float* out = (float*)d_out;

    float *p_pre, *p_b0, *p_b1, *p_h2f;
    __nv_bfloat16 *p_xh, *p_xl, *p_h1h, *p_h1l, *p_h2h, *p_h2l;
    __nv_bfloat16 *p_wih0h, *p_wih0l, *p_wih1h, *p_wih1l;
    __nv_bfloat16 *p_whh0h, *p_whh0l, *p_whh1h, *p_whh1l;
    cudaGetSymbolAddress((void**)&p_pre, g_pre);
    cudaGetSymbolAddress((void**)&p_b0, g_bias0);
    cudaGetSymbolAddress((void**)&p_b1, g_bias1);
    cudaGetSymbolAddress((void**)&p_h2f, g_h2f);
    cudaGetSymbolAddress((void**)&p_xh, g_xh);
    cudaGetSymbolAddress((void**)&p_xl, g_xl);
    cudaGetSymbolAddress((void**)&p_h1h, g_h1h);
    cudaGetSymbolAddress((void**)&p_h1l, g_h1l);
    cudaGetSymbolAddress((void**)&p_h2h, g_h2h);
    cudaGetSymbolAddress((void**)&p_h2l, g_h2l);
    cudaGetSymbolAddress((void**)&p_wih0h, g_wih0h);
    cudaGetSymbolAddress((void**)&p_wih0l, g_wih0l);
    cudaGetSymbolAddress((void**)&p_wih1h, g_wih1h);
    cudaGetSymbolAddress((void**)&p_wih1l, g_wih1l);
    cudaGetSymbolAddress((void**)&p_whh0h, g_whh0h);
    cudaGetSymbolAddress((void**)&p_whh0l, g_whh0l);
    cudaGetSymbolAddress((void**)&p_whh1h, g_whh1h);
    cudaGetSymbolAddress((void**)&p_whh1l, g_whh1l);

    cudaFuncSetAttribute(gemm_mma, cudaFuncAttributeMaxDynamicSharedMemorySize, PG_SMEM);
    cudaFuncSetAttribute(rnn_mma<true>, cudaFuncAttributeMaxDynamicSharedMemorySize, RN_SMEM);
    cudaFuncSetAttribute(rnn_mma<false>, cudaFuncAttributeMaxDynamicSharedMemorySize, RN_SMEM);

    // prep: splits (vectorized x4) + biases
    const long long nx4 = (long long)BB * TT * II / 4;
    split_f32v<<<(unsigned)((nx4 + 255) / 256), 256>>>((const float4*)x, (uint2*)p_xh, (uint2*)p_xl, nx4);
    const long long nw04 = (long long)HH * II / 4;
    split_f32v<<<(unsigned)((nw04 + 255) / 256), 256>>>((const float4*)W_ih0, (uint2*)p_wih0h, (uint2*)p_wih0l, nw04);
    const long long nw4 = (long long)HH * HH / 4;
    split_f32v<<<(unsigned)((nw4 + 255) / 256), 256>>>((const float4*)W_hh0, (uint2*)p_whh0h, (uint2*)p_whh0l, nw4);
    split_f32v<<<(unsigned)((nw4 + 255) / 256), 256>>>((const float4*)W_ih1, (uint2*)p_wih1h, (uint2*)p_wih1l, nw4);
    split_f32v<<<(unsigned)((nw4 + 255) / 256), 256>>>((const float4*)W_hh1, (uint2*)p_whh1h, (uint2*)p_whh1l, nw4);
    bias_combine<<<(HH + 255) / 256, 256>>>(b_ih0, b_hh0, p_b0, HH);
    bias_combine<<<(HH + 255) / 256, 256>>>(b_ih1, b_hh1, p_b1, HH);

    // pre0 = x @ W_ih0^T + bias0
    gemm_mma<<<dim3((BB * TT) / 128, HH / 128), 256, PG_SMEM>>>(
        p_xh, p_xl, p_wih0h, p_wih0l, p_b0, p_pre, II);

    // layer-0 recurrence
    rnn_mma<true><<<128, 256, RN_SMEM>>>(p_whh0h, p_whh0l, p_pre, p_h1h, p_h1l, nullptr);

    // pre1 = h1 @ W_ih1^T + bias1
    gemm_mma<<<dim3((BB * TT) / 128, HH / 128), 256, PG_SMEM>>>(
        p_h1h, p_h1l, p_wih1h, p_wih1l, p_b1, p_pre, HH);

    // layer-1 recurrence
    rnn_mma<false><<<128, 256, RN_SMEM>>>(p_whh1h, p_whh1l, p_pre, p_h2h, p_h2l, p_h2f);

    // fc
    gemm_nt<32, 64, 4, 4><<<dim3(BB / 32, OO / 64), 128>>>(
        p_h2f, HH, fc_w, fc_b, out, OO, HH);
}

// round 7
// speedup vs baseline: 4.3815x; 1.1061x over previous
#include <cuda_runtime.h>
#include <cuda_bf16.h>
#include <cstdint>

// ---------------- problem dims ----------------
#define BB 256
#define TT 512
#define II 512
#define HH 1024
#define OO 256

// ---------------- static device scratch (allocation-free) ----------------
__device__ __align__(16) float g_pre[BB * TT * HH];
__device__ __align__(16) __nv_bfloat16 g_xh[BB * TT * II];
__device__ __align__(16) __nv_bfloat16 g_xl[BB * TT * II];
__device__ __align__(16) __nv_bfloat16 g_h1h[BB * TT * HH];
__device__ __align__(16) __nv_bfloat16 g_h1l[BB * TT * HH];
__device__ __align__(16) __nv_bfloat16 g_h2h[2 * BB * HH];
__device__ __align__(16) __nv_bfloat16 g_h2l[2 * BB * HH];
__device__ __align__(16) float g_h2f[BB * HH];
__device__ __align__(16) __nv_bfloat16 g_wih0h[HH * II], g_wih0l[HH * II];
__device__ __align__(16) __nv_bfloat16 g_wih1h[HH * HH], g_wih1l[HH * HH];
__device__ __align__(16) __nv_bfloat16 g_whh0h[HH * HH], g_whh0l[HH * HH];
__device__ __align__(16) __nv_bfloat16 g_whh1h[HH * HH], g_whh1l[HH * HH];
__device__ __align__(16) float g_bias0[HH];
__device__ __align__(16) float g_bias1[HH];
// per-group barrier state: group g uses slot g*32 (128B apart)
__device__ unsigned g_cnt2[128];
__device__ unsigned g_gen2[128];

// ---------------- PTX helpers (baseline PTX only) ----------------
__device__ __forceinline__ uint32_t smem_u32(const void* p) {
    uint32_t a;
    asm("{ .reg .u64 t; cvta.to.shared.u64 t, %1; cvt.u32.u64 %0, t; }" : "=r"(a) : "l"(p));
    return a;
}
#define CP16(dst, src) \
    asm volatile("cp.async.cg.shared.global [%0], [%1], 16;" :: "r"(dst), "l"(src) : "memory")
#define CP_COMMIT() asm volatile("cp.async.commit_group;" ::: "memory")
#define CP_WAIT(n)  asm volatile("cp.async.wait_group %0;" :: "n"(n) : "memory")

#define LDMX4(r, addr) \
    asm volatile("ldmatrix.sync.aligned.m8n8.x4.shared.b16 {%0,%1,%2,%3}, [%4];" \
                 : "=r"((r)[0]), "=r"((r)[1]), "=r"((r)[2]), "=r"((r)[3]) : "r"(addr))

#define MMA16816(d, a, b0, b1) \
    asm volatile("mma.sync.aligned.m16n8k16.row.col.f32.bf16.bf16.f32 " \
                 "{%0,%1,%2,%3},{%4,%5,%6,%7},{%8,%9},{%0,%1,%2,%3};" \
                 : "+f"((d)[0]), "+f"((d)[1]), "+f"((d)[2]), "+f"((d)[3]) \
                 : "r"((a)[0]), "r"((a)[1]), "r"((a)[2]), "r"((a)[3]), "r"(b0), "r"(b1))

// ---------------- group grid barrier (32 CTAs per group) ----------------
__device__ __forceinline__ void grid_bar_g(int g) {
    __threadfence();
    __syncthreads();
    if (threadIdx.x == 0) {
        volatile unsigned* gen = (volatile unsigned*)&g_gen2[g * 32];
        unsigned my = *gen;
        if (atomicAdd(&g_cnt2[g * 32], 1u) == 31u) {
            atomicExch(&g_cnt2[g * 32], 0u);
            __threadfence();
            *gen = my + 1;
        } else {
            while (*gen == my) { }
        }
    }
    __syncthreads();
}

// ---------------- prep kernels ----------------
__global__ void split_f32v(const float4* __restrict__ s,
                           uint2* __restrict__ hi, uint2* __restrict__ lo,
                           long long n4) {
    long long i = (long long)blockIdx.x * blockDim.x + threadIdx.x;
    if (i < n4) {
        float4 v = s[i];
        __nv_bfloat162 a = __float22bfloat162_rn(make_float2(v.x, v.y));
        __nv_bfloat162 b = __float22bfloat162_rn(make_float2(v.z, v.w));
        float rx = v.x - __bfloat162float(__low2bfloat16(a));
        float ry = v.y - __bfloat162float(__high2bfloat16(a));
        float rz = v.z - __bfloat162float(__low2bfloat16(b));
        float rw = v.w - __bfloat162float(__high2bfloat16(b));
        __nv_bfloat162 c = __float22bfloat162_rn(make_float2(rx, ry));
        __nv_bfloat162 d = __float22bfloat162_rn(make_float2(rz, rw));
        uint2 hv, lv;
        hv.x = *(uint32_t*)&a; hv.y = *(uint32_t*)&b;
        lv.x = *(uint32_t*)&c; lv.y = *(uint32_t*)&d;
        hi[i] = hv; lo[i] = lv;
    }
}
__global__ void bias_combine(const float* __restrict__ a, const float* __restrict__ b,
                             float* __restrict__ out, int n) {
    int i = blockIdx.x * blockDim.x + threadIdx.x;
    if (i < n) out[i] = a[i] + b[i];
}

// ================= HMMA pre-activation GEMM (3-stage) =================
#define PG_STAGE 65536
#define PG_SMEM  (3 * PG_STAGE)

__global__ void __launch_bounds__(256, 1)
gemm_mma(const __nv_bfloat16* __restrict__ Ah, const __nv_bfloat16* __restrict__ Al,
         const __nv_bfloat16* __restrict__ Wh, const __nv_bfloat16* __restrict__ Wl,
         const float* __restrict__ bias, float* __restrict__ C, int K) {
    extern __shared__ __align__(128) char smem[];
    const uint32_t sb = smem_u32(smem);
    const int tid = threadIdx.x, l = tid & 31, w = tid >> 5;
    const long long m0 = (long long)blockIdx.x * 128;
    const int n0 = blockIdx.y * 128;
    const int nch = K >> 6;

    const int r0 = tid >> 3, c = tid & 7;
    const uint32_t sd0 = (uint32_t)r0 * 128 + (((uint32_t)c * 16) ^ (((uint32_t)r0 & 7) * 16));

    const int m_off = (w & 3) * 32, n_off = (w >> 2) * 64;
    const int arw = m_off + (l & 7) + ((l & 8) ? 8 : 0);
    const uint32_t abase = (uint32_t)arw * 128;
    const uint32_t ax = ((uint32_t)arw & 7) * 16;
    const uint32_t akb = (l & 16) ? 16 : 0;
    const int brw = n_off + (l & 7) + ((l & 16) ? 8 : 0);
    const uint32_t bbase = (uint32_t)brw * 128;
    const uint32_t bx = ((uint32_t)brw & 7) * 16;
    const uint32_t bkb = (l & 8) ? 16 : 0;

    float acc[2][8][4];
#pragma unroll
    for (int i = 0; i < 2; i++)
#pragma unroll
        for (int j = 0; j < 8; j++)
#pragma unroll
            for (int k = 0; k < 4; k++) acc[i][j][k] = 0.0f;

    auto issue = [&](int kc) {
        const uint32_t d = sb + (uint32_t)(kc % 3) * PG_STAGE;
        const int ko = kc * 64 + c * 8;
#pragma unroll
        for (int j = 0; j < 4; ++j) {
            const long long ar = (m0 + r0 + 32 * j) * (long long)K + ko;
            const long long wr = ((long long)(n0 + r0 + 32 * j)) * K + ko;
            const uint32_t du = d + sd0 + j * 4096;
            CP16(du,          Ah + ar);
            CP16(du + 16384,  Al + ar);
            CP16(du + 32768,  Wh + wr);
            CP16(du + 49152,  Wl + wr);
        }
        CP_COMMIT();
    };

    issue(0);
    issue(1);

    for (int kc = 0; kc < nch; ++kc) {
        if (kc < nch - 1) CP_WAIT(1); else CP_WAIT(0);
        __syncthreads();
        if (kc + 2 < nch) issue(kc + 2);

        const uint32_t st = sb + (uint32_t)(kc % 3) * PG_STAGE;
#pragma unroll
        for (int ks = 0; ks < 4; ++ks) {
            uint32_t ah0[4], al0[4], ah1[4], al1[4];
            const uint32_t ao = ((uint32_t)(ks * 32) + akb) ^ ax;
            LDMX4(ah0, st + abase + ao);
            LDMX4(al0, st + 16384 + abase + ao);
            LDMX4(ah1, st + abase + 2048 + ao);
            LDMX4(al1, st + 16384 + abase + 2048 + ao);
            uint32_t bh[4][4], bl[4][4];
            const uint32_t bo = ((uint32_t)(ks * 32) + bkb) ^ bx;
#pragma unroll
            for (int nb = 0; nb < 4; ++nb) {
                LDMX4(bh[nb], st + 32768 + bbase + nb * 2048 + bo);
                LDMX4(bl[nb], st + 49152 + bbase + nb * 2048 + bo);
            }
#pragma unroll
            for (int nb = 0; nb < 4; ++nb) {
                MMA16816(acc[0][2 * nb],     ah0, bh[nb][0], bh[nb][1]);
                MMA16816(acc[0][2 * nb],     al0, bh[nb][0], bh[nb][1]);
                MMA16816(acc[0][2 * nb],     ah0, bl[nb][0], bl[nb][1]);
                MMA16816(acc[0][2 * nb + 1], ah0, bh[nb][2], bh[nb][3]);
                MMA16816(acc[0][2 * nb + 1], al0, bh[nb][2], bh[nb][3]);
                MMA16816(acc[0][2 * nb + 1], ah0, bl[nb][2], bl[nb][3]);
                MMA16816(acc[1][2 * nb],     ah1, bh[nb][0], bh[nb][1]);
                MMA16816(acc[1][2 * nb],     al1, bh[nb][0], bh[nb][1]);
                MMA16816(acc[1][2 * nb],     ah1, bl[nb][0], bl[nb][1]);
                MMA16816(acc[1][2 * nb + 1], ah1, bh[nb][2], bh[nb][3]);
                MMA16816(acc[1][2 * nb + 1], al1, bh[nb][2], bh[nb][3]);
                MMA16816(acc[1][2 * nb + 1], ah1, bl[nb][2], bl[nb][3]);
            }
        }
        __syncthreads();
    }

#pragma unroll
    for (int mf = 0; mf < 2; ++mf) {
        const long long R0 = m0 + m_off + mf * 16 + (l >> 2);
#pragma unroll
        for (int nf = 0; nf < 8; ++nf) {
            const int col = n0 + n_off + nf * 8 + (l & 3) * 2;
            const float2 bv = __ldg((const float2*)(bias + col));
            float2 o0, o1;
            o0.x = acc[mf][nf][0] + bv.x; o0.y = acc[mf][nf][1] + bv.y;
            o1.x = acc[mf][nf][2] + bv.x; o1.y = acc[mf][nf][3] + bv.y;
            __stcg((float2*)(C + R0 * HH + col), o0);
            __stcg((float2*)(C + (R0 + 8) * HH + col), o1);
        }
    }
}

// ================= HMMA persistent recurrence (K-split warps) =================
// grid 128 = 4 batch-groups(64 rows) x 32 H-tiles(32 cols). 256 threads.
// 8 warps = 2 m-positions (32 rows each) x 4 K-slots. Warp tile 32m x 32n.
// W hi/lo resident (128KB). A streamed: 8 chunks of 128-K, 3-stage cp.async.
// Per-step 4-way K reduction through smem, then epilogue.
#define RW_LO 65536
#define RA_ST 131072
#define RA_SZ 32768              // per stage: 2x(Ahi 8K) + 2x(Alo 8K)
#define RN_SMEM (RA_ST + 3 * RA_SZ)

template <bool SEQ>
__global__ void __launch_bounds__(256, 1)
rnn_mma(const __nv_bfloat16* __restrict__ Wh, const __nv_bfloat16* __restrict__ Wl,
        const float* __restrict__ pre,
        __nv_bfloat16* __restrict__ hh, __nv_bfloat16* __restrict__ hl,
        float* __restrict__ hfin) {
    extern __shared__ __align__(128) char smem[];
    const uint32_t sb = smem_u32(smem);
    const int tid = threadIdx.x, l = tid & 31, w = tid >> 5;
    const int grp = blockIdx.x & 3;
    const int m0 = grp * 64;
    const int n0 = (blockIdx.x >> 2) * 32;

    // resident W (hi at 0, lo at RW_LO): 16 blocks of [32 rows][128B], swizzled
    for (int u = tid; u < 4096; u += 256) {
        const int kc = u >> 8, rem = u & 255, r = rem >> 3, cc = rem & 7;
        const uint32_t dst = (uint32_t)kc * 4096 + (uint32_t)r * 128 +
                             (((uint32_t)cc * 16) ^ (((uint32_t)r & 7) * 16));
        const long long src = (long long)(n0 + r) * HH + kc * 64 + cc * 8;
        *(uint4*)(smem + dst) = *(const uint4*)(Wh + src);
        *(uint4*)(smem + RW_LO + dst) = *(const uint4*)(Wl + src);
    }
    __syncthreads();

    // staging: rows sr, sr+32 at 16B-col sc within an 8KB 64-K block
    const int sr = tid >> 3, sc = tid & 7;
    const uint32_t st0 = (uint32_t)sr * 128 + (((uint32_t)sc * 16) ^ (((uint32_t)sr & 7) * 16));
    const uint32_t st1 = st0 + 4096;

    // compute mapping: warp tile 32m x 32n, K-split
    const int mpos = w & 1;            // m position: rows mpos*32..+31
    const int kslot = w >> 1;          // 0..3, owns slices {2k, 2k+1} of 8 per chunk
    const int bsel = kslot >> 1;       // 64-K block within 128-K chunk
    const int s0 = (kslot & 1) * 2;    // first k16 slice within block
    const uint32_t ax = ((uint32_t)l & 7) * 16;
    const uint32_t akb = (l & 16) ? 16u : 0u;
    const uint32_t a0base = (uint32_t)(mpos * 32 + (l & 15)) * 128;
    const uint32_t bkb = (l & 8) ? 16u : 0u;
    const uint32_t b0base = (uint32_t)((l & 7) + ((l & 16) ? 8 : 0)) * 128;

    // reduce/epilogue mapping
    const int rmp = tid >> 7;          // m position
    const int rl = (tid >> 2) & 31;    // lane within frag
    const int rfg = tid & 3;           // frag group: mf = rfg>>1, nf0 = 2*(rfg&1)
    const int rmf = rfg >> 1;
    const int erow = m0 + rmp * 32 + rmf * 16 + (rl >> 2);
    const int ecol = n0 + (rfg & 1) * 16 + (rl & 3) * 2;

    for (int t = 0; t < TT; ++t) {
        // prefetch pre_t (independent of h)
        float2 p00, p01, p10, p11;
        {
            const long long R0 = erow, R1 = erow + 8;
            p00 = __ldcg((const float2*)(pre + (R0 * TT + t) * HH + ecol));
            p01 = __ldcg((const float2*)(pre + (R0 * TT + t) * HH + ecol + 8));
            p10 = __ldcg((const float2*)(pre + (R1 * TT + t) * HH + ecol));
            p11 = __ldcg((const float2*)(pre + (R1 * TT + t) * HH + ecol + 8));
        }

        float acc[2][4][4];
#pragma unroll
        for (int i = 0; i < 2; i++)
#pragma unroll
            for (int j = 0; j < 4; j++)
#pragma unroll
                for (int k = 0; k < 4; k++) acc[i][j][k] = 0.0f;

        if (t > 0) {
            long long ab0, ab1;
            if (SEQ) {
                ab0 = ((long long)(m0 + sr) * TT + (t - 1)) * HH + sc * 8;
                ab1 = ab0 + 32LL * TT * HH;
            } else {
                ab0 = (long long)((t - 1) & 1) * BB * HH + (long long)(m0 + sr) * HH + sc * 8;
                ab1 = ab0 + 32LL * HH;
            }

            auto issueA = [&](int cix) {
                const uint32_t d = sb + RA_ST + (uint32_t)(cix % 3) * RA_SZ;
#pragma unroll
                for (int b = 0; b < 2; ++b) {
                    const int ko = cix * 128 + 64 * b;
                    CP16(d + b * 8192 + st0,         hh + ab0 + ko);
                    CP16(d + b * 8192 + st1,         hh + ab1 + ko);
                    CP16(d + 16384 + b * 8192 + st0, hl + ab0 + ko);
                    CP16(d + 16384 + b * 8192 + st1, hl + ab1 + ko);
                }
                CP_COMMIT();
            };

            issueA(0);
            issueA(1);

            for (int cix = 0; cix < 8; ++cix) {
                if (cix < 7) CP_WAIT(1); else CP_WAIT(0);
                __syncthreads();
                if (cix + 2 < 8) issueA(cix + 2);

                const uint32_t stg = sb + RA_ST + (uint32_t)(cix % 3) * RA_SZ;
                const uint32_t ahbuf = stg + (uint32_t)bsel * 8192;
                const uint32_t albuf = ahbuf + 16384;
                const uint32_t wblk = (uint32_t)(2 * cix + bsel) * 4096;
                const uint32_t bhbuf = sb + wblk;
                const uint32_t blbuf = sb + RW_LO + wblk;
#pragma unroll
                for (int si = 0; si < 2; ++si) {
                    const uint32_t ko = (uint32_t)((s0 + si) * 32);
                    const uint32_t ao = (ko + akb) ^ ax;
                    const uint32_t bo = (ko + bkb) ^ ax;
                    uint32_t ah0[4], ah1[4], al0[4], al1[4];
                    LDMX4(ah0, ahbuf + a0base + ao);
                    LDMX4(ah1, ahbuf + a0base + 2048 + ao);
                    LDMX4(al0, albuf + a0base + ao);
                    LDMX4(al1, albuf + a0base + 2048 + ao);
                    uint32_t bh0[4], bh1[4], bl0[4], bl1[4];
                    LDMX4(bh0, bhbuf + b0base + bo);
                    LDMX4(bh1, bhbuf + b0base + 2048 + bo);
                    LDMX4(bl0, blbuf + b0base + bo);
                    LDMX4(bl1, blbuf + b0base + 2048 + bo);
                    // ah x bh
                    MMA16816(acc[0][0], ah0, bh0[0], bh0[1]); MMA16816(acc[0][1], ah0, bh0[2], bh0[3]);
                    MMA16816(acc[0][2], ah0, bh1[0], bh1[1]); MMA16816(acc[0][3], ah0, bh1[2], bh1[3]);
                    MMA16816(acc[1][0], ah1, bh0[0], bh0[1]); MMA16816(acc[1][1], ah1, bh0[2], bh0[3]);
                    MMA16816(acc[1][2], ah1, bh1[0], bh1[1]); MMA16816(acc[1][3], ah1, bh1[2], bh1[3]);
                    // al x bh
                    MMA16816(acc[0][0], al0, bh0[0], bh0[1]); MMA16816(acc[0][1], al0, bh0[2], bh0[3]);
                    MMA16816(acc[0][2], al0, bh1[0], bh1[1]); MMA16816(acc[0][3], al0, bh1[2], bh1[3]);
                    MMA16816(acc[1][0], al1, bh0[0], bh0[1]); MMA16816(acc[1][1], al1, bh0[2], bh0[3]);
                    MMA16816(acc[1][2], al1, bh1[0], bh1[1]); MMA16816(acc[1][3], al1, bh1[2], bh1[3]);
                    // ah x bl
                    MMA16816(acc[0][0], ah0, bl0[0], bl0[1]); MMA16816(acc[0][1], ah0, bl0[2], bl0[3]);
                    MMA16816(acc[0][2], ah0, bl1[0], bl1[1]); MMA16816(acc[0][3], ah0, bl1[2], bl1[3]);
                    MMA16816(acc[1][0], ah1, bl0[0], bl0[1]); MMA16816(acc[1][1], ah1, bl0[2], bl0[3]);
                    MMA16816(acc[1][2], ah1, bl1[0], bl1[1]); MMA16816(acc[1][3], ah1, bl1[2], bl1[3]);
                }
            }
        }

        // ---- 4-way K reduction through smem (reuses A staging area) ----
        __syncthreads();
        {
            char* wp = smem + RA_ST + mpos * 16384 + kslot * 4096 + l * 128;
#pragma unroll
            for (int mf = 0; mf < 2; ++mf)
#pragma unroll
                for (int nf = 0; nf < 4; ++nf)
                    *(float4*)(wp + (mf * 4 + nf) * 16) = *(float4*)acc[mf][nf];
        }
        __syncthreads();
        float s[8];
#pragma unroll
        for (int j = 0; j < 8; ++j) s[j] = 0.0f;
#pragma unroll
        for (int k = 0; k < 4; ++k) {
            const char* rp = smem + RA_ST + rmp * 16384 + k * 4096 + rl * 128 + rfg * 32;
            const float4 u0 = *(const float4*)rp;
            const float4 u1 = *(const float4*)(rp + 16);
            s[0] += u0.x; s[1] += u0.y; s[2] += u0.z; s[3] += u0.w;
            s[4] += u1.x; s[5] += u1.y; s[6] += u1.z; s[7] += u1.w;
        }

        // ---- epilogue: h = relu(sum + pre_t); store bf16 hi/lo (+ final fp32) ----
#pragma unroll
        for (int nf = 0; nf < 2; ++nf) {
            const int col = ecol + nf * 8;
            const long long R0 = erow, R1 = erow + 8;
            const float2 p0 = nf ? p01 : p00;
            const float2 p1 = nf ? p11 : p10;
            float v0 = fmaxf(s[4 * nf + 0] + p0.x, 0.0f);
            float v1 = fmaxf(s[4 * nf + 1] + p0.y, 0.0f);
            float v2 = fmaxf(s[4 * nf + 2] + p1.x, 0.0f);
            float v3 = fmaxf(s[4 * nf + 3] + p1.y, 0.0f);
            __nv_bfloat162 h01 = __float22bfloat162_rn(make_float2(v0, v1));
            __nv_bfloat162 h23 = __float22bfloat162_rn(make_float2(v2, v3));
            float l0 = v0 - __bfloat162float(__low2bfloat16(h01));
            float l1 = v1 - __bfloat162float(__high2bfloat16(h01));
            float l2 = v2 - __bfloat162float(__low2bfloat16(h23));
            float l3 = v3 - __bfloat162float(__high2bfloat16(h23));
            __nv_bfloat162 q01 = __float22bfloat162_rn(make_float2(l0, l1));
            __nv_bfloat162 q23 = __float22bfloat162_rn(make_float2(l2, l3));
            long long ob0, ob1;
            if (SEQ) {
                ob0 = (R0 * TT + t) * HH + col;
                ob1 = (R1 * TT + t) * HH + col;
            } else {
                ob0 = (long long)(t & 1) * BB * HH + R0 * HH + col;
                ob1 = (long long)(t & 1) * BB * HH + R1 * HH + col;
            }
            __stcg((uint32_t*)(hh + ob0), *(uint32_t*)&h01);
            __stcg((uint32_t*)(hl + ob0), *(uint32_t*)&q01);
            __stcg((uint32_t*)(hh + ob1), *(uint32_t*)&h23);
            __stcg((uint32_t*)(hl + ob1), *(uint32_t*)&q23);
            if (!SEQ && t == TT - 1) {
                __stcg((float2*)(hfin + R0 * HH + col), make_float2(v0, v1));
                __stcg((float2*)(hfin + R1 * HH + col), make_float2(v2, v3));
            }
        }
        grid_bar_g(grp);
    }
}

// ---------------- small scalar GEMM for fc ----------------
template <int BM, int BN, int TM, int TN>
__global__ void __launch_bounds__((BM / TM) * (BN / TN))
gemm_nt(const float* __restrict__ A, long long a_stride,
        const float* __restrict__ W, const float* __restrict__ bias,
        float* __restrict__ C, long long c_stride, int K) {
    constexpr int BK = 16, TX = BN / TN, TY = BM / TM, NT = TX * TY;
    __shared__ __align__(16) float As[BK][BM];
    __shared__ __align__(16) float Ws[BK][BN];
    const int tid = threadIdx.x, tx = tid % TX, ty = tid / TX;
    const long long m0 = (long long)blockIdx.x * BM;
    const int n0 = blockIdx.y * BN;
    float acc[TM][TN];
#pragma unroll
    for (int i = 0; i < TM; i++)
#pragma unroll
        for (int j = 0; j < TN; j++) acc[i][j] = 0.0f;
    for (int kt = 0; kt < K; kt += BK) {
#pragma unroll
        for (int idx = tid; idx < BM * 4; idx += NT) {
            const int row = idx >> 2, kq = (idx & 3) * 4;
            const float4 v = *(const float4*)(A + (m0 + row) * a_stride + kt + kq);
            As[kq][row] = v.x; As[kq + 1][row] = v.y; As[kq + 2][row] = v.z; As[kq + 3][row] = v.w;
        }
#pragma unroll
        for (int idx = tid; idx < BN * 4; idx += NT) {
            const int row = idx >> 2, kq = (idx & 3) * 4;
            const float4 v = *(const float4*)(W + (long long)(n0 + row) * K + kt + kq);
            Ws[kq][row] = v.x; Ws[kq + 1][row] = v.y; Ws[kq + 2][row] = v.z; Ws[kq + 3][row] = v.w;
        }
        __syncthreads();
#pragma unroll
        for (int kk = 0; kk < BK; kk++) {
            float a[TM], b[TN];
#pragma unroll
            for (int i = 0; i < TM; i += 4) {
                const float4 v = *(const float4*)&As[kk][ty * TM + i];
                a[i] = v.x; a[i + 1] = v.y; a[i + 2] = v.z; a[i + 3] = v.w;
            }
#pragma unroll
            for (int j = 0; j < TN; j += 4) {
                const float4 v = *(const float4*)&Ws[kk][tx * TN + j];
                b[j] = v.x; b[j + 1] = v.y; b[j + 2] = v.z; b[j + 3] = v.w;
            }
#pragma unroll
            for (int i = 0; i < TM; i++)
#pragma unroll
                for (int j = 0; j < TN; j++) acc[i][j] = fmaf(a[i], b[j], acc[i][j]);
        }
        __syncthreads();
    }
#pragma unroll
    for (int i = 0; i < TM; i++) {
        const long long m = m0 + ty * TM + i;
#pragma unroll
        for (int j = 0; j < TN; j++)
            C[m * c_stride + n0 + tx * TN + j] = acc[i][j] + bias[n0 + tx * TN + j];
    }
}

// ---------------- launch ----------------
extern "C" void kernel_launch(void* const* d_in, const int* in_sizes, int n_in,
                              void* d_out, int out_size) {
    const float* x     = (const float*)d_in[0];
    const float* W_ih0 = (const float*)d_in[1];
    const float* W_hh0 = (const float*)d_in[2];
    const float* b_ih0 = (const float*)d_in[3];
    const float* b_hh0 = (const float*)d_in[4];
    const float* W_ih1 = (const float*)d_in[5];
    const float* W_hh1 = (const float*)d_in[6];
    const float* b_ih1 = (const float*)d_in[7];
    const float* b_hh1 = (const float*)d_in[8];
    const float* fc_w  = (const float*)d_in[9];
    const float* fc_b  = (const float*)d_in[10];
    float* out = (float*)d_out;

    float *p_pre, *p_b0, *p_b1, *p_h2f;
    __nv_bfloat16 *p_xh, *p_xl, *p_h1h, *p_h1l, *p_h2h, *p_h2l;
    __nv_bfloat16 *p_wih0h, *p_wih0l, *p_wih1h, *p_wih1l;
    __nv_bfloat16 *p_whh0h, *p_whh0l, *p_whh1h, *p_whh1l;
    cudaGetSymbolAddress((void**)&p_pre, g_pre);
    cudaGetSymbolAddress((void**)&p_b0, g_bias0);
    cudaGetSymbolAddress((void**)&p_b1, g_bias1);
    cudaGetSymbolAddress((void**)&p_h2f, g_h2f);
    cudaGetSymbolAddress((void**)&p_xh, g_xh);
    cudaGetSymbolAddress((void**)&p_xl, g_xl);
    cudaGetSymbolAddress((void**)&p_h1h, g_h1h);
    cudaGetSymbolAddress((void**)&p_h1l, g_h1l);
    cudaGetSymbolAddress((void**)&p_h2h, g_h2h);
    cudaGetSymbolAddress((void**)&p_h2l, g_h2l);
    cudaGetSymbolAddress((void**)&p_wih0h, g_wih0h);
    cudaGetSymbolAddress((void**)&p_wih0l, g_wih0l);
    cudaGetSymbolAddress((void**)&p_wih1h, g_wih1h);
    cudaGetSymbolAddress((void**)&p_wih1l, g_wih1l);
    cudaGetSymbolAddress((void**)&p_whh0h, g_whh0h);
    cudaGetSymbolAddress((void**)&p_whh0l, g_whh0l);
    cudaGetSymbolAddress((void**)&p_whh1h, g_whh1h);
    cudaGetSymbolAddress((void**)&p_whh1l, g_whh1l);

    cudaFuncSetAttribute(gemm_mma, cudaFuncAttributeMaxDynamicSharedMemorySize, PG_SMEM);
    cudaFuncSetAttribute(rnn_mma<true>, cudaFuncAttributeMaxDynamicSharedMemorySize, RN_SMEM);
    cudaFuncSetAttribute(rnn_mma<false>, cudaFuncAttributeMaxDynamicSharedMemorySize, RN_SMEM);

    // Launch order arranged so ncu (-s 5 -c 1) lands on gemm_mma / rnn_mma.
    const long long nx4 = (long long)BB * TT * II / 4;
    const long long nw04 = (long long)HH * II / 4;
    const long long nw4 = (long long)HH * HH / 4;

    // 1: split x
    split_f32v<<<(unsigned)((nx4 + 255) / 256), 256>>>((const float4*)x, (uint2*)p_xh, (uint2*)p_xl, nx4);
    // 2: split W_ih0
    split_f32v<<<(unsigned)((nw04 + 255) / 256), 256>>>((const float4*)W_ih0, (uint2*)p_wih0h, (uint2*)p_wih0l, nw04);
    // 3: bias0
    bias_combine<<<(HH + 255) / 256, 256>>>(b_ih0, b_hh0, p_b0, HH);
    // 4: split W_hh0
    split_f32v<<<(unsigned)((nw4 + 255) / 256), 256>>>((const float4*)W_hh0, (uint2*)p_whh0h, (uint2*)p_whh0l, nw4);
    // 5: pre0 = x @ W_ih0^T + bias0
    gemm_mma<<<dim3((BB * TT) / 128, HH / 128), 256, PG_SMEM>>>(
        p_xh, p_xl, p_wih0h, p_wih0l, p_b0, p_pre, II);
    // 6: layer-0 recurrence
    rnn_mma<true><<<128, 256, RN_SMEM>>>(p_whh0h, p_whh0l, p_pre, p_h1h, p_h1l, nullptr);
    // 7: split W_ih1
    split_f32v<<<(unsigned)((nw4 + 255) / 256), 256>>>((const float4*)W_ih1, (uint2*)p_wih1h, (uint2*)p_wih1l, nw4);
    // 8: bias1
    bias_combine<<<(HH + 255) / 256, 256>>>(b_ih1, b_hh1, p_b1, HH);
    // 9: pre1 = h1 @ W_ih1^T + bias1
    gemm_mma<<<dim3((BB * TT) / 128, HH / 128), 256, PG_SMEM>>>(
        p_h1h, p_h1l, p_wih1h, p_wih1l, p_b1, p_pre, HH);
    // 10: split W_hh1
    split_f32v<<<(unsigned)((nw4 + 255) / 256), 256>>>((const float4*)W_hh1, (uint2*)p_whh1h, (uint2*)p_whh1l, nw4);
    // 11: layer-1 recurrence
    rnn_mma<false><<<128, 256, RN_SMEM>>>(p_whh1h, p_whh1l, p_pre, p_h2h, p_h2l, p_h2f);
    // 12: fc
    gemm_nt<32, 64, 4, 4><<<dim3(BB / 32, OO / 64), 128>>>(
        p_h2f, HH, fc_w, fc_b, out, OO, HH);
}

// round 8
// speedup vs baseline: 4.7392x; 1.0816x over previous
#include <cuda_runtime.h>
#include <cuda_bf16.h>
#include <cstdint>

// ---------------- problem dims ----------------
#define BB 256
#define TT 512
#define II 512
#define HH 1024
#define OO 256

// ---------------- static device scratch (allocation-free) ----------------
__device__ __align__(16) float g_pre[BB * TT * HH];
__device__ __align__(16) __nv_bfloat16 g_xh[BB * TT * II];
__device__ __align__(16) __nv_bfloat16 g_xl[BB * TT * II];
__device__ __align__(16) __nv_bfloat16 g_h1h[BB * TT * HH];
__device__ __align__(16) __nv_bfloat16 g_h1l[BB * TT * HH];
__device__ __align__(16) __nv_bfloat16 g_h2h[2 * BB * HH];
__device__ __align__(16) __nv_bfloat16 g_h2l[2 * BB * HH];
__device__ __align__(16) float g_h2f[BB * HH];
__device__ __align__(16) __nv_bfloat16 g_wih0h[HH * II], g_wih0l[HH * II];
__device__ __align__(16) __nv_bfloat16 g_wih1h[HH * HH], g_wih1l[HH * HH];
__device__ __align__(16) __nv_bfloat16 g_whh0h[HH * HH], g_whh0l[HH * HH];
__device__ __align__(16) __nv_bfloat16 g_whh1h[HH * HH], g_whh1l[HH * HH];
__device__ __align__(16) float g_bias0[HH];
__device__ __align__(16) float g_bias1[HH];
// per-group barrier state: group g uses slot g*32 (128B apart)
__device__ unsigned g_cnt2[128];
__device__ unsigned g_gen2[128];

// ---------------- PTX helpers (baseline PTX only) ----------------
__device__ __forceinline__ uint32_t smem_u32(const void* p) {
    uint32_t a;
    asm("{ .reg .u64 t; cvta.to.shared.u64 t, %1; cvt.u32.u64 %0, t; }" : "=r"(a) : "l"(p));
    return a;
}
#define CP16(dst, src) \
    asm volatile("cp.async.cg.shared.global [%0], [%1], 16;" :: "r"(dst), "l"(src) : "memory")
#define CP_COMMIT() asm volatile("cp.async.commit_group;" ::: "memory")
#define CP_WAIT(n)  asm volatile("cp.async.wait_group %0;" :: "n"(n) : "memory")

#define LDMX4(r, addr) \
    asm volatile("ldmatrix.sync.aligned.m8n8.x4.shared.b16 {%0,%1,%2,%3}, [%4];" \
                 : "=r"((r)[0]), "=r"((r)[1]), "=r"((r)[2]), "=r"((r)[3]) : "r"(addr))

#define MMA16816(d, a, b0, b1) \
    asm volatile("mma.sync.aligned.m16n8k16.row.col.f32.bf16.bf16.f32 " \
                 "{%0,%1,%2,%3},{%4,%5,%6,%7},{%8,%9},{%0,%1,%2,%3};" \
                 : "+f"((d)[0]), "+f"((d)[1]), "+f"((d)[2]), "+f"((d)[3]) \
                 : "r"((a)[0]), "r"((a)[1]), "r"((a)[2]), "r"((a)[3]), "r"(b0), "r"(b1))

// ---------------- group grid barrier (32 CTAs per group) ----------------
__device__ __forceinline__ void grid_bar_g(int g) {
    __threadfence();
    __syncthreads();
    if (threadIdx.x == 0) {
        volatile unsigned* gen = (volatile unsigned*)&g_gen2[g * 32];
        unsigned my = *gen;
        if (atomicAdd(&g_cnt2[g * 32], 1u) == 31u) {
            atomicExch(&g_cnt2[g * 32], 0u);
            __threadfence();
            *gen = my + 1;
        } else {
            while (*gen == my) { }
        }
    }
    __syncthreads();
}

// ---------------- prep kernels ----------------
__global__ void split_f32v(const float4* __restrict__ s,
                           uint2* __restrict__ hi, uint2* __restrict__ lo,
                           long long n4) {
    long long i = (long long)blockIdx.x * blockDim.x + threadIdx.x;
    if (i < n4) {
        float4 v = s[i];
        __nv_bfloat162 a = __float22bfloat162_rn(make_float2(v.x, v.y));
        __nv_bfloat162 b = __float22bfloat162_rn(make_float2(v.z, v.w));
        float rx = v.x - __bfloat162float(__low2bfloat16(a));
        float ry = v.y - __bfloat162float(__high2bfloat16(a));
        float rz = v.z - __bfloat162float(__low2bfloat16(b));
        float rw = v.w - __bfloat162float(__high2bfloat16(b));
        __nv_bfloat162 c = __float22bfloat162_rn(make_float2(rx, ry));
        __nv_bfloat162 d = __float22bfloat162_rn(make_float2(rz, rw));
        uint2 hv, lv;
        hv.x = *(uint32_t*)&a; hv.y = *(uint32_t*)&b;
        lv.x = *(uint32_t*)&c; lv.y = *(uint32_t*)&d;
        hi[i] = hv; lo[i] = lv;
    }
}
__global__ void bias_combine(const float* __restrict__ a, const float* __restrict__ b,
                             float* __restrict__ out, int n) {
    int i = blockIdx.x * blockDim.x + threadIdx.x;
    if (i < n) out[i] = a[i] + b[i];
}

// ================= HMMA pre-activation GEMM (3-stage) =================
#define PG_STAGE 65536
#define PG_SMEM  (3 * PG_STAGE)

__global__ void __launch_bounds__(256, 1)
gemm_mma(const __nv_bfloat16* __restrict__ Ah, const __nv_bfloat16* __restrict__ Al,
         const __nv_bfloat16* __restrict__ Wh, const __nv_bfloat16* __restrict__ Wl,
         const float* __restrict__ bias, float* __restrict__ C, int K) {
    extern __shared__ __align__(128) char smem[];
    const uint32_t sb = smem_u32(smem);
    const int tid = threadIdx.x, l = tid & 31, w = tid >> 5;
    const long long m0 = (long long)blockIdx.x * 128;
    const int n0 = blockIdx.y * 128;
    const int nch = K >> 6;

    const int r0 = tid >> 3, c = tid & 7;
    const uint32_t sd0 = (uint32_t)r0 * 128 + (((uint32_t)c * 16) ^ (((uint32_t)r0 & 7) * 16));

    const int m_off = (w & 3) * 32, n_off = (w >> 2) * 64;
    const int arw = m_off + (l & 7) + ((l & 8) ? 8 : 0);
    const uint32_t abase = (uint32_t)arw * 128;
    const uint32_t ax = ((uint32_t)arw & 7) * 16;
    const uint32_t akb = (l & 16) ? 16 : 0;
    const int brw = n_off + (l & 7) + ((l & 16) ? 8 : 0);
    const uint32_t bbase = (uint32_t)brw * 128;
    const uint32_t bx = ((uint32_t)brw & 7) * 16;
    const uint32_t bkb = (l & 8) ? 16 : 0;

    float acc[2][8][4];
#pragma unroll
    for (int i = 0; i < 2; i++)
#pragma unroll
        for (int j = 0; j < 8; j++)
#pragma unroll
            for (int k = 0; k < 4; k++) acc[i][j][k] = 0.0f;

    auto issue = [&](int kc) {
        const uint32_t d = sb + (uint32_t)(kc % 3) * PG_STAGE;
        const int ko = kc * 64 + c * 8;
#pragma unroll
        for (int j = 0; j < 4; ++j) {
            const long long ar = (m0 + r0 + 32 * j) * (long long)K + ko;
            const long long wr = ((long long)(n0 + r0 + 32 * j)) * K + ko;
            const uint32_t du = d + sd0 + j * 4096;
            CP16(du,          Ah + ar);
            CP16(du + 16384,  Al + ar);
            CP16(du + 32768,  Wh + wr);
            CP16(du + 49152,  Wl + wr);
        }
        CP_COMMIT();
    };

    issue(0);
    issue(1);

    for (int kc = 0; kc < nch; ++kc) {
        if (kc < nch - 1) CP_WAIT(1); else CP_WAIT(0);
        __syncthreads();
        if (kc + 2 < nch) issue(kc + 2);

        const uint32_t st = sb + (uint32_t)(kc % 3) * PG_STAGE;
#pragma unroll
        for (int ks = 0; ks < 4; ++ks) {
            uint32_t ah0[4], al0[4], ah1[4], al1[4];
            const uint32_t ao = ((uint32_t)(ks * 32) + akb) ^ ax;
            LDMX4(ah0, st + abase + ao);
            LDMX4(al0, st + 16384 + abase + ao);
            LDMX4(ah1, st + abase + 2048 + ao);
            LDMX4(al1, st + 16384 + abase + 2048 + ao);
            uint32_t bh[4][4], bl[4][4];
            const uint32_t bo = ((uint32_t)(ks * 32) + bkb) ^ bx;
#pragma unroll
            for (int nb = 0; nb < 4; ++nb) {
                LDMX4(bh[nb], st + 32768 + bbase + nb * 2048 + bo);
                LDMX4(bl[nb], st + 49152 + bbase + nb * 2048 + bo);
            }
#pragma unroll
            for (int nb = 0; nb < 4; ++nb) {
                MMA16816(acc[0][2 * nb],     ah0, bh[nb][0], bh[nb][1]);
                MMA16816(acc[0][2 * nb],     al0, bh[nb][0], bh[nb][1]);
                MMA16816(acc[0][2 * nb],     ah0, bl[nb][0], bl[nb][1]);
                MMA16816(acc[0][2 * nb + 1], ah0, bh[nb][2], bh[nb][3]);
                MMA16816(acc[0][2 * nb + 1], al0, bh[nb][2], bh[nb][3]);
                MMA16816(acc[0][2 * nb + 1], ah0, bl[nb][2], bl[nb][3]);
                MMA16816(acc[1][2 * nb],     ah1, bh[nb][0], bh[nb][1]);
                MMA16816(acc[1][2 * nb],     al1, bh[nb][0], bh[nb][1]);
                MMA16816(acc[1][2 * nb],     ah1, bl[nb][0], bl[nb][1]);
                MMA16816(acc[1][2 * nb + 1], ah1, bh[nb][2], bh[nb][3]);
                MMA16816(acc[1][2 * nb + 1], al1, bh[nb][2], bh[nb][3]);
                MMA16816(acc[1][2 * nb + 1], ah1, bl[nb][2], bl[nb][3]);
            }
        }
        __syncthreads();
    }

#pragma unroll
    for (int mf = 0; mf < 2; ++mf) {
        const long long R0 = m0 + m_off + mf * 16 + (l >> 2);
#pragma unroll
        for (int nf = 0; nf < 8; ++nf) {
            const int col = n0 + n_off + nf * 8 + (l & 3) * 2;
            const float2 bv = __ldg((const float2*)(bias + col));
            float2 o0, o1;
            o0.x = acc[mf][nf][0] + bv.x; o0.y = acc[mf][nf][1] + bv.y;
            o1.x = acc[mf][nf][2] + bv.x; o1.y = acc[mf][nf][3] + bv.y;
            __stcg((float2*)(C + R0 * HH + col), o0);
            __stcg((float2*)(C + (R0 + 8) * HH + col), o1);
        }
    }
}

// ================= HMMA persistent recurrence (512 thr, 8-way K-split) =================
// grid 128 = 4 batch-groups(64 rows) x 32 H-tiles(32 cols). 512 threads.
// 16 warps = 2 m-positions (32 rows) x 8 K-slots (1 k16-slice per 128-K chunk).
// W hi/lo resident (128KB). A streamed: 8 chunks of 128-K, 3-stage cp.async.
// Per-step 8-way K reduction through smem (XOR-swizzled, conflict-free).
#define RW_LO 65536
#define RA_ST 131072
#define RA_SZ 32768              // per stage: 2x(Ahi 8K) + 2x(Alo 8K)
#define RN_SMEM (RA_ST + 3 * RA_SZ)

template <bool SEQ>
__global__ void __launch_bounds__(512, 1)
rnn_mma(const __nv_bfloat16* __restrict__ Wh, const __nv_bfloat16* __restrict__ Wl,
        const float* __restrict__ pre,
        __nv_bfloat16* __restrict__ hh, __nv_bfloat16* __restrict__ hl,
        float* __restrict__ hfin) {
    extern __shared__ __align__(128) char smem[];
    const uint32_t sb = smem_u32(smem);
    const int tid = threadIdx.x, l = tid & 31, w = tid >> 5;
    const int grp = blockIdx.x & 3;
    const int m0 = grp * 64;
    const int n0 = (blockIdx.x >> 2) * 32;

    // resident W (hi at 0, lo at RW_LO): 16 blocks of [32 rows][128B], swizzled
    for (int u = tid; u < 4096; u += 512) {
        const int kc = u >> 8, rem = u & 255, r = rem >> 3, cc = rem & 7;
        const uint32_t dst = (uint32_t)kc * 4096 + (uint32_t)r * 128 +
                             (((uint32_t)cc * 16) ^ (((uint32_t)r & 7) * 16));
        const long long src = (long long)(n0 + r) * HH + kc * 64 + cc * 8;
        *(uint4*)(smem + dst) = *(const uint4*)(Wh + src);
        *(uint4*)(smem + RW_LO + dst) = *(const uint4*)(Wl + src);
    }
    __syncthreads();

    // staging: one row per thread per 64-K block: row sr, 16B-col sc
    const int sr = tid >> 3, sc = tid & 7;                // sr: 0..63
    const uint32_t st0 = (uint32_t)sr * 128 + (((uint32_t)sc * 16) ^ (((uint32_t)sr & 7) * 16));

    // compute mapping: warp tile 32m x 32n, 8-way K-split
    const int mpos = w & 1;            // rows mpos*32..+31
    const int kslot = w >> 1;          // 0..7: slice index within each 128-K chunk
    const int bsel = kslot >> 2;       // 64-K block within chunk
    const int si = kslot & 3;          // k16 slice within block
    const uint32_t ax = ((uint32_t)l & 7) * 16;
    const uint32_t akb = (l & 16) ? 16u : 0u;
    const uint32_t a0base = (uint32_t)(mpos * 32 + (l & 15)) * 128;
    const uint32_t bkb = (l & 8) ? 16u : 0u;
    const uint32_t b0base = (uint32_t)((l & 7) + ((l & 16) ? 8 : 0)) * 128;
    const uint32_t kob = (uint32_t)(si * 32);
    const uint32_t ao = (kob + akb) ^ ax;
    const uint32_t bo = (kob + bkb) ^ ax;

    // reduce/epilogue mapping: tid = rmp*256 + rl*8 + rfg
    const int rmp = tid >> 8;
    const int rl = (tid >> 3) & 31;
    const int rfg = tid & 7;           // = mf*4 + nf
    const int erow = m0 + rmp * 32 + (rfg >> 2) * 16 + (rl >> 2);
    const int ecol = n0 + (rfg & 3) * 8 + (rl & 3) * 2;
    const uint32_t rsw = ((uint32_t)rfg * 16) ^ (((uint32_t)rl & 7) * 16);

    for (int t = 0; t < TT; ++t) {
        // prefetch pre_t (independent of h)
        float2 p0, p1;
        {
            p0 = __ldcg((const float2*)(pre + ((long long)erow * TT + t) * HH + ecol));
            p1 = __ldcg((const float2*)(pre + ((long long)(erow + 8) * TT + t) * HH + ecol));
        }

        float acc[2][4][4];
#pragma unroll
        for (int i = 0; i < 2; i++)
#pragma unroll
            for (int j = 0; j < 4; j++)
#pragma unroll
                for (int k = 0; k < 4; k++) acc[i][j][k] = 0.0f;

        if (t > 0) {
            long long ab;
            if (SEQ) {
                ab = ((long long)(m0 + sr) * TT + (t - 1)) * HH + sc * 8;
            } else {
                ab = (long long)((t - 1) & 1) * BB * HH + (long long)(m0 + sr) * HH + sc * 8;
            }

            auto issueA = [&](int cix) {
                const uint32_t d = sb + RA_ST + (uint32_t)(cix % 3) * RA_SZ;
#pragma unroll
                for (int b = 0; b < 2; ++b) {
                    const int ko = cix * 128 + 64 * b;
                    CP16(d + b * 8192 + st0,         hh + ab + ko);
                    CP16(d + 16384 + b * 8192 + st0, hl + ab + ko);
                }
                CP_COMMIT();
            };

            issueA(0);
            issueA(1);

            for (int cix = 0; cix < 8; ++cix) {
                if (cix < 7) CP_WAIT(1); else CP_WAIT(0);
                __syncthreads();
                if (cix + 2 < 8) issueA(cix + 2);

                const uint32_t stg = sb + RA_ST + (uint32_t)(cix % 3) * RA_SZ;
                const uint32_t ahbuf = stg + (uint32_t)bsel * 8192;
                const uint32_t albuf = ahbuf + 16384;
                const uint32_t wblk = (uint32_t)(2 * cix + bsel) * 4096;
                const uint32_t bhbuf = sb + wblk;
                const uint32_t blbuf = sb + RW_LO + wblk;

                uint32_t ah0[4], ah1[4], al0[4], al1[4];
                LDMX4(ah0, ahbuf + a0base + ao);
                LDMX4(ah1, ahbuf + a0base + 2048 + ao);
                LDMX4(al0, albuf + a0base + ao);
                LDMX4(al1, albuf + a0base + 2048 + ao);
                uint32_t bh0[4], bh1[4], bl0[4], bl1[4];
                LDMX4(bh0, bhbuf + b0base + bo);
                LDMX4(bh1, bhbuf + b0base + 2048 + bo);
                LDMX4(bl0, blbuf + b0base + bo);
                LDMX4(bl1, blbuf + b0base + 2048 + bo);
                // ah x bh
                MMA16816(acc[0][0], ah0, bh0[0], bh0[1]); MMA16816(acc[0][1], ah0, bh0[2], bh0[3]);
                MMA16816(acc[0][2], ah0, bh1[0], bh1[1]); MMA16816(acc[0][3], ah0, bh1[2], bh1[3]);
                MMA16816(acc[1][0], ah1, bh0[0], bh0[1]); MMA16816(acc[1][1], ah1, bh0[2], bh0[3]);
                MMA16816(acc[1][2], ah1, bh1[0], bh1[1]); MMA16816(acc[1][3], ah1, bh1[2], bh1[3]);
                // al x bh
                MMA16816(acc[0][0], al0, bh0[0], bh0[1]); MMA16816(acc[0][1], al0, bh0[2], bh0[3]);
                MMA16816(acc[0][2], al0, bh1[0], bh1[1]); MMA16816(acc[0][3], al0, bh1[2], bh1[3]);
                MMA16816(acc[1][0], al1, bh0[0], bh0[1]); MMA16816(acc[1][1], al1, bh0[2], bh0[3]);
                MMA16816(acc[1][2], al1, bh1[0], bh1[1]); MMA16816(acc[1][3], al1, bh1[2], bh1[3]);
                // ah x bl
                MMA16816(acc[0][0], ah0, bl0[0], bl0[1]); MMA16816(acc[0][1], ah0, bl0[2], bl0[3]);
                MMA16816(acc[0][2], ah0, bl1[0], bl1[1]); MMA16816(acc[0][3], ah0, bl1[2], bl1[3]);
                MMA16816(acc[1][0], ah1, bl0[0], bl0[1]); MMA16816(acc[1][1], ah1, bl0[2], bl0[3]);
                MMA16816(acc[1][2], ah1, bl1[0], bl1[1]); MMA16816(acc[1][3], ah1, bl1[2], bl1[3]);
            }
        }

        // ---- 8-way K reduction through smem (XOR-swizzled, conflict-free) ----
        __syncthreads();
        {
            char* wp = smem + RA_ST + mpos * 32768 + kslot * 4096 + l * 128;
            const uint32_t wsw = ((uint32_t)l & 7) * 16;
#pragma unroll
            for (int mf = 0; mf < 2; ++mf)
#pragma unroll
                for (int nf = 0; nf < 4; ++nf)
                    *(float4*)(wp + (((uint32_t)(mf * 4 + nf) * 16) ^ wsw)) = *(float4*)acc[mf][nf];
        }
        __syncthreads();
        float s[4];
        s[0] = s[1] = s[2] = s[3] = 0.0f;
#pragma unroll
        for (int k = 0; k < 8; ++k) {
            const float4 u = *(const float4*)(smem + RA_ST + rmp * 32768 + k * 4096 +
                                              rl * 128 + rsw);
            s[0] += u.x; s[1] += u.y; s[2] += u.z; s[3] += u.w;
        }

        // ---- epilogue: h = relu(sum + pre_t); store bf16 hi/lo (+ final fp32) ----
        {
            const long long R0 = erow, R1 = erow + 8;
            float v0 = fmaxf(s[0] + p0.x, 0.0f);
            float v1 = fmaxf(s[1] + p0.y, 0.0f);
            float v2 = fmaxf(s[2] + p1.x, 0.0f);
            float v3 = fmaxf(s[3] + p1.y, 0.0f);
            __nv_bfloat162 h01 = __float22bfloat162_rn(make_float2(v0, v1));
            __nv_bfloat162 h23 = __float22bfloat162_rn(make_float2(v2, v3));
            float l0 = v0 - __bfloat162float(__low2bfloat16(h01));
            float l1 = v1 - __bfloat162float(__high2bfloat16(h01));
            float l2 = v2 - __bfloat162float(__low2bfloat16(h23));
            float l3 = v3 - __bfloat162float(__high2bfloat16(h23));
            __nv_bfloat162 q01 = __float22bfloat162_rn(make_float2(l0, l1));
            __nv_bfloat162 q23 = __float22bfloat162_rn(make_float2(l2, l3));
            long long ob0, ob1;
            if (SEQ) {
                ob0 = (R0 * TT + t) * HH + ecol;
                ob1 = (R1 * TT + t) * HH + ecol;
            } else {
                ob0 = (long long)(t & 1) * BB * HH + R0 * HH + ecol;
                ob1 = (long long)(t & 1) * BB * HH + R1 * HH + ecol;
            }
            __stcg((uint32_t*)(hh + ob0), *(uint32_t*)&h01);
            __stcg((uint32_t*)(hl + ob0), *(uint32_t*)&q01);
            __stcg((uint32_t*)(hh + ob1), *(uint32_t*)&h23);
            __stcg((uint32_t*)(hl + ob1), *(uint32_t*)&q23);
            if (!SEQ && t == TT - 1) {
                __stcg((float2*)(hfin + R0 * HH + ecol), make_float2(v0, v1));
                __stcg((float2*)(hfin + R1 * HH + ecol), make_float2(v2, v3));
            }
        }
        grid_bar_g(grp);
    }
}

// ---------------- small scalar GEMM for fc ----------------
template <int BM, int BN, int TM, int TN>
__global__ void __launch_bounds__((BM / TM) * (BN / TN))
gemm_nt(const float* __restrict__ A, long long a_stride,
        const float* __restrict__ W, const float* __restrict__ bias,
        float* __restrict__ C, long long c_stride, int K) {
    constexpr int BK = 16, TX = BN / TN, TY = BM / TM, NT = TX * TY;
    __shared__ __align__(16) float As[BK][BM];
    __shared__ __align__(16) float Ws[BK][BN];
    const int tid = threadIdx.x, tx = tid % TX, ty = tid / TX;
    const long long m0 = (long long)blockIdx.x * BM;
    const int n0 = blockIdx.y * BN;
    float acc[TM][TN];
#pragma unroll
    for (int i = 0; i < TM; i++)
#pragma unroll
        for (int j = 0; j < TN; j++) acc[i][j] = 0.0f;
    for (int kt = 0; kt < K; kt += BK) {
#pragma unroll
        for (int idx = tid; idx < BM * 4; idx += NT) {
            const int row = idx >> 2, kq = (idx & 3) * 4;
            const float4 v = *(const float4*)(A + (m0 + row) * a_stride + kt + kq);
            As[kq][row] = v.x; As[kq + 1][row] = v.y; As[kq + 2][row] = v.z; As[kq + 3][row] = v.w;
        }
#pragma unroll
        for (int idx = tid; idx < BN * 4; idx += NT) {
            const int row = idx >> 2, kq = (idx & 3) * 4;
            const float4 v = *(const float4*)(W + (long long)(n0 + row) * K + kt + kq);
            Ws[kq][row] = v.x; Ws[kq + 1][row] = v.y; Ws[kq + 2][row] = v.z; Ws[kq + 3][row] = v.w;
        }
        __syncthreads();
#pragma unroll
        for (int kk = 0; kk < BK; kk++) {
            float a[TM], b[TN];
#pragma unroll
            for (int i = 0; i < TM; i += 4) {
                const float4 v = *(const float4*)&As[kk][ty * TM + i];
                a[i] = v.x; a[i + 1] = v.y; a[i + 2] = v.z; a[i + 3] = v.w;
            }
#pragma unroll
            for (int j = 0; j < TN; j += 4) {
                const float4 v = *(const float4*)&Ws[kk][tx * TN + j];
                b[j] = v.x; b[j + 1] = v.y; b[j + 2] = v.z; b[j + 3] = v.w;
            }
#pragma unroll
            for (int i = 0; i < TM; i++)
#pragma unroll
                for (int j = 0; j < TN; j++) acc[i][j] = fmaf(a[i], b[j], acc[i][j]);
        }
        __syncthreads();
    }
#pragma unroll
    for (int i = 0; i < TM; i++) {
        const long long m = m0 + ty * TM + i;
#pragma unroll
        for (int j = 0; j < TN; j++)
            C[m * c_stride + n0 + tx * TN + j] = acc[i][j] + bias[n0 + tx * TN + j];
    }
}

// ---------------- launch ----------------
extern "C" void kernel_launch(void* const* d_in, const int* in_sizes, int n_in,
                              void* d_out, int out_size) {
    const float* x     = (const float*)d_in[0];
    const float* W_ih0 = (const float*)d_in[1];
    const float* W_hh0 = (const float*)d_in[2];
    const float* b_ih0 = (const float*)d_in[3];
    const float* b_hh0 = (const float*)d_in[4];
    const float* W_ih1 = (const float*)d_in[5];
    const float* W_hh1 = (const float*)d_in[6];
    const float* b_ih1 = (const float*)d_in[7];
    const float* b_hh1 = (const float*)d_in[8];
    const float* fc_w  = (const float*)d_in[9];
    const float* fc_b  = (const float*)d_in[10];
    float* out = (float*)d_out;

    float *p_pre, *p_b0, *p_b1, *p_h2f;
    __nv_bfloat16 *p_xh, *p_xl, *p_h1h, *p_h1l, *p_h2h, *p_h2l;
    __nv_bfloat16 *p_wih0h, *p_wih0l, *p_wih1h, *p_wih1l;
    __nv_bfloat16 *p_whh0h, *p_whh0l, *p_whh1h, *p_whh1l;
    cudaGetSymbolAddress((void**)&p_pre, g_pre);
    cudaGetSymbolAddress((void**)&p_b0, g_bias0);
    cudaGetSymbolAddress((void**)&p_b1, g_bias1);
    cudaGetSymbolAddress((void**)&p_h2f, g_h2f);
    cudaGetSymbolAddress((void**)&p_xh, g_xh);
    cudaGetSymbolAddress((void**)&p_xl, g_xl);
    cudaGetSymbolAddress((void**)&p_h1h, g_h1h);
    cudaGetSymbolAddress((void**)&p_h1l, g_h1l);
    cudaGetSymbolAddress((void**)&p_h2h, g_h2h);
    cudaGetSymbolAddress((void**)&p_h2l, g_h2l);
    cudaGetSymbolAddress((void**)&p_wih0h, g_wih0h);
    cudaGetSymbolAddress((void**)&p_wih0l, g_wih0l);
    cudaGetSymbolAddress((void**)&p_wih1h, g_wih1h);
    cudaGetSymbolAddress((void**)&p_wih1l, g_wih1l);
    cudaGetSymbolAddress((void**)&p_whh0h, g_whh0h);
    cudaGetSymbolAddress((void**)&p_whh0l, g_whh0l);
    cudaGetSymbolAddress((void**)&p_whh1h, g_whh1h);
    cudaGetSymbolAddress((void**)&p_whh1l, g_whh1l);

    cudaFuncSetAttribute(gemm_mma, cudaFuncAttributeMaxDynamicSharedMemorySize, PG_SMEM);
    cudaFuncSetAttribute(rnn_mma<true>, cudaFuncAttributeMaxDynamicSharedMemorySize, RN_SMEM);
    cudaFuncSetAttribute(rnn_mma<false>, cudaFuncAttributeMaxDynamicSharedMemorySize, RN_SMEM);

    const long long nx4 = (long long)BB * TT * II / 4;
    const long long nw04 = (long long)HH * II / 4;
    const long long nw4 = (long long)HH * HH / 4;

    // 1: split x
    split_f32v<<<(unsigned)((nx4 + 255) / 256), 256>>>((const float4*)x, (uint2*)p_xh, (uint2*)p_xl, nx4);
    // 2: split W_ih0
    split_f32v<<<(unsigned)((nw04 + 255) / 256), 256>>>((const float4*)W_ih0, (uint2*)p_wih0h, (uint2*)p_wih0l, nw04);
    // 3: bias0
    bias_combine<<<(HH + 255) / 256, 256>>>(b_ih0, b_hh0, p_b0, HH);
    // 4: split W_hh0
    split_f32v<<<(unsigned)((nw4 + 255) / 256), 256>>>((const float4*)W_hh0, (uint2*)p_whh0h, (uint2*)p_whh0l, nw4);
    // 5: pre0 = x @ W_ih0^T + bias0
    gemm_mma<<<dim3((BB * TT) / 128, HH / 128), 256, PG_SMEM>>>(
        p_xh, p_xl, p_wih0h, p_wih0l, p_b0, p_pre, II);
    // 6: layer-0 recurrence
    rnn_mma<true><<<128, 512, RN_SMEM>>>(p_whh0h, p_whh0l, p_pre, p_h1h, p_h1l, nullptr);
    // 7: split W_ih1
    split_f32v<<<(unsigned)((nw4 + 255) / 256), 256>>>((const float4*)W_ih1, (uint2*)p_wih1h, (uint2*)p_wih1l, nw4);
    // 8: bias1
    bias_combine<<<(HH + 255) / 256, 256>>>(b_ih1, b_hh1, p_b1, HH);
    // 9: pre1 = h1 @ W_ih1^T + bias1
    gemm_mma<<<dim3((BB * TT) / 128, HH / 128), 256, PG_SMEM>>>(
        p_h1h, p_h1l, p_wih1h, p_wih1l, p_b1, p_pre, HH);
    // 10: split W_hh1
    split_f32v<<<(unsigned)((nw4 + 255) / 256), 256>>>((const float4*)W_hh1, (uint2*)p_whh1h, (uint2*)p_whh1l, nw4);
    // 11: layer-1 recurrence
    rnn_mma<false><<<128, 512, RN_SMEM>>>(p_whh1h, p_whh1l, p_pre, p_h2h, p_h2l, p_h2f);
    // 12: fc
    gemm_nt<32, 64, 4, 4><<<dim3(BB / 32, OO / 64), 128>>>(
        p_h2f, HH, fc_w, fc_b, out, OO, HH);
}

// round 9
// speedup vs baseline: 5.9173x; 1.2486x over previous
#include <cuda_runtime.h>
#include <cuda_fp16.h>
#include <cstdint>

// ---------------- problem dims ----------------
#define BB 256
#define TT 512
#define II 512
#define HH 1024
#define OO 256

// ---------------- static device scratch (allocation-free) ----------------
__device__ __align__(16) float g_pre[BB * TT * HH];
__device__ __align__(16) __half g_xf[BB * TT * II];          // x as fp16
__device__ __align__(16) __half g_h1f[BB * TT * HH];         // layer0 hidden seq fp16
__device__ __align__(16) __half g_h2f16[2 * BB * HH];        // layer1 ping-pong fp16
__device__ __align__(16) float g_h2f[BB * HH];               // layer1 final fp32
__device__ __align__(16) __half g_wih0h[HH * II], g_wih0l[HH * II];
__device__ __align__(16) __half g_wih1h[HH * HH], g_wih1l[HH * HH];
__device__ __align__(16) __half g_whh0h[HH * HH], g_whh0l[HH * HH];
__device__ __align__(16) __half g_whh1h[HH * HH], g_whh1l[HH * HH];
__device__ __align__(16) float g_bias0[HH];
__device__ __align__(16) float g_bias1[HH];
// per-group barrier state: group g uses slot g*32 (128B apart)
__device__ unsigned g_cnt2[128];
__device__ unsigned g_gen2[128];

// ---------------- PTX helpers (baseline PTX only) ----------------
__device__ __forceinline__ uint32_t smem_u32(const void* p) {
    uint32_t a;
    asm("{ .reg .u64 t; cvta.to.shared.u64 t, %1; cvt.u32.u64 %0, t; }" : "=r"(a) : "l"(p));
    return a;
}
#define CP16(dst, src) \
    asm volatile("cp.async.cg.shared.global [%0], [%1], 16;" :: "r"(dst), "l"(src) : "memory")
#define CP_COMMIT() asm volatile("cp.async.commit_group;" ::: "memory")
#define CP_WAIT(n)  asm volatile("cp.async.wait_group %0;" :: "n"(n) : "memory")

#define LDMX4(r, addr) \
    asm volatile("ldmatrix.sync.aligned.m8n8.x4.shared.b16 {%0,%1,%2,%3}, [%4];" \
                 : "=r"((r)[0]), "=r"((r)[1]), "=r"((r)[2]), "=r"((r)[3]) : "r"(addr))

#define MMAH16816(d, a, b0, b1) \
    asm volatile("mma.sync.aligned.m16n8k16.row.col.f32.f16.f16.f32 " \
                 "{%0,%1,%2,%3},{%4,%5,%6,%7},{%8,%9},{%0,%1,%2,%3};" \
                 : "+f"((d)[0]), "+f"((d)[1]), "+f"((d)[2]), "+f"((d)[3]) \
                 : "r"((a)[0]), "r"((a)[1]), "r"((a)[2]), "r"((a)[3]), "r"(b0), "r"(b1))

// ---------------- group grid barrier (32 CTAs per group) ----------------
__device__ __forceinline__ void grid_bar_g(int g) {
    __threadfence();
    __syncthreads();
    if (threadIdx.x == 0) {
        volatile unsigned* gen = (volatile unsigned*)&g_gen2[g * 32];
        unsigned my = *gen;
        if (atomicAdd(&g_cnt2[g * 32], 1u) == 31u) {
            atomicExch(&g_cnt2[g * 32], 0u);
            __threadfence();
            *gen = my + 1;
        } else {
            while (*gen == my) { }
        }
    }
    __syncthreads();
}

// ---------------- prep kernels ----------------
// fp32 -> fp16 (single)
__global__ void to_f16v(const float4* __restrict__ s, uint2* __restrict__ o, long long n4) {
    long long i = (long long)blockIdx.x * blockDim.x + threadIdx.x;
    if (i < n4) {
        float4 v = s[i];
        __half2 a = __floats2half2_rn(v.x, v.y);
        __half2 b = __floats2half2_rn(v.z, v.w);
        uint2 r;
        r.x = *(uint32_t*)&a; r.y = *(uint32_t*)&b;
        o[i] = r;
    }
}
// fp32 -> fp16 hi + fp16 lo
__global__ void split_f16v(const float4* __restrict__ s,
                           uint2* __restrict__ hi, uint2* __restrict__ lo, long long n4) {
    long long i = (long long)blockIdx.x * blockDim.x + threadIdx.x;
    if (i < n4) {
        float4 v = s[i];
        __half hx = __float2half_rn(v.x), hy = __float2half_rn(v.y);
        __half hz = __float2half_rn(v.z), hw = __float2half_rn(v.w);
        __half lx = __float2half_rn(v.x - __half2float(hx));
        __half ly = __float2half_rn(v.y - __half2float(hy));
        __half lz = __float2half_rn(v.z - __half2float(hz));
        __half lw = __float2half_rn(v.w - __half2float(hw));
        __half2 a = __halves2half2(hx, hy), b = __halves2half2(hz, hw);
        __half2 c = __halves2half2(lx, ly), d = __halves2half2(lz, lw);
        uint2 hv, lv;
        hv.x = *(uint32_t*)&a; hv.y = *(uint32_t*)&b;
        lv.x = *(uint32_t*)&c; lv.y = *(uint32_t*)&d;
        hi[i] = hv; lo[i] = lv;
    }
}
__global__ void bias_combine(const float* __restrict__ a, const float* __restrict__ b,
                             float* __restrict__ out, int n) {
    int i = blockIdx.x * blockDim.x + threadIdx.x;
    if (i < n) out[i] = a[i] + b[i];
}

// ================= fp16 HMMA pre-activation GEMM (2-pass, 3-stage) =================
// C[M][1024] = A @ (Wh+Wl)^T + bias.  A fp16, W fp16 hi/lo.
// Tile 128x128, 256 thr (8 warps: 4m x 2n, warp tile 32x64), 64-K chunks.
// Stage (48KB): A @0 (16K), Wh @16384, Wl @32768.
#define PG_STAGE 49152
#define PG_SMEM  (3 * PG_STAGE)

__global__ void __launch_bounds__(256, 1)
gemm_mma(const __half* __restrict__ Af,
         const __half* __restrict__ Wh, const __half* __restrict__ Wl,
         const float* __restrict__ bias, float* __restrict__ C, int K) {
    extern __shared__ __align__(128) char smem[];
    const uint32_t sb = smem_u32(smem);
    const int tid = threadIdx.x, l = tid & 31, w = tid >> 5;
    const long long m0 = (long long)blockIdx.x * 128;
    const int n0 = blockIdx.y * 128;
    const int nch = K >> 6;

    const int r0 = tid >> 3, c = tid & 7;
    const uint32_t sd0 = (uint32_t)r0 * 128 + (((uint32_t)c * 16) ^ (((uint32_t)r0 & 7) * 16));

    const int m_off = (w & 3) * 32, n_off = (w >> 2) * 64;
    const int arw = m_off + (l & 7) + ((l & 8) ? 8 : 0);
    const uint32_t abase = (uint32_t)arw * 128;
    const uint32_t ax = ((uint32_t)arw & 7) * 16;
    const uint32_t akb = (l & 16) ? 16 : 0;
    const int brw = n_off + (l & 7) + ((l & 16) ? 8 : 0);
    const uint32_t bbase = (uint32_t)brw * 128;
    const uint32_t bx = ((uint32_t)brw & 7) * 16;
    const uint32_t bkb = (l & 8) ? 16 : 0;

    float acc[2][8][4];
#pragma unroll
    for (int i = 0; i < 2; i++)
#pragma unroll
        for (int j = 0; j < 8; j++)
#pragma unroll
            for (int k = 0; k < 4; k++) acc[i][j][k] = 0.0f;

    auto issue = [&](int kc) {
        const uint32_t d = sb + (uint32_t)(kc % 3) * PG_STAGE;
        const int ko = kc * 64 + c * 8;
#pragma unroll
        for (int j = 0; j < 4; ++j) {
            const long long ar = (m0 + r0 + 32 * j) * (long long)K + ko;
            const long long wr = ((long long)(n0 + r0 + 32 * j)) * K + ko;
            const uint32_t du = d + sd0 + j * 4096;
            CP16(du,          Af + ar);
            CP16(du + 16384,  Wh + wr);
            CP16(du + 32768,  Wl + wr);
        }
        CP_COMMIT();
    };

    issue(0);
    issue(1);

    for (int kc = 0; kc < nch; ++kc) {
        if (kc < nch - 1) CP_WAIT(1); else CP_WAIT(0);
        __syncthreads();
        if (kc + 2 < nch) issue(kc + 2);

        const uint32_t st = sb + (uint32_t)(kc % 3) * PG_STAGE;
#pragma unroll
        for (int ks = 0; ks < 4; ++ks) {
            uint32_t ah0[4], ah1[4];
            const uint32_t ao = ((uint32_t)(ks * 32) + akb) ^ ax;
            LDMX4(ah0, st + abase + ao);
            LDMX4(ah1, st + abase + 2048 + ao);
            uint32_t bh[4][4], bl[4][4];
            const uint32_t bo = ((uint32_t)(ks * 32) + bkb) ^ bx;
#pragma unroll
            for (int nb = 0; nb < 4; ++nb) {
                LDMX4(bh[nb], st + 16384 + bbase + nb * 2048 + bo);
                LDMX4(bl[nb], st + 32768 + bbase + nb * 2048 + bo);
            }
#pragma unroll
            for (int nb = 0; nb < 4; ++nb) {
                MMAH16816(acc[0][2 * nb],     ah0, bh[nb][0], bh[nb][1]);
                MMAH16816(acc[0][2 * nb],     ah0, bl[nb][0], bl[nb][1]);
                MMAH16816(acc[0][2 * nb + 1], ah0, bh[nb][2], bh[nb][3]);
                MMAH16816(acc[0][2 * nb + 1], ah0, bl[nb][2], bl[nb][3]);
                MMAH16816(acc[1][2 * nb],     ah1, bh[nb][0], bh[nb][1]);
                MMAH16816(acc[1][2 * nb],     ah1, bl[nb][0], bl[nb][1]);
                MMAH16816(acc[1][2 * nb + 1], ah1, bh[nb][2], bh[nb][3]);
                MMAH16816(acc[1][2 * nb + 1], ah1, bl[nb][2], bl[nb][3]);
            }
        }
        __syncthreads();
    }

#pragma unroll
    for (int mf = 0; mf < 2; ++mf) {
        const long long R0 = m0 + m_off + mf * 16 + (l >> 2);
#pragma unroll
        for (int nf = 0; nf < 8; ++nf) {
            const int col = n0 + n_off + nf * 8 + (l & 3) * 2;
            const float2 bv = __ldg((const float2*)(bias + col));
            float2 o0, o1;
            o0.x = acc[mf][nf][0] + bv.x; o0.y = acc[mf][nf][1] + bv.y;
            o1.x = acc[mf][nf][2] + bv.x; o1.y = acc[mf][nf][3] + bv.y;
            __stcg((float2*)(C + R0 * HH + col), o0);
            __stcg((float2*)(C + (R0 + 8) * HH + col), o1);
        }
    }
}

// ================= fp16 HMMA persistent recurrence (512 thr, 8-way K-split) =================
// grid 128 = 4 batch-groups(64 rows) x 32 H-tiles(32 cols). 512 threads.
// 16 warps = 2 m-positions (32 rows) x 8 K-slots (1 k16-slice per 128-K chunk).
// W fp16 hi/lo resident (128KB). A (h fp16) streamed: 8 chunks of 128-K, 3-stage.
// 2 passes: A*Wh + A*Wl.  8-way K reduction through smem (XOR-swizzled).
#define RW_LO 65536
#define RA_ST 131072
#define RA_STG 16384             // per stage: 2 x 8KB 64-K sub-blocks
#define RN_SMEM (RA_ST + 65536)  // stages use 48KB of this; reduce uses 64KB

template <bool SEQ>
__global__ void __launch_bounds__(512, 1)
rnn_mma(const __half* __restrict__ Wh, const __half* __restrict__ Wl,
        const float* __restrict__ pre,
        __half* __restrict__ hf, float* __restrict__ hfin) {
    extern __shared__ __align__(128) char smem[];
    const uint32_t sb = smem_u32(smem);
    const int tid = threadIdx.x, l = tid & 31, w = tid >> 5;
    const int grp = blockIdx.x & 3;
    const int m0 = grp * 64;
    const int n0 = (blockIdx.x >> 2) * 32;

    // resident W (hi at 0, lo at RW_LO): 16 blocks of [32 rows][128B], swizzled
    for (int u = tid; u < 4096; u += 512) {
        const int kc = u >> 8, rem = u & 255, r = rem >> 3, cc = rem & 7;
        const uint32_t dst = (uint32_t)kc * 4096 + (uint32_t)r * 128 +
                             (((uint32_t)cc * 16) ^ (((uint32_t)r & 7) * 16));
        const long long src = (long long)(n0 + r) * HH + kc * 64 + cc * 8;
        *(uint4*)(smem + dst) = *(const uint4*)(Wh + src);
        *(uint4*)(smem + RW_LO + dst) = *(const uint4*)(Wl + src);
    }
    __syncthreads();

    // staging: one row per thread per 64-K sub-block: row sr, 16B-col sc
    const int sr = tid >> 3, sc = tid & 7;                // sr: 0..63
    const uint32_t st0 = (uint32_t)sr * 128 + (((uint32_t)sc * 16) ^ (((uint32_t)sr & 7) * 16));

    // compute mapping: warp tile 32m x 32n, 8-way K-split
    const int mpos = w & 1;
    const int kslot = w >> 1;          // 0..7
    const int bsel = kslot >> 2;       // 64-K sub-block within chunk
    const int si = kslot & 3;          // k16 slice within sub-block
    const uint32_t ax = ((uint32_t)l & 7) * 16;
    const uint32_t akb = (l & 16) ? 16u : 0u;
    const uint32_t a0base = (uint32_t)(mpos * 32 + (l & 15)) * 128;
    const uint32_t bkb = (l & 8) ? 16u : 0u;
    const uint32_t b0base = (uint32_t)((l & 7) + ((l & 16) ? 8 : 0)) * 128;
    const uint32_t kob = (uint32_t)(si * 32);
    const uint32_t ao = (kob + akb) ^ ax;
    const uint32_t bo = (kob + bkb) ^ ax;

    // reduce/epilogue mapping: tid = rmp*256 + rl*8 + rfg
    const int rmp = tid >> 8;
    const int rl = (tid >> 3) & 31;
    const int rfg = tid & 7;
    const int erow = m0 + rmp * 32 + (rfg >> 2) * 16 + (rl >> 2);
    const int ecol = n0 + (rfg & 3) * 8 + (rl & 3) * 2;
    const uint32_t rsw = ((uint32_t)rfg * 16) ^ (((uint32_t)rl & 7) * 16);

    for (int t = 0; t < TT; ++t) {
        // prefetch pre_t (independent of h)
        float2 p0 = __ldcg((const float2*)(pre + ((long long)erow * TT + t) * HH + ecol));
        float2 p1 = __ldcg((const float2*)(pre + ((long long)(erow + 8) * TT + t) * HH + ecol));

        float acc[2][4][4];
#pragma unroll
        for (int i = 0; i < 2; i++)
#pragma unroll
            for (int j = 0; j < 4; j++)
#pragma unroll
                for (int k = 0; k < 4; k++) acc[i][j][k] = 0.0f;

        if (t > 0) {
            long long ab;
            if (SEQ) {
                ab = ((long long)(m0 + sr) * TT + (t - 1)) * HH + sc * 8;
            } else {
                ab = (long long)((t - 1) & 1) * BB * HH + (long long)(m0 + sr) * HH + sc * 8;
            }

            auto issueA = [&](int cix) {
                const uint32_t d = sb + RA_ST + (uint32_t)(cix % 3) * RA_STG;
#pragma unroll
                for (int b = 0; b < 2; ++b) {
                    const int ko = cix * 128 + 64 * b;
                    CP16(d + b * 8192 + st0, hf + ab + ko);
                }
                CP_COMMIT();
            };

            issueA(0);
            issueA(1);

            for (int cix = 0; cix < 8; ++cix) {
                if (cix < 7) CP_WAIT(1); else CP_WAIT(0);
                __syncthreads();
                if (cix + 2 < 8) issueA(cix + 2);

                const uint32_t stg = sb + RA_ST + (uint32_t)(cix % 3) * RA_STG;
                const uint32_t ahbuf = stg + (uint32_t)bsel * 8192;
                const uint32_t wblk = (uint32_t)(2 * cix + bsel) * 4096;
                const uint32_t bhbuf = sb + wblk;
                const uint32_t blbuf = sb + RW_LO + wblk;

                uint32_t ah0[4], ah1[4];
                LDMX4(ah0, ahbuf + a0base + ao);
                LDMX4(ah1, ahbuf + a0base + 2048 + ao);
                uint32_t bh0[4], bh1[4], bl0[4], bl1[4];
                LDMX4(bh0, bhbuf + b0base + bo);
                LDMX4(bh1, bhbuf + b0base + 2048 + bo);
                LDMX4(bl0, blbuf + b0base + bo);
                LDMX4(bl1, blbuf + b0base + 2048 + bo);
                // A x Wh
                MMAH16816(acc[0][0], ah0, bh0[0], bh0[1]); MMAH16816(acc[0][1], ah0, bh0[2], bh0[3]);
                MMAH16816(acc[0][2], ah0, bh1[0], bh1[1]); MMAH16816(acc[0][3], ah0, bh1[2], bh1[3]);
                MMAH16816(acc[1][0], ah1, bh0[0], bh0[1]); MMAH16816(acc[1][1], ah1, bh0[2], bh0[3]);
                MMAH16816(acc[1][2], ah1, bh1[0], bh1[1]); MMAH16816(acc[1][3], ah1, bh1[2], bh1[3]);
                // A x Wl
                MMAH16816(acc[0][0], ah0, bl0[0], bl0[1]); MMAH16816(acc[0][1], ah0, bl0[2], bl0[3]);
                MMAH16816(acc[0][2], ah0, bl1[0], bl1[1]); MMAH16816(acc[0][3], ah0, bl1[2], bl1[3]);
                MMAH16816(acc[1][0], ah1, bl0[0], bl0[1]); MMAH16816(acc[1][1], ah1, bl0[2], bl0[3]);
                MMAH16816(acc[1][2], ah1, bl1[0], bl1[1]); MMAH16816(acc[1][3], ah1, bl1[2], bl1[3]);
            }
        }

        // ---- 8-way K reduction through smem (XOR-swizzled, conflict-free) ----
        __syncthreads();
        {
            char* wp = smem + RA_ST + mpos * 32768 + kslot * 4096 + l * 128;
            const uint32_t wsw = ((uint32_t)l & 7) * 16;
#pragma unroll
            for (int mf = 0; mf < 2; ++mf)
#pragma unroll
                for (int nf = 0; nf < 4; ++nf)
                    *(float4*)(wp + (((uint32_t)(mf * 4 + nf) * 16) ^ wsw)) = *(float4*)acc[mf][nf];
        }
        __syncthreads();
        float s[4];
        s[0] = s[1] = s[2] = s[3] = 0.0f;
#pragma unroll
        for (int k = 0; k < 8; ++k) {
            const float4 u = *(const float4*)(smem + RA_ST + rmp * 32768 + k * 4096 +
                                              rl * 128 + rsw);
            s[0] += u.x; s[1] += u.y; s[2] += u.z; s[3] += u.w;
        }

        // ---- epilogue: h = relu(sum + pre_t); store fp16 (+ final fp32) ----
        {
            const long long R0 = erow, R1 = erow + 8;
            float v0 = fmaxf(s[0] + p0.x, 0.0f);
            float v1 = fmaxf(s[1] + p0.y, 0.0f);
            float v2 = fmaxf(s[2] + p1.x, 0.0f);
            float v3 = fmaxf(s[3] + p1.y, 0.0f);
            __half2 ha = __floats2half2_rn(v0, v1);
            __half2 hb = __floats2half2_rn(v2, v3);
            long long ob0, ob1;
            if (SEQ) {
                ob0 = (R0 * TT + t) * HH + ecol;
                ob1 = (R1 * TT + t) * HH + ecol;
            } else {
                ob0 = (long long)(t & 1) * BB * HH + R0 * HH + ecol;
                ob1 = (long long)(t & 1) * BB * HH + R1 * HH + ecol;
            }
            __stcg((uint32_t*)(hf + ob0), *(uint32_t*)&ha);
            __stcg((uint32_t*)(hf + ob1), *(uint32_t*)&hb);
            if (!SEQ && t == TT - 1) {
                __stcg((float2*)(hfin + R0 * HH + ecol), make_float2(v0, v1));
                __stcg((float2*)(hfin + R1 * HH + ecol), make_float2(v2, v3));
            }
        }
        grid_bar_g(grp);
    }
}

// ---------------- small scalar GEMM for fc ----------------
template <int BM, int BN, int TM, int TN>
__global__ void __launch_bounds__((BM / TM) * (BN / TN))
gemm_nt(const float* __restrict__ A, long long a_stride,
        const float* __restrict__ W, const float* __restrict__ bias,
        float* __restrict__ C, long long c_stride, int K) {
    constexpr int BK = 16, TX = BN / TN, TY = BM / TM, NT = TX * TY;
    __shared__ __align__(16) float As[BK][BM];
    __shared__ __align__(16) float Ws[BK][BN];
    const int tid = threadIdx.x, tx = tid % TX, ty = tid / TX;
    const long long m0 = (long long)blockIdx.x * BM;
    const int n0 = blockIdx.y * BN;
    float acc[TM][TN];
#pragma unroll
    for (int i = 0; i < TM; i++)
#pragma unroll
        for (int j = 0; j < TN; j++) acc[i][j] = 0.0f;
    for (int kt = 0; kt < K; kt += BK) {
#pragma unroll
        for (int idx = tid; idx < BM * 4; idx += NT) {
            const int row = idx >> 2, kq = (idx & 3) * 4;
            const float4 v = *(const float4*)(A + (m0 + row) * a_stride + kt + kq);
            As[kq][row] = v.x; As[kq + 1][row] = v.y; As[kq + 2][row] = v.z; As[kq + 3][row] = v.w;
        }
#pragma unroll
        for (int idx = tid; idx < BN * 4; idx += NT) {
            const int row = idx >> 2, kq = (idx & 3) * 4;
            const float4 v = *(const float4*)(W + (long long)(n0 + row) * K + kt + kq);
            Ws[kq][row] = v.x; Ws[kq + 1][row] = v.y; Ws[kq + 2][row] = v.z; Ws[kq + 3][row] = v.w;
        }
        __syncthreads();
#pragma unroll
        for (int kk = 0; kk < BK; kk++) {
            float a[TM], b[TN];
#pragma unroll
            for (int i = 0; i < TM; i += 4) {
                const float4 v = *(const float4*)&As[kk][ty * TM + i];
                a[i] = v.x; a[i + 1] = v.y; a[i + 2] = v.z; a[i + 3] = v.w;
            }
#pragma unroll
            for (int j = 0; j < TN; j += 4) {
                const float4 v = *(const float4*)&Ws[kk][tx * TN + j];
                b[j] = v.x; b[j + 1] = v.y; b[j + 2] = v.z; b[j + 3] = v.w;
            }
#pragma unroll
            for (int i = 0; i < TM; i++)
#pragma unroll
                for (int j = 0; j < TN; j++) acc[i][j] = fmaf(a[i], b[j], acc[i][j]);
        }
        __syncthreads();
    }
#pragma unroll
    for (int i = 0; i < TM; i++) {
        const long long m = m0 + ty * TM + i;
#pragma unroll
        for (int j = 0; j < TN; j++)
            C[m * c_stride + n0 + tx * TN + j] = acc[i][j] + bias[n0 + tx * TN + j];
    }
}

// ---------------- launch ----------------
extern "C" void kernel_launch(void* const* d_in, const int* in_sizes, int n_in,
                              void* d_out, int out_size) {
    const float* x     = (const float*)d_in[0];
    const float* W_ih0 = (const float*)d_in[1];
    const float* W_hh0 = (const float*)d_in[2];
    const float* b_ih0 = (const float*)d_in[3];
    const float* b_hh0 = (const float*)d_in[4];
    const float* W_ih1 = (const float*)d_in[5];
    const float* W_hh1 = (const float*)d_in[6];
    const float* b_ih1 = (const float*)d_in[7];
    const float* b_hh1 = (const float*)d_in[8];
    const float* fc_w  = (const float*)d_in[9];
    const float* fc_b  = (const float*)d_in[10];
    float* out = (float*)d_out;

    float *p_pre, *p_b0, *p_b1, *p_h2f;
    __half *p_xf, *p_h1f, *p_h2f16;
    __half *p_wih0h, *p_wih0l, *p_wih1h, *p_wih1l;
    __half *p_whh0h, *p_whh0l, *p_whh1h, *p_whh1l;
    cudaGetSymbolAddress((void**)&p_pre, g_pre);
    cudaGetSymbolAddress((void**)&p_b0, g_bias0);
    cudaGetSymbolAddress((void**)&p_b1, g_bias1);
    cudaGetSymbolAddress((void**)&p_h2f, g_h2f);
    cudaGetSymbolAddress((void**)&p_xf, g_xf);
    cudaGetSymbolAddress((void**)&p_h1f, g_h1f);
    cudaGetSymbolAddress((void**)&p_h2f16, g_h2f16);
    cudaGetSymbolAddress((void**)&p_wih0h, g_wih0h);
    cudaGetSymbolAddress((void**)&p_wih0l, g_wih0l);
    cudaGetSymbolAddress((void**)&p_wih1h, g_wih1h);
    cudaGetSymbolAddress((void**)&p_wih1l, g_wih1l);
    cudaGetSymbolAddress((void**)&p_whh0h, g_whh0h);
    cudaGetSymbolAddress((void**)&p_whh0l, g_whh0l);
    cudaGetSymbolAddress((void**)&p_whh1h, g_whh1h);
    cudaGetSymbolAddress((void**)&p_whh1l, g_whh1l);

    cudaFuncSetAttribute(gemm_mma, cudaFuncAttributeMaxDynamicSharedMemorySize, PG_SMEM);
    cudaFuncSetAttribute(rnn_mma<true>, cudaFuncAttributeMaxDynamicSharedMemorySize, RN_SMEM);
    cudaFuncSetAttribute(rnn_mma<false>, cudaFuncAttributeMaxDynamicSharedMemorySize, RN_SMEM);

    const long long nx4 = (long long)BB * TT * II / 4;
    const long long nw04 = (long long)HH * II / 4;
    const long long nw4 = (long long)HH * HH / 4;

    // 1: x -> fp16
    to_f16v<<<(unsigned)((nx4 + 255) / 256), 256>>>((const float4*)x, (uint2*)p_xf, nx4);
    // 2: split W_ih0
    split_f16v<<<(unsigned)((nw04 + 255) / 256), 256>>>((const float4*)W_ih0, (uint2*)p_wih0h, (uint2*)p_wih0l, nw04);
    // 3: bias0
    bias_combine<<<(HH + 255) / 256, 256>>>(b_ih0, b_hh0, p_b0, HH);
    // 4: split W_hh0
    split_f16v<<<(unsigned)((nw4 + 255) / 256), 256>>>((const float4*)W_hh0, (uint2*)p_whh0h, (uint2*)p_whh0l, nw4);
    // 5: pre0 = x @ W_ih0^T + bias0
    gemm_mma<<<dim3((BB * TT) / 128, HH / 128), 256, PG_SMEM>>>(
        p_xf, p_wih0h, p_wih0l, p_b0, p_pre, II);
    // 6: layer-0 recurrence
    rnn_mma<true><<<128, 512, RN_SMEM>>>(p_whh0h, p_whh0l, p_pre, p_h1f, nullptr);
    // 7: split W_ih1
    split_f16v<<<(unsigned)((nw4 + 255) / 256), 256>>>((const float4*)W_ih1, (uint2*)p_wih1h, (uint2*)p_wih1l, nw4);
    // 8: bias1
    bias_combine<<<(HH + 255) / 256, 256>>>(b_ih1, b_hh1, p_b1, HH);
    // 9: pre1 = h1 @ W_ih1^T + bias1
    gemm_mma<<<dim3((BB * TT) / 128, HH / 128), 256, PG_SMEM>>>(
        p_h1f, p_wih1h, p_wih1l, p_b1, p_pre, HH);
    // 10: split W_hh1
    split_f16v<<<(unsigned)((nw4 + 255) / 256), 256>>>((const float4*)W_hh1, (uint2*)p_whh1h, (uint2*)p_whh1l, nw4);
    // 11: layer-1 recurrence
    rnn_mma<false><<<128, 512, RN_SMEM>>>(p_whh1h, p_whh1l, p_pre, p_h2f16, p_h2f);
    // 12: fc
    gemm_nt<32, 64, 4, 4><<<dim3(BB / 32, OO / 64), 128>>>(
        p_h2f, HH, fc_w, fc_b, out, OO, HH);
}

// round 10
// speedup vs baseline: 7.3328x; 1.2392x over previous
#include <cuda_runtime.h>
#include <cuda_fp16.h>
#include <cstdint>

// ---------------- problem dims ----------------
#define BB 256
#define TT 512
#define II 512
#define HH 1024
#define OO 256

// ---------------- static device scratch (allocation-free) ----------------
__device__ __align__(16) float g_pre[BB * TT * HH];
__device__ __align__(16) __half g_xf[BB * TT * II];          // x as fp16
__device__ __align__(16) __half g_h1f[BB * TT * HH];         // layer0 hidden seq fp16
__device__ __align__(16) __half g_h2f16[2 * BB * HH];        // layer1 ping-pong fp16
__device__ __align__(16) float g_h2f[BB * HH];               // layer1 final fp32
__device__ __align__(16) __half g_wih0[HH * II];
__device__ __align__(16) __half g_wih1[HH * HH];
__device__ __align__(16) __half g_whh0[HH * HH];
__device__ __align__(16) __half g_whh1[HH * HH];
__device__ __align__(16) float g_bias0[HH];
__device__ __align__(16) float g_bias1[HH];
// per-group barrier state: group g uses slot g*32 (128B apart)
__device__ unsigned g_cnt2[128];
__device__ unsigned g_gen2[128];

// ---------------- PTX helpers (baseline PTX only) ----------------
__device__ __forceinline__ uint32_t smem_u32(const void* p) {
    uint32_t a;
    asm("{ .reg .u64 t; cvta.to.shared.u64 t, %1; cvt.u32.u64 %0, t; }" : "=r"(a) : "l"(p));
    return a;
}
#define CP16(dst, src) \
    asm volatile("cp.async.cg.shared.global [%0], [%1], 16;" :: "r"(dst), "l"(src) : "memory")
#define CP_COMMIT() asm volatile("cp.async.commit_group;" ::: "memory")
#define CP_WAIT(n)  asm volatile("cp.async.wait_group %0;" :: "n"(n) : "memory")

#define LDMX4(r, addr) \
    asm volatile("ldmatrix.sync.aligned.m8n8.x4.shared.b16 {%0,%1,%2,%3}, [%4];" \
                 : "=r"((r)[0]), "=r"((r)[1]), "=r"((r)[2]), "=r"((r)[3]) : "r"(addr))

#define MMAH16816(d, a, b0, b1) \
    asm volatile("mma.sync.aligned.m16n8k16.row.col.f32.f16.f16.f32 " \
                 "{%0,%1,%2,%3},{%4,%5,%6,%7},{%8,%9},{%0,%1,%2,%3};" \
                 : "+f"((d)[0]), "+f"((d)[1]), "+f"((d)[2]), "+f"((d)[3]) \
                 : "r"((a)[0]), "r"((a)[1]), "r"((a)[2]), "r"((a)[3]), "r"(b0), "r"(b1))

// ---------------- group grid barrier (32 CTAs per group) ----------------
__device__ __forceinline__ void grid_bar_g(int g) {
    __threadfence();
    __syncthreads();
    if (threadIdx.x == 0) {
        volatile unsigned* gen = (volatile unsigned*)&g_gen2[g * 32];
        unsigned my = *gen;
        if (atomicAdd(&g_cnt2[g * 32], 1u) == 31u) {
            atomicExch(&g_cnt2[g * 32], 0u);
            __threadfence();
            *gen = my + 1;
        } else {
            while (*gen == my) { }
        }
    }
    __syncthreads();
}

// ---------------- prep kernels ----------------
__global__ void to_f16v(const float4* __restrict__ s, uint2* __restrict__ o, long long n4) {
    long long i = (long long)blockIdx.x * blockDim.x + threadIdx.x;
    if (i < n4) {
        float4 v = s[i];
        __half2 a = __floats2half2_rn(v.x, v.y);
        __half2 b = __floats2half2_rn(v.z, v.w);
        uint2 r;
        r.x = *(uint32_t*)&a; r.y = *(uint32_t*)&b;
        o[i] = r;
    }
}
__global__ void bias_combine(const float* __restrict__ a, const float* __restrict__ b,
                             float* __restrict__ out, int n) {
    int i = blockIdx.x * blockDim.x + threadIdx.x;
    if (i < n) out[i] = a[i] + b[i];
}

// ================= fp16 HMMA pre-activation GEMM (1-pass, 3-stage) =================
// C[M][1024] = A @ W^T + bias.  A fp16, W fp16.
// Tile 128x128, 256 thr (8 warps: 4m x 2n, warp tile 32x64), 64-K chunks.
// Stage (32KB): A @0 (16K), W @16384.
#define PG_STAGE 32768
#define PG_SMEM  (3 * PG_STAGE)

__global__ void __launch_bounds__(256, 1)
gemm_mma(const __half* __restrict__ Af, const __half* __restrict__ Wf,
         const float* __restrict__ bias, float* __restrict__ C, int K) {
    extern __shared__ __align__(128) char smem[];
    const uint32_t sb = smem_u32(smem);
    const int tid = threadIdx.x, l = tid & 31, w = tid >> 5;
    const long long m0 = (long long)blockIdx.x * 128;
    const int n0 = blockIdx.y * 128;
    const int nch = K >> 6;

    const int r0 = tid >> 3, c = tid & 7;
    const uint32_t sd0 = (uint32_t)r0 * 128 + (((uint32_t)c * 16) ^ (((uint32_t)r0 & 7) * 16));

    const int m_off = (w & 3) * 32, n_off = (w >> 2) * 64;
    const int arw = m_off + (l & 7) + ((l & 8) ? 8 : 0);
    const uint32_t abase = (uint32_t)arw * 128;
    const uint32_t ax = ((uint32_t)arw & 7) * 16;
    const uint32_t akb = (l & 16) ? 16 : 0;
    const int brw = n_off + (l & 7) + ((l & 16) ? 8 : 0);
    const uint32_t bbase = (uint32_t)brw * 128;
    const uint32_t bx = ((uint32_t)brw & 7) * 16;
    const uint32_t bkb = (l & 8) ? 16 : 0;

    float acc[2][8][4];
#pragma unroll
    for (int i = 0; i < 2; i++)
#pragma unroll
        for (int j = 0; j < 8; j++)
#pragma unroll
            for (int k = 0; k < 4; k++) acc[i][j][k] = 0.0f;

    auto issue = [&](int kc) {
        const uint32_t d = sb + (uint32_t)(kc % 3) * PG_STAGE;
        const int ko = kc * 64 + c * 8;
#pragma unroll
        for (int j = 0; j < 4; ++j) {
            const long long ar = (m0 + r0 + 32 * j) * (long long)K + ko;
            const long long wr = ((long long)(n0 + r0 + 32 * j)) * K + ko;
            const uint32_t du = d + sd0 + j * 4096;
            CP16(du,          Af + ar);
            CP16(du + 16384,  Wf + wr);
        }
        CP_COMMIT();
    };

    issue(0);
    issue(1);

    for (int kc = 0; kc < nch; ++kc) {
        if (kc < nch - 1) CP_WAIT(1); else CP_WAIT(0);
        __syncthreads();
        if (kc + 2 < nch) issue(kc + 2);

        const uint32_t st = sb + (uint32_t)(kc % 3) * PG_STAGE;
#pragma unroll
        for (int ks = 0; ks < 4; ++ks) {
            uint32_t ah0[4], ah1[4];
            const uint32_t ao = ((uint32_t)(ks * 32) + akb) ^ ax;
            LDMX4(ah0, st + abase + ao);
            LDMX4(ah1, st + abase + 2048 + ao);
            uint32_t bh[4][4];
            const uint32_t bo = ((uint32_t)(ks * 32) + bkb) ^ bx;
#pragma unroll
            for (int nb = 0; nb < 4; ++nb)
                LDMX4(bh[nb], st + 16384 + bbase + nb * 2048 + bo);
#pragma unroll
            for (int nb = 0; nb < 4; ++nb) {
                MMAH16816(acc[0][2 * nb],     ah0, bh[nb][0], bh[nb][1]);
                MMAH16816(acc[0][2 * nb + 1], ah0, bh[nb][2], bh[nb][3]);
                MMAH16816(acc[1][2 * nb],     ah1, bh[nb][0], bh[nb][1]);
                MMAH16816(acc[1][2 * nb + 1], ah1, bh[nb][2], bh[nb][3]);
            }
        }
        __syncthreads();
    }

#pragma unroll
    for (int mf = 0; mf < 2; ++mf) {
        const long long R0 = m0 + m_off + mf * 16 + (l >> 2);
#pragma unroll
        for (int nf = 0; nf < 8; ++nf) {
            const int col = n0 + n_off + nf * 8 + (l & 3) * 2;
            const float2 bv = __ldg((const float2*)(bias + col));
            float2 o0, o1;
            o0.x = acc[mf][nf][0] + bv.x; o0.y = acc[mf][nf][1] + bv.y;
            o1.x = acc[mf][nf][2] + bv.x; o1.y = acc[mf][nf][3] + bv.y;
            __stcg((float2*)(C + R0 * HH + col), o0);
            __stcg((float2*)(C + (R0 + 8) * HH + col), o1);
        }
    }
}

// ================= fp16 HMMA persistent recurrence (1-pass, 512 thr, 8-way K-split) =================
// grid 128 = 4 batch-groups(64 rows) x 32 H-tiles(32 cols). 512 threads.
// 16 warps = 2 m-positions (32 rows) x 8 K-slots (1 k16-slice per 128-K chunk).
// W fp16 resident (64KB). A (h fp16) streamed: 8 chunks of 128-K, 3-stage.
// 8-way K reduction through smem (XOR-swizzled, conflict-free).
#define RA_ST 65536
#define RA_STG 16384             // per stage: 2 x 8KB 64-K sub-blocks
#define RN_SMEM (RA_ST + 65536)  // stages use 48KB of tail; reduce uses 64KB

template <bool SEQ>
__global__ void __launch_bounds__(512, 1)
rnn_mma(const __half* __restrict__ Wf,
        const float* __restrict__ pre,
        __half* __restrict__ hf, float* __restrict__ hfin) {
    extern __shared__ __align__(128) char smem[];
    const uint32_t sb = smem_u32(smem);
    const int tid = threadIdx.x, l = tid & 31, w = tid >> 5;
    const int grp = blockIdx.x & 3;
    const int m0 = grp * 64;
    const int n0 = (blockIdx.x >> 2) * 32;

    // resident W: 16 blocks of [32 rows][128B], swizzled
    for (int u = tid; u < 4096; u += 512) {
        const int kc = u >> 8, rem = u & 255, r = rem >> 3, cc = rem & 7;
        const uint32_t dst = (uint32_t)kc * 4096 + (uint32_t)r * 128 +
                             (((uint32_t)cc * 16) ^ (((uint32_t)r & 7) * 16));
        const long long src = (long long)(n0 + r) * HH + kc * 64 + cc * 8;
        *(uint4*)(smem + dst) = *(const uint4*)(Wf + src);
    }
    __syncthreads();

    // staging: one row per thread per 64-K sub-block: row sr, 16B-col sc
    const int sr = tid >> 3, sc = tid & 7;                // sr: 0..63
    const uint32_t st0 = (uint32_t)sr * 128 + (((uint32_t)sc * 16) ^ (((uint32_t)sr & 7) * 16));

    // compute mapping: warp tile 32m x 32n, 8-way K-split
    const int mpos = w & 1;
    const int kslot = w >> 1;          // 0..7
    const int bsel = kslot >> 2;       // 64-K sub-block within chunk
    const int si = kslot & 3;          // k16 slice within sub-block
    const uint32_t ax = ((uint32_t)l & 7) * 16;
    const uint32_t akb = (l & 16) ? 16u : 0u;
    const uint32_t a0base = (uint32_t)(mpos * 32 + (l & 15)) * 128;
    const uint32_t bkb = (l & 8) ? 16u : 0u;
    const uint32_t b0base = (uint32_t)((l & 7) + ((l & 16) ? 8 : 0)) * 128;
    const uint32_t kob = (uint32_t)(si * 32);
    const uint32_t ao = (kob + akb) ^ ax;
    const uint32_t bo = (kob + bkb) ^ ax;

    // reduce/epilogue mapping: tid = rmp*256 + rl*8 + rfg
    const int rmp = tid >> 8;
    const int rl = (tid >> 3) & 31;
    const int rfg = tid & 7;
    const int erow = m0 + rmp * 32 + (rfg >> 2) * 16 + (rl >> 2);
    const int ecol = n0 + (rfg & 3) * 8 + (rl & 3) * 2;
    const uint32_t rsw = ((uint32_t)rfg * 16) ^ (((uint32_t)rl & 7) * 16);

    for (int t = 0; t < TT; ++t) {
        // prefetch pre_t (independent of h)
        float2 p0 = __ldcg((const float2*)(pre + ((long long)erow * TT + t) * HH + ecol));
        float2 p1 = __ldcg((const float2*)(pre + ((long long)(erow + 8) * TT + t) * HH + ecol));

        float acc[2][4][4];
#pragma unroll
        for (int i = 0; i < 2; i++)
#pragma unroll
            for (int j = 0; j < 4; j++)
#pragma unroll
                for (int k = 0; k < 4; k++) acc[i][j][k] = 0.0f;

        if (t > 0) {
            long long ab;
            if (SEQ) {
                ab = ((long long)(m0 + sr) * TT + (t - 1)) * HH + sc * 8;
            } else {
                ab = (long long)((t - 1) & 1) * BB * HH + (long long)(m0 + sr) * HH + sc * 8;
            }

            auto issueA = [&](int cix) {
                const uint32_t d = sb + RA_ST + (uint32_t)(cix % 3) * RA_STG;
#pragma unroll
                for (int b = 0; b < 2; ++b) {
                    const int ko = cix * 128 + 64 * b;
                    CP16(d + b * 8192 + st0, hf + ab + ko);
                }
                CP_COMMIT();
            };

            issueA(0);
            issueA(1);

            for (int cix = 0; cix < 8; ++cix) {
                if (cix < 7) CP_WAIT(1); else CP_WAIT(0);
                __syncthreads();
                if (cix + 2 < 8) issueA(cix + 2);

                const uint32_t stg = sb + RA_ST + (uint32_t)(cix % 3) * RA_STG;
                const uint32_t ahbuf = stg + (uint32_t)bsel * 8192;
                const uint32_t bhbuf = sb + (uint32_t)(2 * cix + bsel) * 4096;

                uint32_t ah0[4], ah1[4];
                LDMX4(ah0, ahbuf + a0base + ao);
                LDMX4(ah1, ahbuf + a0base + 2048 + ao);
                uint32_t bh0[4], bh1[4];
                LDMX4(bh0, bhbuf + b0base + bo);
                LDMX4(bh1, bhbuf + b0base + 2048 + bo);
                MMAH16816(acc[0][0], ah0, bh0[0], bh0[1]); MMAH16816(acc[0][1], ah0, bh0[2], bh0[3]);
                MMAH16816(acc[0][2], ah0, bh1[0], bh1[1]); MMAH16816(acc[0][3], ah0, bh1[2], bh1[3]);
                MMAH16816(acc[1][0], ah1, bh0[0], bh0[1]); MMAH16816(acc[1][1], ah1, bh0[2], bh0[3]);
                MMAH16816(acc[1][2], ah1, bh1[0], bh1[1]); MMAH16816(acc[1][3], ah1, bh1[2], bh1[3]);
            }
        }

        // ---- 8-way K reduction through smem (XOR-swizzled, conflict-free) ----
        __syncthreads();
        {
            char* wp = smem + RA_ST + mpos * 32768 + kslot * 4096 + l * 128;
            const uint32_t wsw = ((uint32_t)l & 7) * 16;
#pragma unroll
            for (int mf = 0; mf < 2; ++mf)
#pragma unroll
                for (int nf = 0; nf < 4; ++nf)
                    *(float4*)(wp + (((uint32_t)(mf * 4 + nf) * 16) ^ wsw)) = *(float4*)acc[mf][nf];
        }
        __syncthreads();
        float s[4];
        s[0] = s[1] = s[2] = s[3] = 0.0f;
#pragma unroll
        for (int k = 0; k < 8; ++k) {
            const float4 u = *(const float4*)(smem + RA_ST + rmp * 32768 + k * 4096 +
                                              rl * 128 + rsw);
            s[0] += u.x; s[1] += u.y; s[2] += u.z; s[3] += u.w;
        }

        // ---- epilogue: h = relu(sum + pre_t); store fp16 (+ final fp32) ----
        {
            const long long R0 = erow, R1 = erow + 8;
            float v0 = fmaxf(s[0] + p0.x, 0.0f);
            float v1 = fmaxf(s[1] + p0.y, 0.0f);
            float v2 = fmaxf(s[2] + p1.x, 0.0f);
            float v3 = fmaxf(s[3] + p1.y, 0.0f);
            __half2 ha = __floats2half2_rn(v0, v1);
            __half2 hb = __floats2half2_rn(v2, v3);
            long long ob0, ob1;
            if (SEQ) {
                ob0 = (R0 * TT + t) * HH + ecol;
                ob1 = (R1 * TT + t) * HH + ecol;
            } else {
                ob0 = (long long)(t & 1) * BB * HH + R0 * HH + ecol;
                ob1 = (long long)(t & 1) * BB * HH + R1 * HH + ecol;
            }
            __stcg((uint32_t*)(hf + ob0), *(uint32_t*)&ha);
            __stcg((uint32_t*)(hf + ob1), *(uint32_t*)&hb);
            if (!SEQ && t == TT - 1) {
                __stcg((float2*)(hfin + R0 * HH + ecol), make_float2(v0, v1));
                __stcg((float2*)(hfin + R1 * HH + ecol), make_float2(v2, v3));
            }
        }
        grid_bar_g(grp);
    }
}

// ---------------- small scalar GEMM for fc ----------------
template <int BM, int BN, int TM, int TN>
__global__ void __launch_bounds__((BM / TM) * (BN / TN))
gemm_nt(const float* __restrict__ A, long long a_stride,
        const float* __restrict__ W, const float* __restrict__ bias,
        float* __restrict__ C, long long c_stride, int K) {
    constexpr int BK = 16, TX = BN / TN, TY = BM / TM, NT = TX * TY;
    __shared__ __align__(16) float As[BK][BM];
    __shared__ __align__(16) float Ws[BK][BN];
    const int tid = threadIdx.x, tx = tid % TX, ty = tid / TX;
    const long long m0 = (long long)blockIdx.x * BM;
    const int n0 = blockIdx.y * BN;
    float acc[TM][TN];
#pragma unroll
    for (int i = 0; i < TM; i++)
#pragma unroll
        for (int j = 0; j < TN; j++) acc[i][j] = 0.0f;
    for (int kt = 0; kt < K; kt += BK) {
#pragma unroll
        for (int idx = tid; idx < BM * 4; idx += NT) {
            const int row = idx >> 2, kq = (idx & 3) * 4;
            const float4 v = *(const float4*)(A + (m0 + row) * a_stride + kt + kq);
            As[kq][row] = v.x; As[kq + 1][row] = v.y; As[kq + 2][row] = v.z; As[kq + 3][row] = v.w;
        }
#pragma unroll
        for (int idx = tid; idx < BN * 4; idx += NT) {
            const int row = idx >> 2, kq = (idx & 3) * 4;
            const float4 v = *(const float4*)(W + (long long)(n0 + row) * K + kt + kq);
            Ws[kq][row] = v.x; Ws[kq + 1][row] = v.y; Ws[kq + 2][row] = v.z; Ws[kq + 3][row] = v.w;
        }
        __syncthreads();
#pragma unroll
        for (int kk = 0; kk < BK; kk++) {
            float a[TM], b[TN];
#pragma unroll
            for (int i = 0; i < TM; i += 4) {
                const float4 v = *(const float4*)&As[kk][ty * TM + i];
                a[i] = v.x; a[i + 1] = v.y; a[i + 2] = v.z; a[i + 3] = v.w;
            }
#pragma unroll
            for (int j = 0; j < TN; j += 4) {
                const float4 v = *(const float4*)&Ws[kk][tx * TN + j];
                b[j] = v.x; b[j + 1] = v.y; b[j + 2] = v.z; b[j + 3] = v.w;
            }
#pragma unroll
            for (int i = 0; i < TM; i++)
#pragma unroll
                for (int j = 0; j < TN; j++) acc[i][j] = fmaf(a[i], b[j], acc[i][j]);
        }
        __syncthreads();
    }
#pragma unroll
    for (int i = 0; i < TM; i++) {
        const long long m = m0 + ty * TM + i;
#pragma unroll
        for (int j = 0; j < TN; j++)
            C[m * c_stride + n0 + tx * TN + j] = acc[i][j] + bias[n0 + tx * TN + j];
    }
}

// ---------------- launch ----------------
extern "C" void kernel_launch(void* const* d_in, const int* in_sizes, int n_in,
                              void* d_out, int out_size) {
    const float* x     = (const float*)d_in[0];
    const float* W_ih0 = (const float*)d_in[1];
    const float* W_hh0 = (const float*)d_in[2];
    const float* b_ih0 = (const float*)d_in[3];
    const float* b_hh0 = (const float*)d_in[4];
    const float* W_ih1 = (const float*)d_in[5];
    const float* W_hh1 = (const float*)d_in[6];
    const float* b_ih1 = (const float*)d_in[7];
    const float* b_hh1 = (const float*)d_in[8];
    const float* fc_w  = (const float*)d_in[9];
    const float* fc_b  = (const float*)d_in[10];
    float* out = (float*)d_out;

    float *p_pre, *p_b0, *p_b1, *p_h2f;
    __half *p_xf, *p_h1f, *p_h2f16;
    __half *p_wih0, *p_wih1, *p_whh0, *p_whh1;
    cudaGetSymbolAddress((void**)&p_pre, g_pre);
    cudaGetSymbolAddress((void**)&p_b0, g_bias0);
    cudaGetSymbolAddress((void**)&p_b1, g_bias1);
    cudaGetSymbolAddress((void**)&p_h2f, g_h2f);
    cudaGetSymbolAddress((void**)&p_xf, g_xf);
    cudaGetSymbolAddress((void**)&p_h1f, g_h1f);
    cudaGetSymbolAddress((void**)&p_h2f16, g_h2f16);
    cudaGetSymbolAddress((void**)&p_wih0, g_wih0);
    cudaGetSymbolAddress((void**)&p_wih1, g_wih1);
    cudaGetSymbolAddress((void**)&p_whh0, g_whh0);
    cudaGetSymbolAddress((void**)&p_whh1, g_whh1);

    cudaFuncSetAttribute(gemm_mma, cudaFuncAttributeMaxDynamicSharedMemorySize, PG_SMEM);
    cudaFuncSetAttribute(rnn_mma<true>, cudaFuncAttributeMaxDynamicSharedMemorySize, RN_SMEM);
    cudaFuncSetAttribute(rnn_mma<false>, cudaFuncAttributeMaxDynamicSharedMemorySize, RN_SMEM);

    const long long nx4 = (long long)BB * TT * II / 4;
    const long long nw04 = (long long)HH * II / 4;
    const long long nw4 = (long long)HH * HH / 4;

    // 1: x -> fp16
    to_f16v<<<(unsigned)((nx4 + 255) / 256), 256>>>((const float4*)x, (uint2*)p_xf, nx4);
    // 2: W_ih0 -> fp16
    to_f16v<<<(unsigned)((nw04 + 255) / 256), 256>>>((const float4*)W_ih0, (uint2*)p_wih0, nw04);
    // 3: bias0
    bias_combine<<<(HH + 255) / 256, 256>>>(b_ih0, b_hh0, p_b0, HH);
    // 4: W_hh0 -> fp16
    to_f16v<<<(unsigned)((nw4 + 255) / 256), 256>>>((const float4*)W_hh0, (uint2*)p_whh0, nw4);
    // 5: pre0 = x @ W_ih0^T + bias0
    gemm_mma<<<dim3((BB * TT) / 128, HH / 128), 256, PG_SMEM>>>(
        p_xf, p_wih0, p_b0, p_pre, II);
    // 6: layer-0 recurrence
    rnn_mma<true><<<128, 512, RN_SMEM>>>(p_whh0, p_pre, p_h1f, nullptr);
    // 7: W_ih1 -> fp16
    to_f16v<<<(unsigned)((nw4 + 255) / 256), 256>>>((const float4*)W_ih1, (uint2*)p_wih1, nw4);
    // 8: bias1
    bias_combine<<<(HH + 255) / 256, 256>>>(b_ih1, b_hh1, p_b1, HH);
    // 9: pre1 = h1 @ W_ih1^T + bias1
    gemm_mma<<<dim3((BB * TT) / 128, HH / 128), 256, PG_SMEM>>>(
        p_h1f, p_wih1, p_b1, p_pre, HH);
    // 10: W_hh1 -> fp16
    to_f16v<<<(unsigned)((nw4 + 255) / 256), 256>>>((const float4*)W_hh1, (uint2*)p_whh1, nw4);
    // 11: layer-1 recurrence
    rnn_mma<false><<<128, 512, RN_SMEM>>>(p_whh1, p_pre, p_h2f16, p_h2f);
    // 12: fc
    gemm_nt<32, 64, 4, 4><<<dim3(BB / 32, OO / 64), 128>>>(
        p_h2f, HH, fc_w, fc_b, out, OO, HH);
}

// round 11
// speedup vs baseline: 7.4332x; 1.0137x over previous
#include <cuda_runtime.h>
#include <cuda_fp16.h>
#include <cstdint>

// ---------------- problem dims ----------------
#define BB 256
#define TT 512
#define II 512
#define HH 1024
#define OO 256

// ---------------- static device scratch (allocation-free) ----------------
__device__ __align__(16) float g_pre[BB * TT * HH];
__device__ __align__(16) __half g_xf[BB * TT * II];          // x as fp16
__device__ __align__(16) __half g_h1f[BB * TT * HH];         // layer0 hidden seq fp16
__device__ __align__(16) __half g_h2f16[2 * BB * HH];        // layer1 ping-pong fp16
__device__ __align__(16) float g_h2f[BB * HH];               // layer1 final fp32
__device__ __align__(16) __half g_wih0[HH * II];
__device__ __align__(16) __half g_wih1[HH * HH];
__device__ __align__(16) __half g_whh0[HH * HH];
__device__ __align__(16) __half g_whh1[HH * HH];
__device__ __align__(16) float g_bias0[HH];
__device__ __align__(16) float g_bias1[HH];
// per-group barrier state: group g uses slot g*32 (128B apart); up to 8 groups
__device__ unsigned g_cnt2[256];
__device__ unsigned g_gen2[256];

// ---------------- PTX helpers (baseline PTX only) ----------------
__device__ __forceinline__ uint32_t smem_u32(const void* p) {
    uint32_t a;
    asm("{ .reg .u64 t; cvta.to.shared.u64 t, %1; cvt.u32.u64 %0, t; }" : "=r"(a) : "l"(p));
    return a;
}
#define CP16(dst, src) \
    asm volatile("cp.async.cg.shared.global [%0], [%1], 16;" :: "r"(dst), "l"(src) : "memory")
#define CP_COMMIT() asm volatile("cp.async.commit_group;" ::: "memory")
#define CP_WAIT(n)  asm volatile("cp.async.wait_group %0;" :: "n"(n) : "memory")

#define LDMX4(r, addr) \
    asm volatile("ldmatrix.sync.aligned.m8n8.x4.shared.b16 {%0,%1,%2,%3}, [%4];" \
                 : "=r"((r)[0]), "=r"((r)[1]), "=r"((r)[2]), "=r"((r)[3]) : "r"(addr))

#define MMAH16816(d, a, b0, b1) \
    asm volatile("mma.sync.aligned.m16n8k16.row.col.f32.f16.f16.f32 " \
                 "{%0,%1,%2,%3},{%4,%5,%6,%7},{%8,%9},{%0,%1,%2,%3};" \
                 : "+f"((d)[0]), "+f"((d)[1]), "+f"((d)[2]), "+f"((d)[3]) \
                 : "r"((a)[0]), "r"((a)[1]), "r"((a)[2]), "r"((a)[3]), "r"(b0), "r"(b1))

// ---------------- group grid barrier (16 CTAs per group) ----------------
__device__ __forceinline__ void grid_bar_g(int g) {
    __threadfence();
    __syncthreads();
    if (threadIdx.x == 0) {
        volatile unsigned* gen = (volatile unsigned*)&g_gen2[g * 32];
        unsigned my = *gen;
        if (atomicAdd(&g_cnt2[g * 32], 1u) == 15u) {
            atomicExch(&g_cnt2[g * 32], 0u);
            __threadfence();
            *gen = my + 1;
        } else {
            while (*gen == my) { }
        }
    }
    __syncthreads();
}

// ---------------- prep kernels ----------------
__global__ void to_f16v(const float4* __restrict__ s, uint2* __restrict__ o, long long n4) {
    long long i = (long long)blockIdx.x * blockDim.x + threadIdx.x;
    if (i < n4) {
        float4 v = s[i];
        __half2 a = __floats2half2_rn(v.x, v.y);
        __half2 b = __floats2half2_rn(v.z, v.w);
        uint2 r;
        r.x = *(uint32_t*)&a; r.y = *(uint32_t*)&b;
        o[i] = r;
    }
}
__global__ void bias_combine(const float* __restrict__ a, const float* __restrict__ b,
                             float* __restrict__ out, int n) {
    int i = blockIdx.x * blockDim.x + threadIdx.x;
    if (i < n) out[i] = a[i] + b[i];
}

// ================= fp16 HMMA pre-activation GEMM (1-pass, 3-stage) =================
#define PG_STAGE 32768
#define PG_SMEM  (3 * PG_STAGE)

__global__ void __launch_bounds__(256, 1)
gemm_mma(const __half* __restrict__ Af, const __half* __restrict__ Wf,
         const float* __restrict__ bias, float* __restrict__ C, int K) {
    extern __shared__ __align__(128) char smem[];
    const uint32_t sb = smem_u32(smem);
    const int tid = threadIdx.x, l = tid & 31, w = tid >> 5;
    const long long m0 = (long long)blockIdx.x * 128;
    const int n0 = blockIdx.y * 128;
    const int nch = K >> 6;

    const int r0 = tid >> 3, c = tid & 7;
    const uint32_t sd0 = (uint32_t)r0 * 128 + (((uint32_t)c * 16) ^ (((uint32_t)r0 & 7) * 16));

    const int m_off = (w & 3) * 32, n_off = (w >> 2) * 64;
    const int arw = m_off + (l & 7) + ((l & 8) ? 8 : 0);
    const uint32_t abase = (uint32_t)arw * 128;
    const uint32_t ax = ((uint32_t)arw & 7) * 16;
    const uint32_t akb = (l & 16) ? 16 : 0;
    const int brw = n_off + (l & 7) + ((l & 16) ? 8 : 0);
    const uint32_t bbase = (uint32_t)brw * 128;
    const uint32_t bx = ((uint32_t)brw & 7) * 16;
    const uint32_t bkb = (l & 8) ? 16 : 0;

    float acc[2][8][4];
#pragma unroll
    for (int i = 0; i < 2; i++)
#pragma unroll
        for (int j = 0; j < 8; j++)
#pragma unroll
            for (int k = 0; k < 4; k++) acc[i][j][k] = 0.0f;

    auto issue = [&](int kc) {
        const uint32_t d = sb + (uint32_t)(kc % 3) * PG_STAGE;
        const int ko = kc * 64 + c * 8;
#pragma unroll
        for (int j = 0; j < 4; ++j) {
            const long long ar = (m0 + r0 + 32 * j) * (long long)K + ko;
            const long long wr = ((long long)(n0 + r0 + 32 * j)) * K + ko;
            const uint32_t du = d + sd0 + j * 4096;
            CP16(du,          Af + ar);
            CP16(du + 16384,  Wf + wr);
        }
        CP_COMMIT();
    };

    issue(0);
    issue(1);

    for (int kc = 0; kc < nch; ++kc) {
        if (kc < nch - 1) CP_WAIT(1); else CP_WAIT(0);
        __syncthreads();
        if (kc + 2 < nch) issue(kc + 2);

        const uint32_t st = sb + (uint32_t)(kc % 3) * PG_STAGE;
#pragma unroll
        for (int ks = 0; ks < 4; ++ks) {
            uint32_t ah0[4], ah1[4];
            const uint32_t ao = ((uint32_t)(ks * 32) + akb) ^ ax;
            LDMX4(ah0, st + abase + ao);
            LDMX4(ah1, st + abase + 2048 + ao);
            uint32_t bh[4][4];
            const uint32_t bo = ((uint32_t)(ks * 32) + bkb) ^ bx;
#pragma unroll
            for (int nb = 0; nb < 4; ++nb)
                LDMX4(bh[nb], st + 16384 + bbase + nb * 2048 + bo);
#pragma unroll
            for (int nb = 0; nb < 4; ++nb) {
                MMAH16816(acc[0][2 * nb],     ah0, bh[nb][0], bh[nb][1]);
                MMAH16816(acc[0][2 * nb + 1], ah0, bh[nb][2], bh[nb][3]);
                MMAH16816(acc[1][2 * nb],     ah1, bh[nb][0], bh[nb][1]);
                MMAH16816(acc[1][2 * nb + 1], ah1, bh[nb][2], bh[nb][3]);
            }
        }
        __syncthreads();
    }

#pragma unroll
    for (int mf = 0; mf < 2; ++mf) {
        const long long R0 = m0 + m_off + mf * 16 + (l >> 2);
#pragma unroll
        for (int nf = 0; nf < 8; ++nf) {
            const int col = n0 + n_off + nf * 8 + (l & 3) * 2;
            const float2 bv = __ldg((const float2*)(bias + col));
            float2 o0, o1;
            o0.x = acc[mf][nf][0] + bv.x; o0.y = acc[mf][nf][1] + bv.y;
            o1.x = acc[mf][nf][2] + bv.x; o1.y = acc[mf][nf][3] + bv.y;
            __stcg((float2*)(C + R0 * HH + col), o0);
            __stcg((float2*)(C + (R0 + 8) * HH + col), o1);
        }
    }
}

// ================= fp16 HMMA persistent recurrence (32m x 64n tiles) =================
// grid 128 = 8 batch-groups(32 rows) x 16 H-tiles(64 cols). 512 threads.
// 16 warps = 2 n-positions (32 cols) x 8 K-slots (1 k16-slice per 128-K chunk).
// W fp16 resident (128KB: 16 blocks of [64 rows][128B]). A (h fp16, 64KB/step)
// streamed: 8 chunks of 128-K, 3-stage cp.async (1 op/thread/chunk).
// 8-way K reduction through smem (XOR-swizzled); reduce area overlaps stages.
#define RA_ST 131072             // stages AND reduce area both live here
#define RA_STG 8192              // per stage: 2 x 4KB 64-K sub-blocks
#define RN_SMEM (RA_ST + 65536)  // 192KB total

template <bool SEQ>
__global__ void __launch_bounds__(512, 1)
rnn_mma(const __half* __restrict__ Wf,
        const float* __restrict__ pre,
        __half* __restrict__ hf, float* __restrict__ hfin) {
    extern __shared__ __align__(128) char smem[];
    const uint32_t sb = smem_u32(smem);
    const int tid = threadIdx.x, l = tid & 31, w = tid >> 5;
    const int grp = blockIdx.x & 7;
    const int m0 = grp * 32;
    const int n0 = (blockIdx.x >> 3) * 64;

    // resident W: 16 blocks of [64 rows][128B], swizzled (8KB each)
    for (int u = tid; u < 8192; u += 512) {
        const int kc = u >> 9, rem = u & 511, r = rem >> 3, cc = rem & 7;
        const uint32_t dst = (uint32_t)kc * 8192 + (uint32_t)r * 128 +
                             (((uint32_t)cc * 16) ^ (((uint32_t)r & 7) * 16));
        const long long src = (long long)(n0 + r) * HH + kc * 64 + cc * 8;
        *(uint4*)(smem + dst) = *(const uint4*)(Wf + src);
    }
    __syncthreads();

    // staging: 512 units per 128-K chunk (2 sub-blocks x 32 rows x 8 cols-of-16B)
    const int sbk = tid >> 8;                 // sub-block 0/1
    const int srr = (tid & 255) >> 3;         // row 0..31
    const int scc = tid & 7;                  // 16B col 0..7
    const uint32_t st0 = (uint32_t)sbk * 4096 + (uint32_t)srr * 128 +
                         (((uint32_t)scc * 16) ^ (((uint32_t)srr & 7) * 16));

    // compute mapping: warp tile 32m x 32n, 8-way K-split, 2 n-positions
    const int npos = w & 1;
    const int kslot = w >> 1;          // 0..7
    const int bsel = kslot >> 2;       // 64-K sub-block within chunk
    const int si = kslot & 3;          // k16 slice within sub-block
    const uint32_t ax = ((uint32_t)l & 7) * 16;
    const uint32_t akb = (l & 16) ? 16u : 0u;
    const uint32_t a0base = (uint32_t)(l & 15) * 128;
    const uint32_t bkb = (l & 8) ? 16u : 0u;
    const uint32_t b0base = (uint32_t)(npos * 32 + (l & 7) + ((l & 16) ? 8 : 0)) * 128;
    const uint32_t kob = (uint32_t)(si * 32);
    const uint32_t ao = (kob + akb) ^ ax;
    const uint32_t bo = (kob + bkb) ^ ax;

    // reduce/epilogue mapping: tid = rnp*256 + rl*8 + rfg
    const int rnp = tid >> 8;
    const int rl = (tid >> 3) & 31;
    const int rfg = tid & 7;           // = mf*4 + nf
    const int erow = m0 + (rfg >> 2) * 16 + (rl >> 2);
    const int ecol = n0 + rnp * 32 + (rfg & 3) * 8 + (rl & 3) * 2;
    const uint32_t rsw = ((uint32_t)rfg * 16) ^ (((uint32_t)rl & 7) * 16);

    for (int t = 0; t < TT; ++t) {
        // prefetch pre_t (independent of h)
        float2 p0 = __ldcg((const float2*)(pre + ((long long)erow * TT + t) * HH + ecol));
        float2 p1 = __ldcg((const float2*)(pre + ((long long)(erow + 8) * TT + t) * HH + ecol));

        float acc[2][4][4];
#pragma unroll
        for (int i = 0; i < 2; i++)
#pragma unroll
            for (int j = 0; j < 4; j++)
#pragma unroll
                for (int k = 0; k < 4; k++) acc[i][j][k] = 0.0f;

        if (t > 0) {
            long long ab;   // element addr of this thread's staging unit at chunk 0
            if (SEQ) {
                ab = ((long long)(m0 + srr) * TT + (t - 1)) * HH + sbk * 64 + scc * 8;
            } else {
                ab = (long long)((t - 1) & 1) * BB * HH + (long long)(m0 + srr) * HH +
                     sbk * 64 + scc * 8;
            }

            auto issueA = [&](int cix) {
                const uint32_t d = sb + RA_ST + (uint32_t)(cix % 3) * RA_STG;
                CP16(d + st0, hf + ab + cix * 128);
                CP_COMMIT();
            };

            issueA(0);
            issueA(1);

            for (int cix = 0; cix < 8; ++cix) {
                if (cix < 7) CP_WAIT(1); else CP_WAIT(0);
                __syncthreads();
                if (cix + 2 < 8) issueA(cix + 2);

                const uint32_t stg = sb + RA_ST + (uint32_t)(cix % 3) * RA_STG;
                const uint32_t ahbuf = stg + (uint32_t)bsel * 4096;
                const uint32_t bhbuf = sb + (uint32_t)(2 * cix + bsel) * 8192;

                uint32_t ah0[4], ah1[4];
                LDMX4(ah0, ahbuf + a0base + ao);
                LDMX4(ah1, ahbuf + a0base + 2048 + ao);
                uint32_t bh0[4], bh1[4];
                LDMX4(bh0, bhbuf + b0base + bo);
                LDMX4(bh1, bhbuf + b0base + 2048 + bo);
                MMAH16816(acc[0][0], ah0, bh0[0], bh0[1]); MMAH16816(acc[0][1], ah0, bh0[2], bh0[3]);
                MMAH16816(acc[0][2], ah0, bh1[0], bh1[1]); MMAH16816(acc[0][3], ah0, bh1[2], bh1[3]);
                MMAH16816(acc[1][0], ah1, bh0[0], bh0[1]); MMAH16816(acc[1][1], ah1, bh0[2], bh0[3]);
                MMAH16816(acc[1][2], ah1, bh1[0], bh1[1]); MMAH16816(acc[1][3], ah1, bh1[2], bh1[3]);
            }
        }

        // ---- 8-way K reduction through smem (XOR-swizzled, conflict-free) ----
        __syncthreads();
        {
            char* wp = smem + RA_ST + npos * 32768 + kslot * 4096 + l * 128;
            const uint32_t wsw = ((uint32_t)l & 7) * 16;
#pragma unroll
            for (int mf = 0; mf < 2; ++mf)
#pragma unroll
                for (int nf = 0; nf < 4; ++nf)
                    *(float4*)(wp + (((uint32_t)(mf * 4 + nf) * 16) ^ wsw)) = *(float4*)acc[mf][nf];
        }
        __syncthreads();
        float s[4];
        s[0] = s[1] = s[2] = s[3] = 0.0f;
#pragma unroll
        for (int k = 0; k < 8; ++k) {
            const float4 u = *(const float4*)(smem + RA_ST + rnp * 32768 + k * 4096 +
                                              rl * 128 + rsw);
            s[0] += u.x; s[1] += u.y; s[2] += u.z; s[3] += u.w;
        }

        // ---- epilogue: h = relu(sum + pre_t); store fp16 (+ final fp32) ----
        {
            const long long R0 = erow, R1 = erow + 8;
            float v0 = fmaxf(s[0] + p0.x, 0.0f);
            float v1 = fmaxf(s[1] + p0.y, 0.0f);
            float v2 = fmaxf(s[2] + p1.x, 0.0f);
            float v3 = fmaxf(s[3] + p1.y, 0.0f);
            __half2 ha = __floats2half2_rn(v0, v1);
            __half2 hb = __floats2half2_rn(v2, v3);
            long long ob0, ob1;
            if (SEQ) {
                ob0 = (R0 * TT + t) * HH + ecol;
                ob1 = (R1 * TT + t) * HH + ecol;
            } else {
                ob0 = (long long)(t & 1) * BB * HH + R0 * HH + ecol;
                ob1 = (long long)(t & 1) * BB * HH + R1 * HH + ecol;
            }
            __stcg((uint32_t*)(hf + ob0), *(uint32_t*)&ha);
            __stcg((uint32_t*)(hf + ob1), *(uint32_t*)&hb);
            if (!SEQ && t == TT - 1) {
                __stcg((float2*)(hfin + R0 * HH + ecol), make_float2(v0, v1));
                __stcg((float2*)(hfin + R1 * HH + ecol), make_float2(v2, v3));
            }
        }
        grid_bar_g(grp);
    }
}

// ---------------- small scalar GEMM for fc ----------------
template <int BM, int BN, int TM, int TN>
__global__ void __launch_bounds__((BM / TM) * (BN / TN))
gemm_nt(const float* __restrict__ A, long long a_stride,
        const float* __restrict__ W, const float* __restrict__ bias,
        float* __restrict__ C, long long c_stride, int K) {
    constexpr int BK = 16, TX = BN / TN, TY = BM / TM, NT = TX * TY;
    __shared__ __align__(16) float As[BK][BM];
    __shared__ __align__(16) float Ws[BK][BN];
    const int tid = threadIdx.x, tx = tid % TX, ty = tid / TX;
    const long long m0 = (long long)blockIdx.x * BM;
    const int n0 = blockIdx.y * BN;
    float acc[TM][TN];
#pragma unroll
    for (int i = 0; i < TM; i++)
#pragma unroll
        for (int j = 0; j < TN; j++) acc[i][j] = 0.0f;
    for (int kt = 0; kt < K; kt += BK) {
#pragma unroll
        for (int idx = tid; idx < BM * 4; idx += NT) {
            const int row = idx >> 2, kq = (idx & 3) * 4;
            const float4 v = *(const float4*)(A + (m0 + row) * a_stride + kt + kq);
            As[kq][row] = v.x; As[kq + 1][row] = v.y; As[kq + 2][row] = v.z; As[kq + 3][row] = v.w;
        }
#pragma unroll
        for (int idx = tid; idx < BN * 4; idx += NT) {
            const int row = idx >> 2, kq = (idx & 3) * 4;
            const float4 v = *(const float4*)(W + (long long)(n0 + row) * K + kt + kq);
            Ws[kq][row] = v.x; Ws[kq + 1][row] = v.y; Ws[kq + 2][row] = v.z; Ws[kq + 3][row] = v.w;
        }
        __syncthreads();
#pragma unroll
        for (int kk = 0; kk < BK; kk++) {
            float a[TM], b[TN];
#pragma unroll
            for (int i = 0; i < TM; i += 4) {
                const float4 v = *(const float4*)&As[kk][ty * TM + i];
                a[i] = v.x; a[i + 1] = v.y; a[i + 2] = v.z; a[i + 3] = v.w;
            }
#pragma unroll
            for (int j = 0; j < TN; j += 4) {
                const float4 v = *(const float4*)&Ws[kk][tx * TN + j];
                b[j] = v.x; b[j + 1] = v.y; b[j + 2] = v.z; b[j + 3] = v.w;
            }
#pragma unroll
            for (int i = 0; i < TM; i++)
#pragma unroll
                for (int j = 0; j < TN; j++) acc[i][j] = fmaf(a[i], b[j], acc[i][j]);
        }
        __syncthreads();
    }
#pragma unroll
    for (int i = 0; i < TM; i++) {
        const long long m = m0 + ty * TM + i;
#pragma unroll
        for (int j = 0; j < TN; j++)
            C[m * c_stride + n0 + tx * TN + j] = acc[i][j] + bias[n0 + tx * TN + j];
    }
}

// ---------------- launch ----------------
extern "C" void kernel_launch(void* const* d_in, const int* in_sizes, int n_in,
                              void* d_out, int out_size) {
    const float* x     = (const float*)d_in[0];
    const float* W_ih0 = (const float*)d_in[1];
    const float* W_hh0 = (const float*)d_in[2];
    const float* b_ih0 = (const float*)d_in[3];
    const float* b_hh0 = (const float*)d_in[4];
    const float* W_ih1 = (const float*)d_in[5];
    const float* W_hh1 = (const float*)d_in[6];
    const float* b_ih1 = (const float*)d_in[7];
    const float* b_hh1 = (const float*)d_in[8];
    const float* fc_w  = (const float*)d_in[9];
    const float* fc_b  = (const float*)d_in[10];
    float* out = (float*)d_out;

    float *p_pre, *p_b0, *p_b1, *p_h2f;
    __half *p_xf, *p_h1f, *p_h2f16;
    __half *p_wih0, *p_wih1, *p_whh0, *p_whh1;
    cudaGetSymbolAddress((void**)&p_pre, g_pre);
    cudaGetSymbolAddress((void**)&p_b0, g_bias0);
    cudaGetSymbolAddress((void**)&p_b1, g_bias1);
    cudaGetSymbolAddress((void**)&p_h2f, g_h2f);
    cudaGetSymbolAddress((void**)&p_xf, g_xf);
    cudaGetSymbolAddress((void**)&p_h1f, g_h1f);
    cudaGetSymbolAddress((void**)&p_h2f16, g_h2f16);
    cudaGetSymbolAddress((void**)&p_wih0, g_wih0);
    cudaGetSymbolAddress((void**)&p_wih1, g_wih1);
    cudaGetSymbolAddress((void**)&p_whh0, g_whh0);
    cudaGetSymbolAddress((void**)&p_whh1, g_whh1);

    cudaFuncSetAttribute(gemm_mma, cudaFuncAttributeMaxDynamicSharedMemorySize, PG_SMEM);
    cudaFuncSetAttribute(rnn_mma<true>, cudaFuncAttributeMaxDynamicSharedMemorySize, RN_SMEM);
    cudaFuncSetAttribute(rnn_mma<false>, cudaFuncAttributeMaxDynamicSharedMemorySize, RN_SMEM);

    const long long nx4 = (long long)BB * TT * II / 4;
    const long long nw04 = (long long)HH * II / 4;
    const long long nw4 = (long long)HH * HH / 4;

    // 1: x -> fp16
    to_f16v<<<(unsigned)((nx4 + 255) / 256), 256>>>((const float4*)x, (uint2*)p_xf, nx4);
    // 2: W_ih0 -> fp16
    to_f16v<<<(unsigned)((nw04 + 255) / 256), 256>>>((const float4*)W_ih0, (uint2*)p_wih0, nw04);
    // 3: bias0
    bias_combine<<<(HH + 255) / 256, 256>>>(b_ih0, b_hh0, p_b0, HH);
    // 4: W_hh0 -> fp16
    to_f16v<<<(unsigned)((nw4 + 255) / 256), 256>>>((const float4*)W_hh0, (uint2*)p_whh0, nw4);
    // 5: pre0 = x @ W_ih0^T + bias0
    gemm_mma<<<dim3((BB * TT) / 128, HH / 128), 256, PG_SMEM>>>(
        p_xf, p_wih0, p_b0, p_pre, II);
    // 6: layer-0 recurrence
    rnn_mma<true><<<128, 512, RN_SMEM>>>(p_whh0, p_pre, p_h1f, nullptr);
    // 7: W_ih1 -> fp16
    to_f16v<<<(unsigned)((nw4 + 255) / 256), 256>>>((const float4*)W_ih1, (uint2*)p_wih1, nw4);
    // 8: bias1
    bias_combine<<<(HH + 255) / 256, 256>>>(b_ih1, b_hh1, p_b1, HH);
    // 9: pre1 = h1 @ W_ih1^T + bias1
    gemm_mma<<<dim3((BB * TT) / 128, HH / 128), 256, PG_SMEM>>>(
        p_h1f, p_wih1, p_b1, p_pre, HH);
    // 10: W_hh1 -> fp16
    to_f16v<<<(unsigned)((nw4 + 255) / 256), 256>>>((const float4*)W_hh1, (uint2*)p_whh1, nw4);
    // 11: layer-1 recurrence
    rnn_mma<false><<<128, 512, RN_SMEM>>>(p_whh1, p_pre, p_h2f16, p_h2f);
    // 12: fc
    gemm_nt<32, 64, 4, 4><<<dim3(BB / 32, OO / 64), 128>>>(
        p_h2f, HH, fc_w, fc_b, out, OO, HH);
}

// round 12
// speedup vs baseline: 7.5382x; 1.0141x over previous
#include <cuda_runtime.h>
#include <cuda_fp16.h>
#include <cstdint>

// ---------------- problem dims ----------------
#define BB 256
#define TT 512
#define II 512
#define HH 1024
#define OO 256

// ---------------- static device scratch (allocation-free) ----------------
__device__ __align__(16) float g_pre[BB * TT * HH];
__device__ __align__(16) __half g_xf[BB * TT * II];          // x as fp16
__device__ __align__(16) __half g_h1f[BB * TT * HH];         // layer0 hidden seq fp16
__device__ __align__(16) __half g_h2f16[2 * BB * HH];        // layer1 ping-pong fp16
__device__ __align__(16) float g_h2f[BB * HH];               // layer1 final fp32
__device__ __align__(16) __half g_wih0[HH * II];
__device__ __align__(16) __half g_wih1[HH * HH];
__device__ __align__(16) __half g_whh0[HH * HH];
__device__ __align__(16) __half g_whh1[HH * HH];
__device__ __align__(16) float g_bias0[HH];
__device__ __align__(16) float g_bias1[HH];
// per-group barrier state: group g uses slot g*32 (128B apart); 8 groups
__device__ unsigned g_cnt2[256];
__device__ unsigned g_gen2[256];

// ---------------- PTX helpers (baseline PTX only) ----------------
__device__ __forceinline__ uint32_t smem_u32(const void* p) {
    uint32_t a;
    asm("{ .reg .u64 t; cvta.to.shared.u64 t, %1; cvt.u32.u64 %0, t; }" : "=r"(a) : "l"(p));
    return a;
}
#define CP16(dst, src) \
    asm volatile("cp.async.cg.shared.global [%0], [%1], 16;" :: "r"(dst), "l"(src) : "memory")
#define CP_COMMIT() asm volatile("cp.async.commit_group;" ::: "memory")
#define CP_WAIT(n)  asm volatile("cp.async.wait_group %0;" :: "n"(n) : "memory")

#define LDMX4(r, addr) \
    asm volatile("ldmatrix.sync.aligned.m8n8.x4.shared.b16 {%0,%1,%2,%3}, [%4];" \
                 : "=r"((r)[0]), "=r"((r)[1]), "=r"((r)[2]), "=r"((r)[3]) : "r"(addr))

#define MMAH16816(d, a, b0, b1) \
    asm volatile("mma.sync.aligned.m16n8k16.row.col.f32.f16.f16.f32 " \
                 "{%0,%1,%2,%3},{%4,%5,%6,%7},{%8,%9},{%0,%1,%2,%3};" \
                 : "+f"((d)[0]), "+f"((d)[1]), "+f"((d)[2]), "+f"((d)[3]) \
                 : "r"((a)[0]), "r"((a)[1]), "r"((a)[2]), "r"((a)[3]), "r"(b0), "r"(b1))

// ---------------- group grid barrier (32 CTAs per group) ----------------
__device__ __forceinline__ void grid_bar_g(int g) {
    __threadfence();
    __syncthreads();
    if (threadIdx.x == 0) {
        volatile unsigned* gen = (volatile unsigned*)&g_gen2[g * 32];
        unsigned my = *gen;
        if (atomicAdd(&g_cnt2[g * 32], 1u) == 31u) {
            atomicExch(&g_cnt2[g * 32], 0u);
            __threadfence();
            *gen = my + 1;
        } else {
            while (*gen == my) { }
        }
    }
    __syncthreads();
}

// ---------------- prep kernels ----------------
__global__ void to_f16v(const float4* __restrict__ s, uint2* __restrict__ o, long long n4) {
    long long i = (long long)blockIdx.x * blockDim.x + threadIdx.x;
    if (i < n4) {
        float4 v = s[i];
        __half2 a = __floats2half2_rn(v.x, v.y);
        __half2 b = __floats2half2_rn(v.z, v.w);
        uint2 r;
        r.x = *(uint32_t*)&a; r.y = *(uint32_t*)&b;
        o[i] = r;
    }
}
__global__ void bias_combine(const float* __restrict__ a, const float* __restrict__ b,
                             float* __restrict__ out, int n) {
    int i = blockIdx.x * blockDim.x + threadIdx.x;
    if (i < n) out[i] = a[i] + b[i];
}

// ================= fp16 HMMA pre-activation GEMM (1-pass, 3-stage) =================
#define PG_STAGE 32768
#define PG_SMEM  (3 * PG_STAGE)

__global__ void __launch_bounds__(256, 1)
gemm_mma(const __half* __restrict__ Af, const __half* __restrict__ Wf,
         const float* __restrict__ bias, float* __restrict__ C, int K) {
    extern __shared__ __align__(128) char smem[];
    const uint32_t sb = smem_u32(smem);
    const int tid = threadIdx.x, l = tid & 31, w = tid >> 5;
    const long long m0 = (long long)blockIdx.x * 128;
    const int n0 = blockIdx.y * 128;
    const int nch = K >> 6;

    const int r0 = tid >> 3, c = tid & 7;
    const uint32_t sd0 = (uint32_t)r0 * 128 + (((uint32_t)c * 16) ^ (((uint32_t)r0 & 7) * 16));

    const int m_off = (w & 3) * 32, n_off = (w >> 2) * 64;
    const int arw = m_off + (l & 7) + ((l & 8) ? 8 : 0);
    const uint32_t abase = (uint32_t)arw * 128;
    const uint32_t ax = ((uint32_t)arw & 7) * 16;
    const uint32_t akb = (l & 16) ? 16 : 0;
    const int brw = n_off + (l & 7) + ((l & 16) ? 8 : 0);
    const uint32_t bbase = (uint32_t)brw * 128;
    const uint32_t bx = ((uint32_t)brw & 7) * 16;
    const uint32_t bkb = (l & 8) ? 16 : 0;

    float acc[2][8][4];
#pragma unroll
    for (int i = 0; i < 2; i++)
#pragma unroll
        for (int j = 0; j < 8; j++)
#pragma unroll
            for (int k = 0; k < 4; k++) acc[i][j][k] = 0.0f;

    auto issue = [&](int kc) {
        const uint32_t d = sb + (uint32_t)(kc % 3) * PG_STAGE;
        const int ko = kc * 64 + c * 8;
#pragma unroll
        for (int j = 0; j < 4; ++j) {
            const long long ar = (m0 + r0 + 32 * j) * (long long)K + ko;
            const long long wr = ((long long)(n0 + r0 + 32 * j)) * K + ko;
            const uint32_t du = d + sd0 + j * 4096;
            CP16(du,          Af + ar);
            CP16(du + 16384,  Wf + wr);
        }
        CP_COMMIT();
    };

    issue(0);
    issue(1);

    for (int kc = 0; kc < nch; ++kc) {
        if (kc < nch - 1) CP_WAIT(1); else CP_WAIT(0);
        __syncthreads();
        if (kc + 2 < nch) issue(kc + 2);

        const uint32_t st = sb + (uint32_t)(kc % 3) * PG_STAGE;
#pragma unroll
        for (int ks = 0; ks < 4; ++ks) {
            uint32_t ah0[4], ah1[4];
            const uint32_t ao = ((uint32_t)(ks * 32) + akb) ^ ax;
            LDMX4(ah0, st + abase + ao);
            LDMX4(ah1, st + abase + 2048 + ao);
            uint32_t bh[4][4];
            const uint32_t bo = ((uint32_t)(ks * 32) + bkb) ^ bx;
#pragma unroll
            for (int nb = 0; nb < 4; ++nb)
                LDMX4(bh[nb], st + 16384 + bbase + nb * 2048 + bo);
#pragma unroll
            for (int nb = 0; nb < 4; ++nb) {
                MMAH16816(acc[0][2 * nb],     ah0, bh[nb][0], bh[nb][1]);
                MMAH16816(acc[0][2 * nb + 1], ah0, bh[nb][2], bh[nb][3]);
                MMAH16816(acc[1][2 * nb],     ah1, bh[nb][0], bh[nb][1]);
                MMAH16816(acc[1][2 * nb + 1], ah1, bh[nb][2], bh[nb][3]);
            }
        }
        __syncthreads();
    }

#pragma unroll
    for (int mf = 0; mf < 2; ++mf) {
        const long long R0 = m0 + m_off + mf * 16 + (l >> 2);
#pragma unroll
        for (int nf = 0; nf < 8; ++nf) {
            const int col = n0 + n_off + nf * 8 + (l & 3) * 2;
            const float2 bv = __ldg((const float2*)(bias + col));
            float2 o0, o1;
            o0.x = acc[mf][nf][0] + bv.x; o0.y = acc[mf][nf][1] + bv.y;
            o1.x = acc[mf][nf][2] + bv.x; o1.y = acc[mf][nf][3] + bv.y;
            __stcg((float2*)(C + R0 * HH + col), o0);
            __stcg((float2*)(C + (R0 + 8) * HH + col), o1);
        }
    }
}

// ================= fp16 HMMA persistent recurrence (2 CTAs/SM) =================
// grid 256 = 8 batch-groups(32 rows) x 32 H-tiles(32 cols). 256 threads.
// 8 warps = 8 K-slots (1 k16-slice per 128-K chunk each), warp tile 32m x 32n.
// W fp16 resident (64KB). A (h fp16, 32KB/step) streamed: 8 chunks of 128-K,
// 3-stage cp.async. 8-way K reduction through smem (reduce area overlaps stages).
// 96KB smem + <=128 regs -> 2 CTAs/SM: phases of one CTA overlap the other's MMAs.
#define RA_ST 65536              // stages AND reduce area both live here
#define RA_STG 8192              // per stage: 2 x 4KB 64-K sub-blocks
#define RN_SMEM (RA_ST + 32768)  // 96KB total

template <bool SEQ>
__global__ void __launch_bounds__(256, 2)
rnn_mma(const __half* __restrict__ Wf,
        const float* __restrict__ pre,
        __half* __restrict__ hf, float* __restrict__ hfin) {
    extern __shared__ __align__(128) char smem[];
    const uint32_t sb = smem_u32(smem);
    const int tid = threadIdx.x, l = tid & 31, w = tid >> 5;
    const int grp = blockIdx.x & 7;
    const int m0 = grp * 32;
    const int n0 = (blockIdx.x >> 3) * 32;

    // resident W: 16 blocks of [32 rows][128B], swizzled (4KB each)
    for (int u = tid; u < 4096; u += 256) {
        const int kc = u >> 8, rem = u & 255, r = rem >> 3, cc = rem & 7;
        const uint32_t dst = (uint32_t)kc * 4096 + (uint32_t)r * 128 +
                             (((uint32_t)cc * 16) ^ (((uint32_t)r & 7) * 16));
        const long long src = (long long)(n0 + r) * HH + kc * 64 + cc * 8;
        *(uint4*)(smem + dst) = *(const uint4*)(Wf + src);
    }
    __syncthreads();

    // staging: per 128-K chunk, 512 16B units = 2 sub-blocks x 32 rows x 8 cols.
    // each thread stages 2 units: sub-block j, row tid>>3, 16B-col tid&7.
    const int srr = tid >> 3, scc = tid & 7;
    const uint32_t st0 = (uint32_t)srr * 128 + (((uint32_t)scc * 16) ^ (((uint32_t)srr & 7) * 16));

    // compute mapping: warp = kslot 0..7 (one k16 slice per chunk), tile 32m x 32n
    const int kslot = w;
    const int bsel = kslot >> 2;       // 64-K sub-block within chunk
    const int si = kslot & 3;          // k16 slice within sub-block
    const uint32_t ax = ((uint32_t)l & 7) * 16;
    const uint32_t akb = (l & 16) ? 16u : 0u;
    const uint32_t a0base = (uint32_t)(l & 15) * 128;
    const uint32_t bkb = (l & 8) ? 16u : 0u;
    const uint32_t b0base = (uint32_t)((l & 7) + ((l & 16) ? 8 : 0)) * 128;
    const uint32_t kob = (uint32_t)(si * 32);
    const uint32_t ao = (kob + akb) ^ ax;
    const uint32_t bo = (kob + bkb) ^ ax;

    // reduce/epilogue mapping: tid = rl*8 + rfg
    const int rl = tid >> 3;
    const int rfg = tid & 7;           // = mf*4 + nf
    const int erow = m0 + (rfg >> 2) * 16 + (rl >> 2);
    const int ecol = n0 + (rfg & 3) * 8 + (rl & 3) * 2;
    const uint32_t rsw = ((uint32_t)rfg * 16) ^ (((uint32_t)rl & 7) * 16);

    for (int t = 0; t < TT; ++t) {
        // prefetch pre_t (independent of h)
        float2 p0 = __ldcg((const float2*)(pre + ((long long)erow * TT + t) * HH + ecol));
        float2 p1 = __ldcg((const float2*)(pre + ((long long)(erow + 8) * TT + t) * HH + ecol));

        float acc[2][4][4];
#pragma unroll
        for (int i = 0; i < 2; i++)
#pragma unroll
            for (int j = 0; j < 4; j++)
#pragma unroll
                for (int k = 0; k < 4; k++) acc[i][j][k] = 0.0f;

        if (t > 0) {
            long long ab;   // element addr of this thread's row at chunk 0, sub-block 0
            if (SEQ) {
                ab = ((long long)(m0 + srr) * TT + (t - 1)) * HH + scc * 8;
            } else {
                ab = (long long)((t - 1) & 1) * BB * HH + (long long)(m0 + srr) * HH + scc * 8;
            }

            auto issueA = [&](int cix) {
                const uint32_t d = sb + RA_ST + (uint32_t)(cix % 3) * RA_STG;
                CP16(d + st0,        hf + ab + cix * 128);
                CP16(d + 4096 + st0, hf + ab + cix * 128 + 64);
                CP_COMMIT();
            };

            issueA(0);
            issueA(1);

            for (int cix = 0; cix < 8; ++cix) {
                if (cix < 7) CP_WAIT(1); else CP_WAIT(0);
                __syncthreads();
                if (cix + 2 < 8) issueA(cix + 2);

                const uint32_t stg = sb + RA_ST + (uint32_t)(cix % 3) * RA_STG;
                const uint32_t ahbuf = stg + (uint32_t)bsel * 4096;
                const uint32_t bhbuf = sb + (uint32_t)(2 * cix + bsel) * 4096;

                uint32_t ah0[4], ah1[4];
                LDMX4(ah0, ahbuf + a0base + ao);
                LDMX4(ah1, ahbuf + a0base + 2048 + ao);
                uint32_t bh0[4], bh1[4];
                LDMX4(bh0, bhbuf + b0base + bo);
                LDMX4(bh1, bhbuf + b0base + 2048 + bo);
                MMAH16816(acc[0][0], ah0, bh0[0], bh0[1]); MMAH16816(acc[0][1], ah0, bh0[2], bh0[3]);
                MMAH16816(acc[0][2], ah0, bh1[0], bh1[1]); MMAH16816(acc[0][3], ah0, bh1[2], bh1[3]);
                MMAH16816(acc[1][0], ah1, bh0[0], bh0[1]); MMAH16816(acc[1][1], ah1, bh0[2], bh0[3]);
                MMAH16816(acc[1][2], ah1, bh1[0], bh1[1]); MMAH16816(acc[1][3], ah1, bh1[2], bh1[3]);
            }
        }

        // ---- 8-way K reduction through smem (XOR-swizzled, conflict-free) ----
        __syncthreads();
        {
            char* wp = smem + RA_ST + kslot * 4096 + l * 128;
            const uint32_t wsw = ((uint32_t)l & 7) * 16;
#pragma unroll
            for (int mf = 0; mf < 2; ++mf)
#pragma unroll
                for (int nf = 0; nf < 4; ++nf)
                    *(float4*)(wp + (((uint32_t)(mf * 4 + nf) * 16) ^ wsw)) = *(float4*)acc[mf][nf];
        }
        __syncthreads();
        float s[4];
        s[0] = s[1] = s[2] = s[3] = 0.0f;
#pragma unroll
        for (int k = 0; k < 8; ++k) {
            const float4 u = *(const float4*)(smem + RA_ST + k * 4096 + rl * 128 + rsw);
            s[0] += u.x; s[1] += u.y; s[2] += u.z; s[3] += u.w;
        }

        // ---- epilogue: h = relu(sum + pre_t); store fp16 (+ final fp32) ----
        {
            const long long R0 = erow, R1 = erow + 8;
            float v0 = fmaxf(s[0] + p0.x, 0.0f);
            float v1 = fmaxf(s[1] + p0.y, 0.0f);
            float v2 = fmaxf(s[2] + p1.x, 0.0f);
            float v3 = fmaxf(s[3] + p1.y, 0.0f);
            __half2 ha = __floats2half2_rn(v0, v1);
            __half2 hb = __floats2half2_rn(v2, v3);
            long long ob0, ob1;
            if (SEQ) {
                ob0 = (R0 * TT + t) * HH + ecol;
                ob1 = (R1 * TT + t) * HH + ecol;
            } else {
                ob0 = (long long)(t & 1) * BB * HH + R0 * HH + ecol;
                ob1 = (long long)(t & 1) * BB * HH + R1 * HH + ecol;
            }
            __stcg((uint32_t*)(hf + ob0), *(uint32_t*)&ha);
            __stcg((uint32_t*)(hf + ob1), *(uint32_t*)&hb);
            if (!SEQ && t == TT - 1) {
                __stcg((float2*)(hfin + R0 * HH + ecol), make_float2(v0, v1));
                __stcg((float2*)(hfin + R1 * HH + ecol), make_float2(v2, v3));
            }
        }
        grid_bar_g(grp);
    }
}

// ---------------- small scalar GEMM for fc ----------------
template <int BM, int BN, int TM, int TN>
__global__ void __launch_bounds__((BM / TM) * (BN / TN))
gemm_nt(const float* __restrict__ A, long long a_stride,
        const float* __restrict__ W, const float* __restrict__ bias,
        float* __restrict__ C, long long c_stride, int K) {
    constexpr int BK = 16, TX = BN / TN, TY = BM / TM, NT = TX * TY;
    __shared__ __align__(16) float As[BK][BM];
    __shared__ __align__(16) float Ws[BK][BN];
    const int tid = threadIdx.x, tx = tid % TX, ty = tid / TX;
    const long long m0 = (long long)blockIdx.x * BM;
    const int n0 = blockIdx.y * BN;
    float acc[TM][TN];
#pragma unroll
    for (int i = 0; i < TM; i++)
#pragma unroll
        for (int j = 0; j < TN; j++) acc[i][j] = 0.0f;
    for (int kt = 0; kt < K; kt += BK) {
#pragma unroll
        for (int idx = tid; idx < BM * 4; idx += NT) {
            const int row = idx >> 2, kq = (idx & 3) * 4;
            const float4 v = *(const float4*)(A + (m0 + row) * a_stride + kt + kq);
            As[kq][row] = v.x; As[kq + 1][row] = v.y; As[kq + 2][row] = v.z; As[kq + 3][row] = v.w;
        }
#pragma unroll
        for (int idx = tid; idx < BN * 4; idx += NT) {
            const int row = idx >> 2, kq = (idx & 3) * 4;
            const float4 v = *(const float4*)(W + (long long)(n0 + row) * K + kt + kq);
            Ws[kq][row] = v.x; Ws[kq + 1][row] = v.y; Ws[kq + 2][row] = v.z; Ws[kq + 3][row] = v.w;
        }
        __syncthreads();
#pragma unroll
        for (int kk = 0; kk < BK; kk++) {
            float a[TM], b[TN];
#pragma unroll
            for (int i = 0; i < TM; i += 4) {
                const float4 v = *(const float4*)&As[kk][ty * TM + i];
                a[i] = v.x; a[i + 1] = v.y; a[i + 2] = v.z; a[i + 3] = v.w;
            }
#pragma unroll
            for (int j = 0; j < TN; j += 4) {
                const float4 v = *(const float4*)&Ws[kk][tx * TN + j];
                b[j] = v.x; b[j + 1] = v.y; b[j + 2] = v.z; b[j + 3] = v.w;
            }
#pragma unroll
            for (int i = 0; i < TM; i++)
#pragma unroll
                for (int j = 0; j < TN; j++) acc[i][j] = fmaf(a[i], b[j], acc[i][j]);
        }
        __syncthreads();
    }
#pragma unroll
    for (int i = 0; i < TM; i++) {
        const long long m = m0 + ty * TM + i;
#pragma unroll
        for (int j = 0; j < TN; j++)
            C[m * c_stride + n0 + tx * TN + j] = acc[i][j] + bias[n0 + tx * TN + j];
    }
}

// ---------------- launch ----------------
extern "C" void kernel_launch(void* const* d_in, const int* in_sizes, int n_in,
                              void* d_out, int out_size) {
    const float* x     = (const float*)d_in[0];
    const float* W_ih0 = (const float*)d_in[1];
    const float* W_hh0 = (const float*)d_in[2];
    const float* b_ih0 = (const float*)d_in[3];
    const float* b_hh0 = (const float*)d_in[4];
    const float* W_ih1 = (const float*)d_in[5];
    const float* W_hh1 = (const float*)d_in[6];
    const float* b_ih1 = (const float*)d_in[7];
    const float* b_hh1 = (const float*)d_in[8];
    const float* fc_w  = (const float*)d_in[9];
    const float* fc_b  = (const float*)d_in[10];
    float* out = (float*)d_out;

    float *p_pre, *p_b0, *p_b1, *p_h2f;
    __half *p_xf, *p_h1f, *p_h2f16;
    __half *p_wih0, *p_wih1, *p_whh0, *p_whh1;
    cudaGetSymbolAddress((void**)&p_pre, g_pre);
    cudaGetSymbolAddress((void**)&p_b0, g_bias0);
    cudaGetSymbolAddress((void**)&p_b1, g_bias1);
    cudaGetSymbolAddress((void**)&p_h2f, g_h2f);
    cudaGetSymbolAddress((void**)&p_xf, g_xf);
    cudaGetSymbolAddress((void**)&p_h1f, g_h1f);
    cudaGetSymbolAddress((void**)&p_h2f16, g_h2f16);
    cudaGetSymbolAddress((void**)&p_wih0, g_wih0);
    cudaGetSymbolAddress((void**)&p_wih1, g_wih1);
    cudaGetSymbolAddress((void**)&p_whh0, g_whh0);
    cudaGetSymbolAddress((void**)&p_whh1, g_whh1);

    cudaFuncSetAttribute(gemm_mma, cudaFuncAttributeMaxDynamicSharedMemorySize, PG_SMEM);
    cudaFuncSetAttribute(rnn_mma<true>, cudaFuncAttributeMaxDynamicSharedMemorySize, RN_SMEM);
    cudaFuncSetAttribute(rnn_mma<false>, cudaFuncAttributeMaxDynamicSharedMemorySize, RN_SMEM);

    const long long nx4 = (long long)BB * TT * II / 4;
    const long long nw04 = (long long)HH * II / 4;
    const long long nw4 = (long long)HH * HH / 4;

    // 1: x -> fp16
    to_f16v<<<(unsigned)((nx4 + 255) / 256), 256>>>((const float4*)x, (uint2*)p_xf, nx4);
    // 2: W_ih0 -> fp16
    to_f16v<<<(unsigned)((nw04 + 255) / 256), 256>>>((const float4*)W_ih0, (uint2*)p_wih0, nw04);
    // 3: bias0
    bias_combine<<<(HH + 255) / 256, 256>>>(b_ih0, b_hh0, p_b0, HH);
    // 4: W_hh0 -> fp16
    to_f16v<<<(unsigned)((nw4 + 255) / 256), 256>>>((const float4*)W_hh0, (uint2*)p_whh0, nw4);
    // 5: pre0 = x @ W_ih0^T + bias0
    gemm_mma<<<dim3((BB * TT) / 128, HH / 128), 256, PG_SMEM>>>(
        p_xf, p_wih0, p_b0, p_pre, II);
    // 6: layer-0 recurrence (256 CTAs, 2/SM)
    rnn_mma<true><<<256, 256, RN_SMEM>>>(p_whh0, p_pre, p_h1f, nullptr);
    // 7: W_ih1 -> fp16
    to_f16v<<<(unsigned)((nw4 + 255) / 256), 256>>>((const float4*)W_ih1, (uint2*)p_wih1, nw4);
    // 8: bias1
    bias_combine<<<(HH + 255) / 256, 256>>>(b_ih1, b_hh1, p_b1, HH);
    // 9: pre1 = h1 @ W_ih1^T + bias1
    gemm_mma<<<dim3((BB * TT) / 128, HH / 128), 256, PG_SMEM>>>(
        p_h1f, p_wih1, p_b1, p_pre, HH);
    // 10: W_hh1 -> fp16
    to_f16v<<<(unsigned)((nw4 + 255) / 256), 256>>>((const float4*)W_hh1, (uint2*)p_whh1, nw4);
    // 11: layer-1 recurrence
    rnn_mma<false><<<256, 256, RN_SMEM>>>(p_whh1, p_pre, p_h2f16, p_h2f);
    // 12: fc
    gemm_nt<32, 64, 4, 4><<<dim3(BB / 32, OO / 64), 128>>>(
        p_h2f, HH, fc_w, fc_b, out, OO, HH);
}